// round 1
// baseline (speedup 1.0000x reference)
#include <cuda_runtime.h>
#include <cstdint>

// Problem constants (fixed by the dataset)
#define NPTS 16384   // fine points
#define MPTS 4096    // coarse points
#define CF   256     // fine feature channels
#define CC   512     // coarse feature channels
#define INCH 768     // CC + CF
#define H1   512
#define H2   512
#define BN_EPS 1e-5f

// ---------------- scratch (device globals; no runtime allocation) ----------
__device__ float g_fcT[MPTS * CC];        // transposed coarse feats [M][CC]  (8 MB)
__device__ int   g_idx[NPTS * 3];
__device__ float g_w[NPTS * 3];
__device__ float g_interp[CC * NPTS];     // interpolated feats [CC][N] (32 MB)
__device__ float g_y1[H1 * NPTS];         // raw layer-1 output (32 MB)
__device__ float g_y2[H2 * NPTS];         // raw layer-2 output (32 MB)
__device__ float g_sc1[H1], g_sh1[H1], g_sc2[H2], g_sh2[H2];

// ---------------- kNN: warp per query, coarse xyz in smem ------------------
__device__ __forceinline__ void top3_insert(float d, int j,
                                            float& d0, float& d1, float& d2,
                                            int& i0, int& i1, int& i2) {
    if (d < d2) {
        if (d < d1) {
            d2 = d1; i2 = i1;
            if (d < d0) { d1 = d0; i1 = i0; d0 = d; i0 = j; }
            else        { d1 = d;  i1 = j; }
        } else { d2 = d; i2 = j; }
    }
}

__global__ __launch_bounds__(256) void knn_kernel(
    const float* __restrict__ xf, const float* __restrict__ xc,
    int* __restrict__ idx_out, float* __restrict__ w_out)
{
    __shared__ float sx[MPTS], sy[MPTS], sz[MPTS];
    for (int j = threadIdx.x; j < MPTS; j += 256) {
        sx[j] = xc[j];
        sy[j] = xc[MPTS + j];
        sz[j] = xc[2 * MPTS + j];
    }
    __syncthreads();

    const int warp = threadIdx.x >> 5;
    const int lane = threadIdx.x & 31;
    const int n = blockIdx.x * 8 + warp;

    const float qx = xf[n], qy = xf[NPTS + n], qz = xf[2 * NPTS + n];

    float d0 = 3.4e38f, d1 = 3.4e38f, d2 = 3.4e38f;
    int   i0 = 0, i1 = 0, i2 = 0;

    for (int j = lane; j < MPTS; j += 32) {
        float dx = qx - sx[j], dy = qy - sy[j], dz = qz - sz[j];
        float d = fmaf(dx, dx, fmaf(dy, dy, dz * dz));
        top3_insert(d, j, d0, d1, d2, i0, i1, i2);
    }
    // warp-level merge of per-lane sorted triples
    for (int off = 16; off; off >>= 1) {
        float od0 = __shfl_xor_sync(0xffffffffu, d0, off);
        float od1 = __shfl_xor_sync(0xffffffffu, d1, off);
        float od2 = __shfl_xor_sync(0xffffffffu, d2, off);
        int   oi0 = __shfl_xor_sync(0xffffffffu, i0, off);
        int   oi1 = __shfl_xor_sync(0xffffffffu, i1, off);
        int   oi2 = __shfl_xor_sync(0xffffffffu, i2, off);
        top3_insert(od0, oi0, d0, d1, d2, i0, i1, i2);
        top3_insert(od1, oi1, d0, d1, d2, i0, i1, i2);
        top3_insert(od2, oi2, d0, d1, d2, i0, i1, i2);
    }
    if (lane == 0) {
        float D0 = fmaxf(sqrtf(d0), 1e-8f);
        float D1 = fmaxf(sqrtf(d1), 1e-8f);
        float D2 = fmaxf(sqrtf(d2), 1e-8f);
        float w0 = 1.f / D0, w1 = 1.f / D1, w2 = 1.f / D2;
        float inv = 1.f / (w0 + w1 + w2);
        idx_out[n * 3 + 0] = i0; idx_out[n * 3 + 1] = i1; idx_out[n * 3 + 2] = i2;
        w_out[n * 3 + 0] = w0 * inv;
        w_out[n * 3 + 1] = w1 * inv;
        w_out[n * 3 + 2] = w2 * inv;
    }
}

// ---------------- transpose feats_coarse [CC][M] -> [M][CC] ----------------
__global__ void transpose_kernel(const float* __restrict__ in, float* __restrict__ out)
{
    __shared__ float t[32][33];
    int bx = blockIdx.x * 32;  // M dim
    int by = blockIdx.y * 32;  // CC dim
    for (int r = threadIdx.y; r < 32; r += 8)
        t[r][threadIdx.x] = in[(size_t)(by + r) * MPTS + bx + threadIdx.x];
    __syncthreads();
    for (int r = threadIdx.y; r < 32; r += 8)
        out[(size_t)(bx + r) * CC + by + threadIdx.x] = t[threadIdx.x][r];
}

// ---------------- interpolation: warp per point, coalesced gathers ---------
__global__ __launch_bounds__(256) void interp_kernel(
    const float* __restrict__ fcT, const int* __restrict__ idx,
    const float* __restrict__ wgt, float* __restrict__ interp)
{
    __shared__ float tile[32][9];
    const int warp = threadIdx.x >> 5;
    const int lane = threadIdx.x & 31;
    const int n = blockIdx.x * 8 + warp;
    const int n_base = blockIdx.x * 8;

    const int i0 = idx[n * 3 + 0], i1 = idx[n * 3 + 1], i2 = idx[n * 3 + 2];
    const float w0 = wgt[n * 3 + 0], w1 = wgt[n * 3 + 1], w2 = wgt[n * 3 + 2];
    const float* __restrict__ r0 = fcT + (size_t)i0 * CC;
    const float* __restrict__ r1 = fcT + (size_t)i1 * CC;
    const float* __restrict__ r2 = fcT + (size_t)i2 * CC;

    const int cl = threadIdx.x >> 3;
    const int nl = threadIdx.x & 7;

    for (int c0 = 0; c0 < CC; c0 += 32) {
        int c = c0 + lane;
        float v = fmaf(w0, __ldg(&r0[c]), fmaf(w1, __ldg(&r1[c]), w2 * __ldg(&r2[c])));
        __syncthreads();
        tile[lane][warp] = v;
        __syncthreads();
        interp[(size_t)(c0 + cl) * NPTS + n_base + nl] = tile[cl][nl];
    }
}

// ---------------- tiled SGEMM: C[512][16384] = A[512][K] * B[K][16384] -----
// SPLIT_B: rows k<512 from B0 (interp), k>=512 from B1 (feats_fine)
// NORM_B:  apply relu(scale[k]*v + shift[k]) to B elements on load (fused BN)
template<bool SPLIT_B, bool NORM_B>
__global__ __launch_bounds__(256) void sgemm_kernel(
    const float* __restrict__ A, const float* __restrict__ B0,
    const float* __restrict__ B1, const float* __restrict__ scale,
    const float* __restrict__ shift, float* __restrict__ C, int K)
{
    constexpr int BM = 128, BN = 128, BK = 16;
    __shared__ float As[BK][BM];
    __shared__ float Bs[BK][BN];

    const int tid = threadIdx.x;
    const int m0 = blockIdx.y * BM;
    const int n0 = blockIdx.x * BN;
    const int tm = (tid >> 4) * 8;
    const int tn = (tid & 15) * 8;

    float acc[8][8] = {};

    for (int kt = 0; kt < K; kt += BK) {
        // A tile (W): 128x16, float4 along k, store transposed
        #pragma unroll
        for (int r = 0; r < 2; r++) {
            int id = tid + r * 256;
            int m = id >> 2;
            int k4 = (id & 3) << 2;
            float4 v = *reinterpret_cast<const float4*>(&A[(size_t)(m0 + m) * K + kt + k4]);
            As[k4 + 0][m] = v.x; As[k4 + 1][m] = v.y;
            As[k4 + 2][m] = v.z; As[k4 + 3][m] = v.w;
        }
        // B tile: 16x128, float4 along n
        #pragma unroll
        for (int r = 0; r < 2; r++) {
            int id = tid + r * 256;
            int k = id >> 5;
            int n4 = (id & 31) << 2;
            int kg = kt + k;
            const float* src;
            int row;
            if (SPLIT_B) {
                if (kg < CC) { src = B0; row = kg; }
                else         { src = B1; row = kg - CC; }
            } else { src = B0; row = kg; }
            float4 v = *reinterpret_cast<const float4*>(&src[(size_t)row * NPTS + n0 + n4]);
            if (NORM_B) {
                float sc = scale[kg], sh = shift[kg];
                v.x = fmaxf(fmaf(sc, v.x, sh), 0.f);
                v.y = fmaxf(fmaf(sc, v.y, sh), 0.f);
                v.z = fmaxf(fmaf(sc, v.z, sh), 0.f);
                v.w = fmaxf(fmaf(sc, v.w, sh), 0.f);
            }
            *reinterpret_cast<float4*>(&Bs[k][n4]) = v;
        }
        __syncthreads();

        #pragma unroll
        for (int k = 0; k < BK; k++) {
            float a[8], b[8];
            *reinterpret_cast<float4*>(&a[0]) = *reinterpret_cast<const float4*>(&As[k][tm]);
            *reinterpret_cast<float4*>(&a[4]) = *reinterpret_cast<const float4*>(&As[k][tm + 4]);
            *reinterpret_cast<float4*>(&b[0]) = *reinterpret_cast<const float4*>(&Bs[k][tn]);
            *reinterpret_cast<float4*>(&b[4]) = *reinterpret_cast<const float4*>(&Bs[k][tn + 4]);
            #pragma unroll
            for (int i = 0; i < 8; i++)
                #pragma unroll
                for (int j = 0; j < 8; j++)
                    acc[i][j] = fmaf(a[i], b[j], acc[i][j]);
        }
        __syncthreads();
    }

    #pragma unroll
    for (int i = 0; i < 8; i++) {
        size_t off = (size_t)(m0 + tm + i) * NPTS + n0 + tn;
        *reinterpret_cast<float4*>(&C[off]) =
            make_float4(acc[i][0], acc[i][1], acc[i][2], acc[i][3]);
        *reinterpret_cast<float4*>(&C[off + 4]) =
            make_float4(acc[i][4], acc[i][5], acc[i][6], acc[i][7]);
    }
}

// ---------------- BN statistics: block per channel --------------------------
__global__ __launch_bounds__(256) void bn_stats_kernel(
    const float* __restrict__ Y, const float* __restrict__ g,
    const float* __restrict__ b, float* __restrict__ sc, float* __restrict__ sh)
{
    const int c = blockIdx.x;
    const float4* row = reinterpret_cast<const float4*>(Y + (size_t)c * NPTS);
    float s = 0.f, s2 = 0.f;
    for (int i = threadIdx.x; i < NPTS / 4; i += 256) {
        float4 v = row[i];
        s  += v.x + v.y + v.z + v.w;
        s2 += v.x * v.x + v.y * v.y + v.z * v.z + v.w * v.w;
    }
    __shared__ float ss[8], ss2[8];
    for (int o = 16; o; o >>= 1) {
        s  += __shfl_xor_sync(0xffffffffu, s, o);
        s2 += __shfl_xor_sync(0xffffffffu, s2, o);
    }
    if ((threadIdx.x & 31) == 0) { ss[threadIdx.x >> 5] = s; ss2[threadIdx.x >> 5] = s2; }
    __syncthreads();
    if (threadIdx.x == 0) {
        s = 0.f; s2 = 0.f;
        #pragma unroll
        for (int i = 0; i < 8; i++) { s += ss[i]; s2 += ss2[i]; }
        float mean = s * (1.f / NPTS);
        float var  = s2 * (1.f / NPTS) - mean * mean;
        float isd  = rsqrtf(var + BN_EPS);
        float scl  = g[c] * isd;
        sc[c] = scl;
        sh[c] = fmaf(-mean, scl, b[c]);
    }
}

// ---------------- final BN+ReLU elementwise ---------------------------------
__global__ __launch_bounds__(256) void bn_apply_kernel(
    const float* __restrict__ Y, const float* __restrict__ sc,
    const float* __restrict__ sh, float* __restrict__ out)
{
    int i = blockIdx.x * 256 + threadIdx.x;       // over float4s: 512*16384/4
    int c = i >> 12;                               // 4096 float4 per channel
    float4 v = reinterpret_cast<const float4*>(Y)[i];
    float s = sc[c], h = sh[c];
    v.x = fmaxf(fmaf(s, v.x, h), 0.f);
    v.y = fmaxf(fmaf(s, v.y, h), 0.f);
    v.z = fmaxf(fmaf(s, v.z, h), 0.f);
    v.w = fmaxf(fmaf(s, v.w, h), 0.f);
    reinterpret_cast<float4*>(out)[i] = v;
}

// ---------------- launch -----------------------------------------------------
extern "C" void kernel_launch(void* const* d_in, const int* in_sizes, int n_in,
                              void* d_out, int out_size)
{
    const float* xyz_fine     = (const float*)d_in[0];
    const float* xyz_coarse   = (const float*)d_in[1];
    const float* feats_fine   = (const float*)d_in[2];
    const float* feats_coarse = (const float*)d_in[3];
    const float* W1 = (const float*)d_in[4];
    const float* g1 = (const float*)d_in[5];
    const float* b1 = (const float*)d_in[6];
    const float* W2 = (const float*)d_in[7];
    const float* g2 = (const float*)d_in[8];
    const float* b2 = (const float*)d_in[9];
    float* out = (float*)d_out;

    void* p;
    cudaGetSymbolAddress(&p, g_fcT);    float* fcT    = (float*)p;
    cudaGetSymbolAddress(&p, g_idx);    int*   idxp   = (int*)p;
    cudaGetSymbolAddress(&p, g_w);      float* wp     = (float*)p;
    cudaGetSymbolAddress(&p, g_interp); float* interp = (float*)p;
    cudaGetSymbolAddress(&p, g_y1);     float* y1     = (float*)p;
    cudaGetSymbolAddress(&p, g_y2);     float* y2     = (float*)p;
    cudaGetSymbolAddress(&p, g_sc1);    float* sc1    = (float*)p;
    cudaGetSymbolAddress(&p, g_sh1);    float* sh1    = (float*)p;
    cudaGetSymbolAddress(&p, g_sc2);    float* sc2    = (float*)p;
    cudaGetSymbolAddress(&p, g_sh2);    float* sh2    = (float*)p;

    transpose_kernel<<<dim3(MPTS / 32, CC / 32), dim3(32, 8)>>>(feats_coarse, fcT);
    knn_kernel<<<NPTS / 8, 256>>>(xyz_fine, xyz_coarse, idxp, wp);
    interp_kernel<<<NPTS / 8, 256>>>(fcT, idxp, wp, interp);

    sgemm_kernel<true, false><<<dim3(NPTS / 128, H1 / 128), 256>>>(
        W1, interp, feats_fine, nullptr, nullptr, y1, INCH);
    bn_stats_kernel<<<H1, 256>>>(y1, g1, b1, sc1, sh1);

    sgemm_kernel<false, true><<<dim3(NPTS / 128, H2 / 128), 256>>>(
        W2, y1, nullptr, sc1, sh1, y2, H1);
    bn_stats_kernel<<<H2, 256>>>(y2, g2, b2, sc2, sh2);

    bn_apply_kernel<<<(H2 * NPTS / 4) / 256, 256>>>(y2, sc2, sh2, out);
}

// round 2
// speedup vs baseline: 1.0218x; 1.0218x over previous
#include <cuda_runtime.h>
#include <cstdint>

// Problem constants (fixed by the dataset)
#define NPTS 16384   // fine points
#define MPTS 4096    // coarse points
#define CF   256     // fine feature channels
#define CC   512     // coarse feature channels
#define INCH 768     // CC + CF
#define H1   512
#define H2   512
#define BN_EPS 1e-5f

// ---------------- scratch (device globals; no runtime allocation) ----------
__device__ float g_fcT[MPTS * CC];        // transposed coarse feats [M][CC]  (8 MB)
__device__ int   g_idx[NPTS * 3];
__device__ float g_w[NPTS * 3];
__device__ float g_interp[CC * NPTS];     // interpolated feats [CC][N] (32 MB)
__device__ float g_y1[H1 * NPTS];         // raw layer-1 output (32 MB)
__device__ float g_y2[H2 * NPTS];         // raw layer-2 output (32 MB)
__device__ float g_sc1[H1], g_sh1[H1], g_sc2[H2], g_sh2[H2];

// ---------------- packed f32x2 helpers (Blackwell dual-FP32 pipe) ----------
__device__ __forceinline__ unsigned long long dup_f32x2(float x) {
    unsigned long long r;
    asm("mov.b64 %0, {%1, %1};" : "=l"(r) : "f"(x));
    return r;
}
__device__ __forceinline__ void fma_f32x2(unsigned long long& d,
                                          unsigned long long a,
                                          unsigned long long b) {
    asm("fma.rn.f32x2 %0, %1, %2, %0;" : "+l"(d) : "l"(a), "l"(b));
}
__device__ __forceinline__ float2 unpack_f32x2(unsigned long long v) {
    float2 f;
    asm("mov.b64 {%0, %1}, %2;" : "=f"(f.x), "=f"(f.y) : "l"(v));
    return f;
}

// ---------------- kNN: warp per query, coarse xyz in smem ------------------
__device__ __forceinline__ void top3_insert(float d, int j,
                                            float& d0, float& d1, float& d2,
                                            int& i0, int& i1, int& i2) {
    if (d < d2) {
        if (d < d1) {
            d2 = d1; i2 = i1;
            if (d < d0) { d1 = d0; i1 = i0; d0 = d; i0 = j; }
            else        { d1 = d;  i1 = j; }
        } else { d2 = d; i2 = j; }
    }
}

__global__ __launch_bounds__(256) void knn_kernel(
    const float* __restrict__ xf, const float* __restrict__ xc,
    int* __restrict__ idx_out, float* __restrict__ w_out)
{
    __shared__ float sx[MPTS], sy[MPTS], sz[MPTS];
    for (int j = threadIdx.x; j < MPTS; j += 256) {
        sx[j] = xc[j];
        sy[j] = xc[MPTS + j];
        sz[j] = xc[2 * MPTS + j];
    }
    __syncthreads();

    const int warp = threadIdx.x >> 5;
    const int lane = threadIdx.x & 31;
    const int n = blockIdx.x * 8 + warp;

    const float qx = xf[n], qy = xf[NPTS + n], qz = xf[2 * NPTS + n];

    float d0 = 3.4e38f, d1 = 3.4e38f, d2 = 3.4e38f;
    int   i0 = 0, i1 = 0, i2 = 0;

    for (int j = lane; j < MPTS; j += 32) {
        float dx = qx - sx[j], dy = qy - sy[j], dz = qz - sz[j];
        float d = fmaf(dx, dx, fmaf(dy, dy, dz * dz));
        top3_insert(d, j, d0, d1, d2, i0, i1, i2);
    }
    // warp-level merge of per-lane sorted triples
    for (int off = 16; off; off >>= 1) {
        float od0 = __shfl_xor_sync(0xffffffffu, d0, off);
        float od1 = __shfl_xor_sync(0xffffffffu, d1, off);
        float od2 = __shfl_xor_sync(0xffffffffu, d2, off);
        int   oi0 = __shfl_xor_sync(0xffffffffu, i0, off);
        int   oi1 = __shfl_xor_sync(0xffffffffu, i1, off);
        int   oi2 = __shfl_xor_sync(0xffffffffu, i2, off);
        top3_insert(od0, oi0, d0, d1, d2, i0, i1, i2);
        top3_insert(od1, oi1, d0, d1, d2, i0, i1, i2);
        top3_insert(od2, oi2, d0, d1, d2, i0, i1, i2);
    }
    if (lane == 0) {
        float D0 = fmaxf(sqrtf(d0), 1e-8f);
        float D1 = fmaxf(sqrtf(d1), 1e-8f);
        float D2 = fmaxf(sqrtf(d2), 1e-8f);
        float w0 = 1.f / D0, w1 = 1.f / D1, w2 = 1.f / D2;
        float inv = 1.f / (w0 + w1 + w2);
        idx_out[n * 3 + 0] = i0; idx_out[n * 3 + 1] = i1; idx_out[n * 3 + 2] = i2;
        w_out[n * 3 + 0] = w0 * inv;
        w_out[n * 3 + 1] = w1 * inv;
        w_out[n * 3 + 2] = w2 * inv;
    }
}

// ---------------- transpose feats_coarse [CC][M] -> [M][CC] ----------------
__global__ void transpose_kernel(const float* __restrict__ in, float* __restrict__ out)
{
    __shared__ float t[32][33];
    int bx = blockIdx.x * 32;  // M dim
    int by = blockIdx.y * 32;  // CC dim
    for (int r = threadIdx.y; r < 32; r += 8)
        t[r][threadIdx.x] = in[(size_t)(by + r) * MPTS + bx + threadIdx.x];
    __syncthreads();
    for (int r = threadIdx.y; r < 32; r += 8)
        out[(size_t)(bx + r) * CC + by + threadIdx.x] = t[threadIdx.x][r];
}

// ---------------- interpolation: warp per point, coalesced gathers ---------
__global__ __launch_bounds__(256) void interp_kernel(
    const float* __restrict__ fcT, const int* __restrict__ idx,
    const float* __restrict__ wgt, float* __restrict__ interp)
{
    __shared__ float tile[32][9];
    const int warp = threadIdx.x >> 5;
    const int lane = threadIdx.x & 31;
    const int n = blockIdx.x * 8 + warp;
    const int n_base = blockIdx.x * 8;

    const int i0 = idx[n * 3 + 0], i1 = idx[n * 3 + 1], i2 = idx[n * 3 + 2];
    const float w0 = wgt[n * 3 + 0], w1 = wgt[n * 3 + 1], w2 = wgt[n * 3 + 2];
    const float* __restrict__ r0 = fcT + (size_t)i0 * CC;
    const float* __restrict__ r1 = fcT + (size_t)i1 * CC;
    const float* __restrict__ r2 = fcT + (size_t)i2 * CC;

    const int cl = threadIdx.x >> 3;
    const int nl = threadIdx.x & 7;

    for (int c0 = 0; c0 < CC; c0 += 32) {
        int c = c0 + lane;
        float v = fmaf(w0, __ldg(&r0[c]), fmaf(w1, __ldg(&r1[c]), w2 * __ldg(&r2[c])));
        __syncthreads();
        tile[lane][warp] = v;
        __syncthreads();
        interp[(size_t)(c0 + cl) * NPTS + n_base + nl] = tile[cl][nl];
    }
}

// ---------------- tiled SGEMM (f32x2 packed): C = A * B ---------------------
// C[512][16384] = A[512][K] * B[K][16384]
// SPLIT_B: rows k<512 from B0 (interp), k>=512 from B1 (feats_fine)
// NORM_B:  apply relu(scale[k]*v + shift[k]) to B elements on load (fused BN)
template<bool SPLIT_B, bool NORM_B>
__global__ __launch_bounds__(256) void sgemm_kernel(
    const float* __restrict__ A, const float* __restrict__ B0,
    const float* __restrict__ B1, const float* __restrict__ scale,
    const float* __restrict__ shift, float* __restrict__ C, int K)
{
    constexpr int BM = 128, BN = 128, BK = 16;
    __shared__ float As[BK][BM];
    __shared__ float Bs[BK][BN];

    const int tid = threadIdx.x;
    const int m0 = blockIdx.y * BM;
    const int n0 = blockIdx.x * BN;
    const int tm = (tid >> 4) * 8;
    const int tn = (tid & 15) * 8;

    // 8 (m) x 4 (n-pairs) packed accumulators = 8x8 scalar C tile
    unsigned long long acc2[8][4] = {};

    for (int kt = 0; kt < K; kt += BK) {
        // A tile (W): 128x16, float4 along k, store transposed
        #pragma unroll
        for (int r = 0; r < 2; r++) {
            int id = tid + r * 256;
            int m = id >> 2;
            int k4 = (id & 3) << 2;
            float4 v = *reinterpret_cast<const float4*>(&A[(size_t)(m0 + m) * K + kt + k4]);
            As[k4 + 0][m] = v.x; As[k4 + 1][m] = v.y;
            As[k4 + 2][m] = v.z; As[k4 + 3][m] = v.w;
        }
        // B tile: 16x128, float4 along n
        #pragma unroll
        for (int r = 0; r < 2; r++) {
            int id = tid + r * 256;
            int k = id >> 5;
            int n4 = (id & 31) << 2;
            int kg = kt + k;
            const float* src;
            int row;
            if (SPLIT_B) {
                if (kg < CC) { src = B0; row = kg; }
                else         { src = B1; row = kg - CC; }
            } else { src = B0; row = kg; }
            float4 v = *reinterpret_cast<const float4*>(&src[(size_t)row * NPTS + n0 + n4]);
            if (NORM_B) {
                float sc = scale[kg], sh = shift[kg];
                v.x = fmaxf(fmaf(sc, v.x, sh), 0.f);
                v.y = fmaxf(fmaf(sc, v.y, sh), 0.f);
                v.z = fmaxf(fmaf(sc, v.z, sh), 0.f);
                v.w = fmaxf(fmaf(sc, v.w, sh), 0.f);
            }
            *reinterpret_cast<float4*>(&Bs[k][n4]) = v;
        }
        __syncthreads();

        #pragma unroll
        for (int k = 0; k < BK; k++) {
            float a[8];
            unsigned long long b2[4];
            *reinterpret_cast<float4*>(&a[0]) = *reinterpret_cast<const float4*>(&As[k][tm]);
            *reinterpret_cast<float4*>(&a[4]) = *reinterpret_cast<const float4*>(&As[k][tm + 4]);
            ulonglong2 t0 = *reinterpret_cast<const ulonglong2*>(&Bs[k][tn]);
            ulonglong2 t1 = *reinterpret_cast<const ulonglong2*>(&Bs[k][tn + 4]);
            b2[0] = t0.x; b2[1] = t0.y; b2[2] = t1.x; b2[3] = t1.y;
            #pragma unroll
            for (int i = 0; i < 8; i++) {
                unsigned long long ai = dup_f32x2(a[i]);
                #pragma unroll
                for (int j = 0; j < 4; j++)
                    fma_f32x2(acc2[i][j], ai, b2[j]);
            }
        }
        __syncthreads();
    }

    #pragma unroll
    for (int i = 0; i < 8; i++) {
        float2 p0 = unpack_f32x2(acc2[i][0]);
        float2 p1 = unpack_f32x2(acc2[i][1]);
        float2 p2 = unpack_f32x2(acc2[i][2]);
        float2 p3 = unpack_f32x2(acc2[i][3]);
        size_t off = (size_t)(m0 + tm + i) * NPTS + n0 + tn;
        *reinterpret_cast<float4*>(&C[off])     = make_float4(p0.x, p0.y, p1.x, p1.y);
        *reinterpret_cast<float4*>(&C[off + 4]) = make_float4(p2.x, p2.y, p3.x, p3.y);
    }
}

// ---------------- BN statistics: block per channel --------------------------
__global__ __launch_bounds__(256) void bn_stats_kernel(
    const float* __restrict__ Y, const float* __restrict__ g,
    const float* __restrict__ b, float* __restrict__ sc, float* __restrict__ sh)
{
    const int c = blockIdx.x;
    const float4* row = reinterpret_cast<const float4*>(Y + (size_t)c * NPTS);
    float s = 0.f, s2 = 0.f;
    for (int i = threadIdx.x; i < NPTS / 4; i += 256) {
        float4 v = row[i];
        s  += v.x + v.y + v.z + v.w;
        s2 += v.x * v.x + v.y * v.y + v.z * v.z + v.w * v.w;
    }
    __shared__ float ss[8], ss2[8];
    for (int o = 16; o; o >>= 1) {
        s  += __shfl_xor_sync(0xffffffffu, s, o);
        s2 += __shfl_xor_sync(0xffffffffu, s2, o);
    }
    if ((threadIdx.x & 31) == 0) { ss[threadIdx.x >> 5] = s; ss2[threadIdx.x >> 5] = s2; }
    __syncthreads();
    if (threadIdx.x == 0) {
        s = 0.f; s2 = 0.f;
        #pragma unroll
        for (int i = 0; i < 8; i++) { s += ss[i]; s2 += ss2[i]; }
        float mean = s * (1.f / NPTS);
        float var  = s2 * (1.f / NPTS) - mean * mean;
        float isd  = rsqrtf(var + BN_EPS);
        float scl  = g[c] * isd;
        sc[c] = scl;
        sh[c] = fmaf(-mean, scl, b[c]);
    }
}

// ---------------- final BN+ReLU elementwise ---------------------------------
__global__ __launch_bounds__(256) void bn_apply_kernel(
    const float* __restrict__ Y, const float* __restrict__ sc,
    const float* __restrict__ sh, float* __restrict__ out)
{
    int i = blockIdx.x * 256 + threadIdx.x;       // over float4s: 512*16384/4
    int c = i >> 12;                               // 4096 float4 per channel
    float4 v = reinterpret_cast<const float4*>(Y)[i];
    float s = sc[c], h = sh[c];
    v.x = fmaxf(fmaf(s, v.x, h), 0.f);
    v.y = fmaxf(fmaf(s, v.y, h), 0.f);
    v.z = fmaxf(fmaf(s, v.z, h), 0.f);
    v.w = fmaxf(fmaf(s, v.w, h), 0.f);
    reinterpret_cast<float4*>(out)[i] = v;
}

// ---------------- launch -----------------------------------------------------
extern "C" void kernel_launch(void* const* d_in, const int* in_sizes, int n_in,
                              void* d_out, int out_size)
{
    const float* xyz_fine     = (const float*)d_in[0];
    const float* xyz_coarse   = (const float*)d_in[1];
    const float* feats_fine   = (const float*)d_in[2];
    const float* feats_coarse = (const float*)d_in[3];
    const float* W1 = (const float*)d_in[4];
    const float* g1 = (const float*)d_in[5];
    const float* b1 = (const float*)d_in[6];
    const float* W2 = (const float*)d_in[7];
    const float* g2 = (const float*)d_in[8];
    const float* b2 = (const float*)d_in[9];
    float* out = (float*)d_out;

    void* p;
    cudaGetSymbolAddress(&p, g_fcT);    float* fcT    = (float*)p;
    cudaGetSymbolAddress(&p, g_idx);    int*   idxp   = (int*)p;
    cudaGetSymbolAddress(&p, g_w);      float* wp     = (float*)p;
    cudaGetSymbolAddress(&p, g_interp); float* interp = (float*)p;
    cudaGetSymbolAddress(&p, g_y1);     float* y1     = (float*)p;
    cudaGetSymbolAddress(&p, g_y2);     float* y2     = (float*)p;
    cudaGetSymbolAddress(&p, g_sc1);    float* sc1    = (float*)p;
    cudaGetSymbolAddress(&p, g_sh1);    float* sh1    = (float*)p;
    cudaGetSymbolAddress(&p, g_sc2);    float* sc2    = (float*)p;
    cudaGetSymbolAddress(&p, g_sh2);    float* sh2    = (float*)p;

    transpose_kernel<<<dim3(MPTS / 32, CC / 32), dim3(32, 8)>>>(feats_coarse, fcT);
    knn_kernel<<<NPTS / 8, 256>>>(xyz_fine, xyz_coarse, idxp, wp);
    interp_kernel<<<NPTS / 8, 256>>>(fcT, idxp, wp, interp);

    sgemm_kernel<true, false><<<dim3(NPTS / 128, H1 / 128), 256>>>(
        W1, interp, feats_fine, nullptr, nullptr, y1, INCH);
    bn_stats_kernel<<<H1, 256>>>(y1, g1, b1, sc1, sh1);

    sgemm_kernel<false, true><<<dim3(NPTS / 128, H2 / 128), 256>>>(
        W2, y1, nullptr, sc1, sh1, y2, H1);
    bn_stats_kernel<<<H2, 256>>>(y2, g2, b2, sc2, sh2);

    bn_apply_kernel<<<(H2 * NPTS / 4) / 256, 256>>>(y2, sc2, sh2, out);
}

// round 4
// speedup vs baseline: 1.7026x; 1.6663x over previous
#include <cuda_runtime.h>
#include <cuda_bf16.h>
#include <cstdint>

// Problem constants (fixed by the dataset)
#define NPTS 16384   // fine points
#define MPTS 4096    // coarse points
#define CF   256     // fine feature channels
#define CC   512     // coarse feature channels
#define INCH 768     // CC + CF
#define H1   512
#define H2   512
#define BN_EPS 1e-5f

using bf16 = __nv_bfloat16;

// ---------------- scratch (device globals; no runtime allocation) ----------
__device__ __align__(256) float g_fcT[MPTS * CC];            // [M][CC]
__device__ int   g_idx[NPTS * 3];
__device__ float g_w[NPTS * 3];
__device__ __align__(256) bf16  g_Bt1h[(size_t)NPTS * INCH]; // B1^T hi [N][768]
__device__ __align__(256) bf16  g_Bt1l[(size_t)NPTS * INCH];
__device__ __align__(256) bf16  g_Bt2h[(size_t)NPTS * H1];   // B2^T hi [N][512]
__device__ __align__(256) bf16  g_Bt2l[(size_t)NPTS * H1];
__device__ __align__(256) bf16  g_A1h[H1 * INCH], g_A1l[H1 * INCH];
__device__ __align__(256) bf16  g_A2h[H2 * H1],   g_A2l[H2 * H1];
__device__ __align__(256) float g_y1[(size_t)H1 * NPTS];
__device__ __align__(256) float g_y2[(size_t)H2 * NPTS];
__device__ float g_sc1[H1], g_sh1[H1], g_sc2[H2], g_sh2[H2];

// ---------------- PTX helpers (all baseline, no 103a features) -------------
__device__ __forceinline__ uint32_t smem_u32(const void* p) {
    uint32_t a;
    asm("{ .reg .u64 t; cvta.to.shared.u64 t, %1; cvt.u32.u64 %0, t; }"
        : "=r"(a) : "l"(p));
    return a;
}
__device__ __forceinline__ void cp16(uint32_t dst, const void* src) {
    asm volatile("cp.async.cg.shared.global [%0], [%1], 16;"
                 :: "r"(dst), "l"(src) : "memory");
}
#define CP_COMMIT() asm volatile("cp.async.commit_group;" ::: "memory")
#define CP_WAIT1()  asm volatile("cp.async.wait_group 1;" ::: "memory")

#define LDSM_X4(r, addr) \
    asm volatile("ldmatrix.sync.aligned.m8n8.x4.shared.b16 {%0,%1,%2,%3}, [%4];" \
                 : "=r"((r)[0]), "=r"((r)[1]), "=r"((r)[2]), "=r"((r)[3]) : "r"(addr))
#define LDSM_X2(r, addr) \
    asm volatile("ldmatrix.sync.aligned.m8n8.x2.shared.b16 {%0,%1}, [%2];" \
                 : "=r"((r)[0]), "=r"((r)[1]) : "r"(addr))

__device__ __forceinline__ void mma_bf16(float c[4], const uint32_t a[4],
                                         const uint32_t b[2]) {
    asm volatile(
        "mma.sync.aligned.m16n8k16.row.col.f32.bf16.bf16.f32 "
        "{%0,%1,%2,%3}, {%4,%5,%6,%7}, {%8,%9}, {%0,%1,%2,%3};"
        : "+f"(c[0]), "+f"(c[1]), "+f"(c[2]), "+f"(c[3])
        : "r"(a[0]), "r"(a[1]), "r"(a[2]), "r"(a[3]), "r"(b[0]), "r"(b[1]));
}

__device__ __forceinline__ void split_bf16(float v, bf16& h, bf16& l) {
    h = __float2bfloat16(v);
    l = __float2bfloat16(v - __bfloat162float(h));
}

// ---------------- kNN: warp per query, coarse xyz in smem ------------------
__device__ __forceinline__ void top3_insert(float d, int j,
                                            float& d0, float& d1, float& d2,
                                            int& i0, int& i1, int& i2) {
    if (d < d2) {
        if (d < d1) {
            d2 = d1; i2 = i1;
            if (d < d0) { d1 = d0; i1 = i0; d0 = d; i0 = j; }
            else        { d1 = d;  i1 = j; }
        } else { d2 = d; i2 = j; }
    }
}

__global__ __launch_bounds__(256) void knn_kernel(
    const float* __restrict__ xf, const float* __restrict__ xc,
    int* __restrict__ idx_out, float* __restrict__ w_out)
{
    __shared__ float sx[MPTS], sy[MPTS], sz[MPTS];
    for (int j = threadIdx.x; j < MPTS; j += 256) {
        sx[j] = xc[j];
        sy[j] = xc[MPTS + j];
        sz[j] = xc[2 * MPTS + j];
    }
    __syncthreads();

    const int warp = threadIdx.x >> 5;
    const int lane = threadIdx.x & 31;
    const int n = blockIdx.x * 8 + warp;

    const float qx = xf[n], qy = xf[NPTS + n], qz = xf[2 * NPTS + n];

    float d0 = 3.4e38f, d1 = 3.4e38f, d2 = 3.4e38f;
    int   i0 = 0, i1 = 0, i2 = 0;

    for (int j = lane; j < MPTS; j += 32) {
        float dx = qx - sx[j], dy = qy - sy[j], dz = qz - sz[j];
        float d = fmaf(dx, dx, fmaf(dy, dy, dz * dz));
        top3_insert(d, j, d0, d1, d2, i0, i1, i2);
    }
    for (int off = 16; off; off >>= 1) {
        float od0 = __shfl_xor_sync(0xffffffffu, d0, off);
        float od1 = __shfl_xor_sync(0xffffffffu, d1, off);
        float od2 = __shfl_xor_sync(0xffffffffu, d2, off);
        int   oi0 = __shfl_xor_sync(0xffffffffu, i0, off);
        int   oi1 = __shfl_xor_sync(0xffffffffu, i1, off);
        int   oi2 = __shfl_xor_sync(0xffffffffu, i2, off);
        top3_insert(od0, oi0, d0, d1, d2, i0, i1, i2);
        top3_insert(od1, oi1, d0, d1, d2, i0, i1, i2);
        top3_insert(od2, oi2, d0, d1, d2, i0, i1, i2);
    }
    if (lane == 0) {
        float D0 = fmaxf(sqrtf(d0), 1e-8f);
        float D1 = fmaxf(sqrtf(d1), 1e-8f);
        float D2 = fmaxf(sqrtf(d2), 1e-8f);
        float w0 = 1.f / D0, w1 = 1.f / D1, w2 = 1.f / D2;
        float inv = 1.f / (w0 + w1 + w2);
        idx_out[n * 3 + 0] = i0; idx_out[n * 3 + 1] = i1; idx_out[n * 3 + 2] = i2;
        w_out[n * 3 + 0] = w0 * inv;
        w_out[n * 3 + 1] = w1 * inv;
        w_out[n * 3 + 2] = w2 * inv;
    }
}

// ---------------- transpose feats_coarse [CC][M] -> [M][CC] ----------------
__global__ void transpose_kernel(const float* __restrict__ in, float* __restrict__ out)
{
    __shared__ float t[32][33];
    int bx = blockIdx.x * 32;
    int by = blockIdx.y * 32;
    for (int r = threadIdx.y; r < 32; r += 8)
        t[r][threadIdx.x] = in[(size_t)(by + r) * MPTS + bx + threadIdx.x];
    __syncthreads();
    for (int r = threadIdx.y; r < 32; r += 8)
        out[(size_t)(bx + r) * CC + by + threadIdx.x] = t[threadIdx.x][r];
}

// ---------------- interpolation -> Bt1 rows [n][0..511] (hi/lo bf16) -------
__global__ __launch_bounds__(256) void interp_bt_kernel(
    const float* __restrict__ fcT, const int* __restrict__ idx,
    const float* __restrict__ wgt, bf16* __restrict__ bh, bf16* __restrict__ bl)
{
    const int warp = threadIdx.x >> 5;
    const int lane = threadIdx.x & 31;
    const int n = blockIdx.x * 8 + warp;

    const int i0 = idx[n * 3 + 0], i1 = idx[n * 3 + 1], i2 = idx[n * 3 + 2];
    const float w0 = wgt[n * 3 + 0], w1 = wgt[n * 3 + 1], w2 = wgt[n * 3 + 2];
    const float* __restrict__ r0 = fcT + (size_t)i0 * CC;
    const float* __restrict__ r1 = fcT + (size_t)i1 * CC;
    const float* __restrict__ r2 = fcT + (size_t)i2 * CC;

    for (int c0 = 0; c0 < CC; c0 += 32) {
        int c = c0 + lane;
        float v = fmaf(w0, __ldg(&r0[c]), fmaf(w1, __ldg(&r1[c]), w2 * __ldg(&r2[c])));
        bf16 h, l;
        split_bf16(v, h, l);
        bh[(size_t)n * INCH + c] = h;
        bl[(size_t)n * INCH + c] = l;
    }
}

// ---------------- transpose + (optional BN/ReLU) + split -------------------
__global__ void transpose_split_kernel(
    const float* __restrict__ in, bf16* __restrict__ oh, bf16* __restrict__ ol,
    int outStride, int colOff,
    const float* __restrict__ sc, const float* __restrict__ sh)
{
    __shared__ float t[32][33];
    const int n0 = blockIdx.x * 32;
    const int c0 = blockIdx.y * 32;
    for (int r = threadIdx.y; r < 32; r += 8)
        t[r][threadIdx.x] = in[(size_t)(c0 + r) * NPTS + n0 + threadIdx.x];
    __syncthreads();
    const int ch = c0 + threadIdx.x;
    float s = sc ? sc[ch] : 1.f;
    float b = sc ? sh[ch] : 0.f;
    for (int r = threadIdx.y; r < 32; r += 8) {
        float v = t[threadIdx.x][r];
        if (sc) v = fmaxf(fmaf(s, v, b), 0.f);
        bf16 h, l;
        split_bf16(v, h, l);
        size_t o = (size_t)(n0 + r) * outStride + colOff + ch;
        oh[o] = h;
        ol[o] = l;
    }
}

// ---------------- W -> bf16 hi/lo -------------------------------------------
__global__ void convert_w_kernel(const float* __restrict__ W,
                                 bf16* __restrict__ h, bf16* __restrict__ l, int n)
{
    int i = blockIdx.x * 256 + threadIdx.x;
    if (i < n) {
        bf16 hh, ll;
        split_bf16(W[i], hh, ll);
        h[i] = hh; l[i] = ll;
    }
}

// ---------------- HMMA split-bf16 GEMM --------------------------------------
// C[512][NPTS] = (Ah+Al)[512][K] @ (Bh+Bl)^T, B stored [NPTS][K] K-major bf16.
// CTA 128x128, K-slab 32, 3-stage cp.async, 8 warps 2(M)x4(N), warp 64x32.
static constexpr int ROWH = 40;             // padded halves per 32-half row
static constexpr int MATH = 128 * ROWH;     // halves per matrix tile
static constexpr int STAGE_H = 4 * MATH;    // Ah, Al, Bh, Bl
static constexpr int GEMM_SMEM = 3 * STAGE_H * 2;  // bytes (122880)

__global__ __launch_bounds__(256) void gemm_mma_kernel(
    const bf16* __restrict__ Ah, const bf16* __restrict__ Al,
    const bf16* __restrict__ Bh, const bf16* __restrict__ Bl,
    float* __restrict__ C, int K)
{
    extern __shared__ bf16 sm[];
    const uint32_t base = smem_u32(sm);
    const int tid  = threadIdx.x;
    const int lane = tid & 31;
    const int wid  = tid >> 5;
    const int wm   = wid & 1;       // 2 M-groups of 64
    const int wn   = wid >> 1;      // 4 N-groups of 32
    const int m0 = blockIdx.y * 128;
    const int n0 = blockIdx.x * 128;
    const int nsl = K >> 5;

    float acc[4][4][4] = {};

    auto load_slab = [&](int s, int buf) {
        const int kt = s << 5;
        const uint32_t sb = base + buf * STAGE_H * 2;
        #pragma unroll
        for (int i = 0; i < 2; i++) {
            int id = tid + i * 256;          // 0..511
            int r = id >> 2, seg = id & 3;
            uint32_t off = (uint32_t)(r * ROWH + seg * 8) * 2;
            size_t ga = (size_t)(m0 + r) * K + kt + seg * 8;
            size_t gb = (size_t)(n0 + r) * K + kt + seg * 8;
            cp16(sb + off,                Ah + ga);
            cp16(sb + MATH * 2 + off,     Al + ga);
            cp16(sb + 2 * MATH * 2 + off, Bh + gb);
            cp16(sb + 3 * MATH * 2 + off, Bl + gb);
        }
    };

    auto compute = [&](int buf) {
        const uint32_t sb = base + buf * STAGE_H * 2;
        #pragma unroll
        for (int kk = 0; kk < 2; kk++) {
            const int kh = kk * 16;
            uint32_t fAh[4][4], fAl[4][4], fBh[4][2], fBl[4][2];
            const int arow = wm * 64 + (lane & 15);
            const int acol = kh + ((lane >> 4) << 3);
            #pragma unroll
            for (int mi = 0; mi < 4; mi++) {
                uint32_t ad = sb + (uint32_t)((arow + mi * 16) * ROWH + acol) * 2;
                LDSM_X4(fAh[mi], ad);
                LDSM_X4(fAl[mi], ad + MATH * 2);
            }
            const int brow = wn * 32 + (lane & 7);
            const int bcol = kh + (((lane >> 3) & 1) << 3);
            #pragma unroll
            for (int ni = 0; ni < 4; ni++) {
                uint32_t bd = sb + 2 * MATH * 2 +
                              (uint32_t)((brow + ni * 8) * ROWH + bcol) * 2;
                LDSM_X2(fBh[ni], bd);
                LDSM_X2(fBl[ni], bd + MATH * 2);
            }
            #pragma unroll
            for (int mi = 0; mi < 4; mi++)
                #pragma unroll
                for (int ni = 0; ni < 4; ni++) {
                    mma_bf16(acc[mi][ni], fAh[mi], fBh[ni]);
                    mma_bf16(acc[mi][ni], fAh[mi], fBl[ni]);
                    mma_bf16(acc[mi][ni], fAl[mi], fBh[ni]);
                }
        }
    };

    load_slab(0, 0); CP_COMMIT();
    load_slab(1, 1); CP_COMMIT();

    for (int s = 0; s < nsl; s++) {
        CP_WAIT1();
        __syncthreads();
        int ps = s + 2;
        if (ps < nsl) load_slab(ps, ps % 3);
        CP_COMMIT();
        compute(s % 3);
    }

    // epilogue
    const int gr = lane >> 2;
    const int gc = (lane & 3) * 2;
    #pragma unroll
    for (int mi = 0; mi < 4; mi++) {
        #pragma unroll
        for (int ni = 0; ni < 4; ni++) {
            int row = m0 + wm * 64 + mi * 16 + gr;
            int col = n0 + wn * 32 + ni * 8 + gc;
            *(float2*)&C[(size_t)row * NPTS + col] =
                make_float2(acc[mi][ni][0], acc[mi][ni][1]);
            *(float2*)&C[(size_t)(row + 8) * NPTS + col] =
                make_float2(acc[mi][ni][2], acc[mi][ni][3]);
        }
    }
}

// ---------------- BN statistics: block per channel --------------------------
__global__ __launch_bounds__(256) void bn_stats_kernel(
    const float* __restrict__ Y, const float* __restrict__ g,
    const float* __restrict__ b, float* __restrict__ sc, float* __restrict__ sh)
{
    const int c = blockIdx.x;
    const float4* row = reinterpret_cast<const float4*>(Y + (size_t)c * NPTS);
    float s = 0.f, s2 = 0.f;
    for (int i = threadIdx.x; i < NPTS / 4; i += 256) {
        float4 v = row[i];
        s  += v.x + v.y + v.z + v.w;
        s2 += v.x * v.x + v.y * v.y + v.z * v.z + v.w * v.w;
    }
    __shared__ float ss[8], ss2[8];
    for (int o = 16; o; o >>= 1) {
        s  += __shfl_xor_sync(0xffffffffu, s, o);
        s2 += __shfl_xor_sync(0xffffffffu, s2, o);
    }
    if ((threadIdx.x & 31) == 0) { ss[threadIdx.x >> 5] = s; ss2[threadIdx.x >> 5] = s2; }
    __syncthreads();
    if (threadIdx.x == 0) {
        s = 0.f; s2 = 0.f;
        #pragma unroll
        for (int i = 0; i < 8; i++) { s += ss[i]; s2 += ss2[i]; }
        float mean = s * (1.f / NPTS);
        float var  = s2 * (1.f / NPTS) - mean * mean;
        float isd  = rsqrtf(var + BN_EPS);
        float scl  = g[c] * isd;
        sc[c] = scl;
        sh[c] = fmaf(-mean, scl, b[c]);
    }
}

// ---------------- final BN+ReLU elementwise ---------------------------------
__global__ __launch_bounds__(256) void bn_apply_kernel(
    const float* __restrict__ Y, const float* __restrict__ sc,
    const float* __restrict__ sh, float* __restrict__ out)
{
    int i = blockIdx.x * 256 + threadIdx.x;
    int c = i >> 12;
    float4 v = reinterpret_cast<const float4*>(Y)[i];
    float s = sc[c], h = sh[c];
    v.x = fmaxf(fmaf(s, v.x, h), 0.f);
    v.y = fmaxf(fmaf(s, v.y, h), 0.f);
    v.z = fmaxf(fmaf(s, v.z, h), 0.f);
    v.w = fmaxf(fmaf(s, v.w, h), 0.f);
    reinterpret_cast<float4*>(out)[i] = v;
}

// ---------------- launch -----------------------------------------------------
extern "C" void kernel_launch(void* const* d_in, const int* in_sizes, int n_in,
                              void* d_out, int out_size)
{
    const float* xyz_fine     = (const float*)d_in[0];
    const float* xyz_coarse   = (const float*)d_in[1];
    const float* feats_fine   = (const float*)d_in[2];
    const float* feats_coarse = (const float*)d_in[3];
    const float* W1 = (const float*)d_in[4];
    const float* g1 = (const float*)d_in[5];
    const float* b1 = (const float*)d_in[6];
    const float* W2 = (const float*)d_in[7];
    const float* g2 = (const float*)d_in[8];
    const float* b2 = (const float*)d_in[9];
    float* out = (float*)d_out;

    void* p;
    cudaGetSymbolAddress(&p, g_fcT);  float* fcT  = (float*)p;
    cudaGetSymbolAddress(&p, g_idx);  int*   idxp = (int*)p;
    cudaGetSymbolAddress(&p, g_w);    float* wp   = (float*)p;
    cudaGetSymbolAddress(&p, g_Bt1h); bf16* bt1h = (bf16*)p;
    cudaGetSymbolAddress(&p, g_Bt1l); bf16* bt1l = (bf16*)p;
    cudaGetSymbolAddress(&p, g_Bt2h); bf16* bt2h = (bf16*)p;
    cudaGetSymbolAddress(&p, g_Bt2l); bf16* bt2l = (bf16*)p;
    cudaGetSymbolAddress(&p, g_A1h);  bf16* a1h  = (bf16*)p;
    cudaGetSymbolAddress(&p, g_A1l);  bf16* a1l  = (bf16*)p;
    cudaGetSymbolAddress(&p, g_A2h);  bf16* a2h  = (bf16*)p;
    cudaGetSymbolAddress(&p, g_A2l);  bf16* a2l  = (bf16*)p;
    cudaGetSymbolAddress(&p, g_y1);   float* y1  = (float*)p;
    cudaGetSymbolAddress(&p, g_y2);   float* y2  = (float*)p;
    cudaGetSymbolAddress(&p, g_sc1);  float* sc1 = (float*)p;
    cudaGetSymbolAddress(&p, g_sh1);  float* sh1 = (float*)p;
    cudaGetSymbolAddress(&p, g_sc2);  float* sc2 = (float*)p;
    cudaGetSymbolAddress(&p, g_sh2);  float* sh2 = (float*)p;

    cudaFuncSetAttribute(gemm_mma_kernel,
                         cudaFuncAttributeMaxDynamicSharedMemorySize, GEMM_SMEM);

    transpose_kernel<<<dim3(MPTS / 32, CC / 32), dim3(32, 8)>>>(feats_coarse, fcT);
    knn_kernel<<<NPTS / 8, 256>>>(xyz_fine, xyz_coarse, idxp, wp);
    interp_bt_kernel<<<NPTS / 8, 256>>>(fcT, idxp, wp, bt1h, bt1l);
    transpose_split_kernel<<<dim3(NPTS / 32, CF / 32), dim3(32, 8)>>>(
        feats_fine, bt1h, bt1l, INCH, CC, nullptr, nullptr);
    convert_w_kernel<<<(H1 * INCH + 255) / 256, 256>>>(W1, a1h, a1l, H1 * INCH);
    convert_w_kernel<<<(H2 * H1 + 255) / 256, 256>>>(W2, a2h, a2l, H2 * H1);

    gemm_mma_kernel<<<dim3(NPTS / 128, H1 / 128), 256, GEMM_SMEM>>>(
        a1h, a1l, bt1h, bt1l, y1, INCH);
    bn_stats_kernel<<<H1, 256>>>(y1, g1, b1, sc1, sh1);

    transpose_split_kernel<<<dim3(NPTS / 32, H1 / 32), dim3(32, 8)>>>(
        y1, bt2h, bt2l, H1, 0, sc1, sh1);

    gemm_mma_kernel<<<dim3(NPTS / 128, H2 / 128), 256, GEMM_SMEM>>>(
        a2h, a2l, bt2h, bt2l, y2, H1);
    bn_stats_kernel<<<H2, 256>>>(y2, g2, b2, sc2, sh2);

    bn_apply_kernel<<<(H2 * NPTS / 4) / 256, 256>>>(y2, sc2, sh2, out);
}

// round 5
// speedup vs baseline: 1.7041x; 1.0009x over previous
#include <cuda_runtime.h>
#include <cuda_bf16.h>
#include <cstdint>

// Problem constants (fixed by the dataset)
#define NPTS 16384   // fine points
#define MPTS 4096    // coarse points
#define CF   256     // fine feature channels
#define CC   512     // coarse feature channels
#define INCH 768     // CC + CF
#define H1   512
#define H2   512
#define BN_EPS 1e-5f

using bf16 = __nv_bfloat16;

// ---------------- scratch (device globals; no runtime allocation) ----------
__device__ __align__(256) float g_fcT[MPTS * CC];            // [M][CC]
__device__ int   g_idx[NPTS * 3];
__device__ float g_w[NPTS * 3];
__device__ __align__(256) bf16  g_Bt1h[(size_t)NPTS * INCH]; // B1^T hi [N][768]
__device__ __align__(256) bf16  g_Bt1l[(size_t)NPTS * INCH];
__device__ __align__(256) bf16  g_Bt2h[(size_t)NPTS * H1];   // B2^T hi [N][512]
__device__ __align__(256) bf16  g_Bt2l[(size_t)NPTS * H1];
__device__ __align__(256) bf16  g_A1h[H1 * INCH], g_A1l[H1 * INCH];
__device__ __align__(256) bf16  g_A2h[H2 * H1],   g_A2l[H2 * H1];
__device__ __align__(256) float g_y1[(size_t)H1 * NPTS];
__device__ __align__(256) float g_y2[(size_t)H2 * NPTS];
__device__ float g_sc1[H1], g_sh1[H1], g_sc2[H2], g_sh2[H2];

// ---------------- PTX helpers (all baseline, no 103a features) -------------
__device__ __forceinline__ uint32_t smem_u32(const void* p) {
    uint32_t a;
    asm("{ .reg .u64 t; cvta.to.shared.u64 t, %1; cvt.u32.u64 %0, t; }"
        : "=r"(a) : "l"(p));
    return a;
}
__device__ __forceinline__ void cp16(uint32_t dst, const void* src) {
    asm volatile("cp.async.cg.shared.global [%0], [%1], 16;"
                 :: "r"(dst), "l"(src) : "memory");
}
#define CP_COMMIT() asm volatile("cp.async.commit_group;" ::: "memory")
#define CP_WAIT1()  asm volatile("cp.async.wait_group 1;" ::: "memory")

#define LDSM_X4(r, addr) \
    asm volatile("ldmatrix.sync.aligned.m8n8.x4.shared.b16 {%0,%1,%2,%3}, [%4];" \
                 : "=r"((r)[0]), "=r"((r)[1]), "=r"((r)[2]), "=r"((r)[3]) : "r"(addr))
#define LDSM_X2(r, addr) \
    asm volatile("ldmatrix.sync.aligned.m8n8.x2.shared.b16 {%0,%1}, [%2];" \
                 : "=r"((r)[0]), "=r"((r)[1]) : "r"(addr))

__device__ __forceinline__ void mma_bf16(float c[4], const uint32_t a[4],
                                         const uint32_t b[2]) {
    asm volatile(
        "mma.sync.aligned.m16n8k16.row.col.f32.bf16.bf16.f32 "
        "{%0,%1,%2,%3}, {%4,%5,%6,%7}, {%8,%9}, {%0,%1,%2,%3};"
        : "+f"(c[0]), "+f"(c[1]), "+f"(c[2]), "+f"(c[3])
        : "r"(a[0]), "r"(a[1]), "r"(a[2]), "r"(a[3]), "r"(b[0]), "r"(b[1]));
}

__device__ __forceinline__ void split_bf16(float v, bf16& h, bf16& l) {
    h = __float2bfloat16(v);
    l = __float2bfloat16(v - __bfloat162float(h));
}

// ---------------- kNN: warp per query, coarse xyz in smem ------------------
__device__ __forceinline__ void top3_insert(float d, int j,
                                            float& d0, float& d1, float& d2,
                                            int& i0, int& i1, int& i2) {
    if (d < d2) {
        if (d < d1) {
            d2 = d1; i2 = i1;
            if (d < d0) { d1 = d0; i1 = i0; d0 = d; i0 = j; }
            else        { d1 = d;  i1 = j; }
        } else { d2 = d; i2 = j; }
    }
}

__global__ __launch_bounds__(256) void knn_kernel(
    const float* __restrict__ xf, const float* __restrict__ xc,
    int* __restrict__ idx_out, float* __restrict__ w_out)
{
    __shared__ float sx[MPTS], sy[MPTS], sz[MPTS];
    for (int j = threadIdx.x; j < MPTS; j += 256) {
        sx[j] = xc[j];
        sy[j] = xc[MPTS + j];
        sz[j] = xc[2 * MPTS + j];
    }
    __syncthreads();

    const int warp = threadIdx.x >> 5;
    const int lane = threadIdx.x & 31;
    const int n = blockIdx.x * 8 + warp;

    const float qx = xf[n], qy = xf[NPTS + n], qz = xf[2 * NPTS + n];

    float d0 = 3.4e38f, d1 = 3.4e38f, d2 = 3.4e38f;
    int   i0 = 0, i1 = 0, i2 = 0;

    for (int j = lane; j < MPTS; j += 32) {
        float dx = qx - sx[j], dy = qy - sy[j], dz = qz - sz[j];
        float d = fmaf(dx, dx, fmaf(dy, dy, dz * dz));
        top3_insert(d, j, d0, d1, d2, i0, i1, i2);
    }
    for (int off = 16; off; off >>= 1) {
        float od0 = __shfl_xor_sync(0xffffffffu, d0, off);
        float od1 = __shfl_xor_sync(0xffffffffu, d1, off);
        float od2 = __shfl_xor_sync(0xffffffffu, d2, off);
        int   oi0 = __shfl_xor_sync(0xffffffffu, i0, off);
        int   oi1 = __shfl_xor_sync(0xffffffffu, i1, off);
        int   oi2 = __shfl_xor_sync(0xffffffffu, i2, off);
        top3_insert(od0, oi0, d0, d1, d2, i0, i1, i2);
        top3_insert(od1, oi1, d0, d1, d2, i0, i1, i2);
        top3_insert(od2, oi2, d0, d1, d2, i0, i1, i2);
    }
    if (lane == 0) {
        float D0 = fmaxf(sqrtf(d0), 1e-8f);
        float D1 = fmaxf(sqrtf(d1), 1e-8f);
        float D2 = fmaxf(sqrtf(d2), 1e-8f);
        float w0 = 1.f / D0, w1 = 1.f / D1, w2 = 1.f / D2;
        float inv = 1.f / (w0 + w1 + w2);
        idx_out[n * 3 + 0] = i0; idx_out[n * 3 + 1] = i1; idx_out[n * 3 + 2] = i2;
        w_out[n * 3 + 0] = w0 * inv;
        w_out[n * 3 + 1] = w1 * inv;
        w_out[n * 3 + 2] = w2 * inv;
    }
}

// ---------------- transpose feats_coarse [CC][M] -> [M][CC] ----------------
__global__ void transpose_kernel(const float* __restrict__ in, float* __restrict__ out)
{
    __shared__ float t[32][33];
    int bx = blockIdx.x * 32;
    int by = blockIdx.y * 32;
    for (int r = threadIdx.y; r < 32; r += 8)
        t[r][threadIdx.x] = in[(size_t)(by + r) * MPTS + bx + threadIdx.x];
    __syncthreads();
    for (int r = threadIdx.y; r < 32; r += 8)
        out[(size_t)(bx + r) * CC + by + threadIdx.x] = t[threadIdx.x][r];
}

// ---------------- interpolation -> Bt1 rows [n][0..511] (hi/lo bf16) -------
__global__ __launch_bounds__(256) void interp_bt_kernel(
    const float* __restrict__ fcT, const int* __restrict__ idx,
    const float* __restrict__ wgt, bf16* __restrict__ bh, bf16* __restrict__ bl)
{
    const int warp = threadIdx.x >> 5;
    const int lane = threadIdx.x & 31;
    const int n = blockIdx.x * 8 + warp;

    const int i0 = idx[n * 3 + 0], i1 = idx[n * 3 + 1], i2 = idx[n * 3 + 2];
    const float w0 = wgt[n * 3 + 0], w1 = wgt[n * 3 + 1], w2 = wgt[n * 3 + 2];
    const float* __restrict__ r0 = fcT + (size_t)i0 * CC;
    const float* __restrict__ r1 = fcT + (size_t)i1 * CC;
    const float* __restrict__ r2 = fcT + (size_t)i2 * CC;

    for (int c0 = 0; c0 < CC; c0 += 32) {
        int c = c0 + lane;
        float v = fmaf(w0, __ldg(&r0[c]), fmaf(w1, __ldg(&r1[c]), w2 * __ldg(&r2[c])));
        bf16 h, l;
        split_bf16(v, h, l);
        bh[(size_t)n * INCH + c] = h;
        bl[(size_t)n * INCH + c] = l;
    }
}

// ---------------- transpose + (optional BN/ReLU) + split -------------------
__global__ void transpose_split_kernel(
    const float* __restrict__ in, bf16* __restrict__ oh, bf16* __restrict__ ol,
    int outStride, int colOff,
    const float* __restrict__ sc, const float* __restrict__ sh)
{
    __shared__ float t[32][33];
    const int n0 = blockIdx.x * 32;
    const int c0 = blockIdx.y * 32;
    for (int r = threadIdx.y; r < 32; r += 8)
        t[r][threadIdx.x] = in[(size_t)(c0 + r) * NPTS + n0 + threadIdx.x];
    __syncthreads();
    const int ch = c0 + threadIdx.x;
    float s = sc ? sc[ch] : 1.f;
    float b = sc ? sh[ch] : 0.f;
    for (int r = threadIdx.y; r < 32; r += 8) {
        float v = t[threadIdx.x][r];
        if (sc) v = fmaxf(fmaf(s, v, b), 0.f);
        bf16 h, l;
        split_bf16(v, h, l);
        size_t o = (size_t)(n0 + r) * outStride + colOff + ch;
        oh[o] = h;
        ol[o] = l;
    }
}

// ---------------- W -> bf16 hi/lo -------------------------------------------
__global__ void convert_w_kernel(const float* __restrict__ W,
                                 bf16* __restrict__ h, bf16* __restrict__ l, int n)
{
    int i = blockIdx.x * 256 + threadIdx.x;
    if (i < n) {
        bf16 hh, ll;
        split_bf16(W[i], hh, ll);
        h[i] = hh; l[i] = ll;
    }
}

// ---------------- HMMA split-bf16 GEMM --------------------------------------
// C[512][NPTS] = (Ah+Al)[512][K] @ (Bh+Bl)^T, B stored [NPTS][K] K-major bf16.
// CTA 128x128, K-slab 32, 3-stage cp.async, 8 warps 2(M)x4(N), warp 64x32.
// MMA issue is TERM-MAJOR: 16 independent accumulators between same-acc reuse.
static constexpr int ROWH = 40;             // padded halves per 32-half row
static constexpr int MATH = 128 * ROWH;     // halves per matrix tile
static constexpr int STAGE_H = 4 * MATH;    // Ah, Al, Bh, Bl
static constexpr int GEMM_SMEM = 3 * STAGE_H * 2;  // bytes (122880)

__global__ __launch_bounds__(256) void gemm_mma_kernel(
    const bf16* __restrict__ Ah, const bf16* __restrict__ Al,
    const bf16* __restrict__ Bh, const bf16* __restrict__ Bl,
    float* __restrict__ C, int K)
{
    extern __shared__ bf16 sm[];
    const uint32_t base = smem_u32(sm);
    const int tid  = threadIdx.x;
    const int lane = tid & 31;
    const int wid  = tid >> 5;
    const int wm   = wid & 1;       // 2 M-groups of 64
    const int wn   = wid >> 1;      // 4 N-groups of 32
    const int m0 = blockIdx.y * 128;
    const int n0 = blockIdx.x * 128;
    const int nsl = K >> 5;

    float acc[4][4][4] = {};

    auto load_slab = [&](int s, int buf) {
        const int kt = s << 5;
        const uint32_t sb = base + buf * STAGE_H * 2;
        #pragma unroll
        for (int i = 0; i < 2; i++) {
            int id = tid + i * 256;          // 0..511
            int r = id >> 2, seg = id & 3;
            uint32_t off = (uint32_t)(r * ROWH + seg * 8) * 2;
            size_t ga = (size_t)(m0 + r) * K + kt + seg * 8;
            size_t gb = (size_t)(n0 + r) * K + kt + seg * 8;
            cp16(sb + off,                Ah + ga);
            cp16(sb + MATH * 2 + off,     Al + ga);
            cp16(sb + 2 * MATH * 2 + off, Bh + gb);
            cp16(sb + 3 * MATH * 2 + off, Bl + gb);
        }
    };

    auto compute = [&](int buf) {
        const uint32_t sb = base + buf * STAGE_H * 2;
        #pragma unroll
        for (int kk = 0; kk < 2; kk++) {
            const int kh = kk * 16;
            uint32_t fAh[4][4], fAl[4][4], fBh[4][2], fBl[4][2];
            const int arow = wm * 64 + (lane & 15);
            const int acol = kh + ((lane >> 4) << 3);
            #pragma unroll
            for (int mi = 0; mi < 4; mi++) {
                uint32_t ad = sb + (uint32_t)((arow + mi * 16) * ROWH + acol) * 2;
                LDSM_X4(fAh[mi], ad);
                LDSM_X4(fAl[mi], ad + MATH * 2);
            }
            const int brow = wn * 32 + (lane & 7);
            const int bcol = kh + (((lane >> 3) & 1) << 3);
            #pragma unroll
            for (int ni = 0; ni < 4; ni++) {
                uint32_t bd = sb + 2 * MATH * 2 +
                              (uint32_t)((brow + ni * 8) * ROWH + bcol) * 2;
                LDSM_X2(fBh[ni], bd);
                LDSM_X2(fBl[ni], bd + MATH * 2);
            }
            // term-major: 16 independent accs between same-acc reuse
            #pragma unroll
            for (int mi = 0; mi < 4; mi++)
                #pragma unroll
                for (int ni = 0; ni < 4; ni++)
                    mma_bf16(acc[mi][ni], fAh[mi], fBh[ni]);
            #pragma unroll
            for (int mi = 0; mi < 4; mi++)
                #pragma unroll
                for (int ni = 0; ni < 4; ni++)
                    mma_bf16(acc[mi][ni], fAh[mi], fBl[ni]);
            #pragma unroll
            for (int mi = 0; mi < 4; mi++)
                #pragma unroll
                for (int ni = 0; ni < 4; ni++)
                    mma_bf16(acc[mi][ni], fAl[mi], fBh[ni]);
        }
    };

    load_slab(0, 0); CP_COMMIT();
    load_slab(1, 1); CP_COMMIT();

    for (int s = 0; s < nsl; s++) {
        CP_WAIT1();
        __syncthreads();
        int ps = s + 2;
        if (ps < nsl) load_slab(ps, ps % 3);
        CP_COMMIT();
        compute(s % 3);
    }

    // epilogue
    const int gr = lane >> 2;
    const int gc = (lane & 3) * 2;
    #pragma unroll
    for (int mi = 0; mi < 4; mi++) {
        #pragma unroll
        for (int ni = 0; ni < 4; ni++) {
            int row = m0 + wm * 64 + mi * 16 + gr;
            int col = n0 + wn * 32 + ni * 8 + gc;
            *(float2*)&C[(size_t)row * NPTS + col] =
                make_float2(acc[mi][ni][0], acc[mi][ni][1]);
            *(float2*)&C[(size_t)(row + 8) * NPTS + col] =
                make_float2(acc[mi][ni][2], acc[mi][ni][3]);
        }
    }
}

// ---------------- BN statistics: block per channel --------------------------
__global__ __launch_bounds__(256) void bn_stats_kernel(
    const float* __restrict__ Y, const float* __restrict__ g,
    const float* __restrict__ b, float* __restrict__ sc, float* __restrict__ sh)
{
    const int c = blockIdx.x;
    const float4* row = reinterpret_cast<const float4*>(Y + (size_t)c * NPTS);
    float s = 0.f, s2 = 0.f;
    for (int i = threadIdx.x; i < NPTS / 4; i += 256) {
        float4 v = row[i];
        s  += v.x + v.y + v.z + v.w;
        s2 += v.x * v.x + v.y * v.y + v.z * v.z + v.w * v.w;
    }
    __shared__ float ss[8], ss2[8];
    for (int o = 16; o; o >>= 1) {
        s  += __shfl_xor_sync(0xffffffffu, s, o);
        s2 += __shfl_xor_sync(0xffffffffu, s2, o);
    }
    if ((threadIdx.x & 31) == 0) { ss[threadIdx.x >> 5] = s; ss2[threadIdx.x >> 5] = s2; }
    __syncthreads();
    if (threadIdx.x == 0) {
        s = 0.f; s2 = 0.f;
        #pragma unroll
        for (int i = 0; i < 8; i++) { s += ss[i]; s2 += ss2[i]; }
        float mean = s * (1.f / NPTS);
        float var  = s2 * (1.f / NPTS) - mean * mean;
        float isd  = rsqrtf(var + BN_EPS);
        float scl  = g[c] * isd;
        sc[c] = scl;
        sh[c] = fmaf(-mean, scl, b[c]);
    }
}

// ---------------- final BN+ReLU elementwise ---------------------------------
__global__ __launch_bounds__(256) void bn_apply_kernel(
    const float* __restrict__ Y, const float* __restrict__ sc,
    const float* __restrict__ sh, float* __restrict__ out)
{
    int i = blockIdx.x * 256 + threadIdx.x;
    int c = i >> 12;
    float4 v = reinterpret_cast<const float4*>(Y)[i];
    float s = sc[c], h = sh[c];
    v.x = fmaxf(fmaf(s, v.x, h), 0.f);
    v.y = fmaxf(fmaf(s, v.y, h), 0.f);
    v.z = fmaxf(fmaf(s, v.z, h), 0.f);
    v.w = fmaxf(fmaf(s, v.w, h), 0.f);
    reinterpret_cast<float4*>(out)[i] = v;
}

// ---------------- launch -----------------------------------------------------
extern "C" void kernel_launch(void* const* d_in, const int* in_sizes, int n_in,
                              void* d_out, int out_size)
{
    const float* xyz_fine     = (const float*)d_in[0];
    const float* xyz_coarse   = (const float*)d_in[1];
    const float* feats_fine   = (const float*)d_in[2];
    const float* feats_coarse = (const float*)d_in[3];
    const float* W1 = (const float*)d_in[4];
    const float* g1 = (const float*)d_in[5];
    const float* b1 = (const float*)d_in[6];
    const float* W2 = (const float*)d_in[7];
    const float* g2 = (const float*)d_in[8];
    const float* b2 = (const float*)d_in[9];
    float* out = (float*)d_out;

    void* p;
    cudaGetSymbolAddress(&p, g_fcT);  float* fcT  = (float*)p;
    cudaGetSymbolAddress(&p, g_idx);  int*   idxp = (int*)p;
    cudaGetSymbolAddress(&p, g_w);    float* wp   = (float*)p;
    cudaGetSymbolAddress(&p, g_Bt1h); bf16* bt1h = (bf16*)p;
    cudaGetSymbolAddress(&p, g_Bt1l); bf16* bt1l = (bf16*)p;
    cudaGetSymbolAddress(&p, g_Bt2h); bf16* bt2h = (bf16*)p;
    cudaGetSymbolAddress(&p, g_Bt2l); bf16* bt2l = (bf16*)p;
    cudaGetSymbolAddress(&p, g_A1h);  bf16* a1h  = (bf16*)p;
    cudaGetSymbolAddress(&p, g_A1l);  bf16* a1l  = (bf16*)p;
    cudaGetSymbolAddress(&p, g_A2h);  bf16* a2h  = (bf16*)p;
    cudaGetSymbolAddress(&p, g_A2l);  bf16* a2l  = (bf16*)p;
    cudaGetSymbolAddress(&p, g_y1);   float* y1  = (float*)p;
    cudaGetSymbolAddress(&p, g_y2);   float* y2  = (float*)p;
    cudaGetSymbolAddress(&p, g_sc1);  float* sc1 = (float*)p;
    cudaGetSymbolAddress(&p, g_sh1);  float* sh1 = (float*)p;
    cudaGetSymbolAddress(&p, g_sc2);  float* sc2 = (float*)p;
    cudaGetSymbolAddress(&p, g_sh2);  float* sh2 = (float*)p;

    cudaFuncSetAttribute(gemm_mma_kernel,
                         cudaFuncAttributeMaxDynamicSharedMemorySize, GEMM_SMEM);

    transpose_kernel<<<dim3(MPTS / 32, CC / 32), dim3(32, 8)>>>(feats_coarse, fcT);
    knn_kernel<<<NPTS / 8, 256>>>(xyz_fine, xyz_coarse, idxp, wp);
    interp_bt_kernel<<<NPTS / 8, 256>>>(fcT, idxp, wp, bt1h, bt1l);
    transpose_split_kernel<<<dim3(NPTS / 32, CF / 32), dim3(32, 8)>>>(
        feats_fine, bt1h, bt1l, INCH, CC, nullptr, nullptr);
    convert_w_kernel<<<(H1 * INCH + 255) / 256, 256>>>(W1, a1h, a1l, H1 * INCH);
    convert_w_kernel<<<(H2 * H1 + 255) / 256, 256>>>(W2, a2h, a2l, H2 * H1);

    gemm_mma_kernel<<<dim3(NPTS / 128, H1 / 128), 256, GEMM_SMEM>>>(
        a1h, a1l, bt1h, bt1l, y1, INCH);
    bn_stats_kernel<<<H1, 256>>>(y1, g1, b1, sc1, sh1);

    transpose_split_kernel<<<dim3(NPTS / 32, H1 / 32), dim3(32, 8)>>>(
        y1, bt2h, bt2l, H1, 0, sc1, sh1);

    gemm_mma_kernel<<<dim3(NPTS / 128, H2 / 128), 256, GEMM_SMEM>>>(
        a2h, a2l, bt2h, bt2l, y2, H1);
    bn_stats_kernel<<<H2, 256>>>(y2, g2, b2, sc2, sh2);

    bn_apply_kernel<<<(H2 * NPTS / 4) / 256, 256>>>(y2, sc2, sh2, out);
}

// round 7
// speedup vs baseline: 2.4041x; 1.4107x over previous
#include <cuda_runtime.h>
#include <cuda_fp16.h>
#include <cstdint>

// Problem constants (fixed by the dataset)
#define NPTS 16384   // fine points
#define MPTS 4096    // coarse points
#define CF   256     // fine feature channels
#define CC   512     // coarse feature channels
#define INCH 768     // CC + CF
#define H1   512
#define H2   512
#define BN_EPS 1e-5f

// ---------------- scratch (device globals; no runtime allocation) ----------
__device__ __align__(256) float  g_fcT[MPTS * CC];            // [M][CC]
__device__ int    g_idx[NPTS * 3];
__device__ float  g_w[NPTS * 3];
__device__ __align__(256) __half g_Bt1[(size_t)NPTS * INCH];  // B1^T fp16 [N][768]
__device__ __align__(256) __half g_Bt2[(size_t)NPTS * H1];    // B2^T fp16 [N][512]
__device__ __align__(256) __half g_A1h[H1 * INCH], g_A1l[H1 * INCH];
__device__ __align__(256) __half g_A2h[H2 * H1],   g_A2l[H2 * H1];
__device__ __align__(256) float  g_y1[(size_t)H1 * NPTS];
__device__ __align__(256) float  g_y2[(size_t)H2 * NPTS];
__device__ float g_sum1[H1], g_sq1[H1], g_sum2[H2], g_sq2[H2];
__device__ float g_sc1[H1], g_sh1[H1], g_sc2[H2], g_sh2[H2];

// ---------------- PTX helpers (all baseline, no 103a features) -------------
__device__ __forceinline__ uint32_t smem_u32(const void* p) {
    uint32_t a;
    asm("{ .reg .u64 t; cvta.to.shared.u64 t, %1; cvt.u32.u64 %0, t; }"
        : "=r"(a) : "l"(p));
    return a;
}
__device__ __forceinline__ void cp16(uint32_t dst, const void* src) {
    asm volatile("cp.async.cg.shared.global [%0], [%1], 16;"
                 :: "r"(dst), "l"(src) : "memory");
}
#define CP_COMMIT() asm volatile("cp.async.commit_group;" ::: "memory")
#define CP_WAIT1()  asm volatile("cp.async.wait_group 1;" ::: "memory")

#define LDSM_X4(r, addr) \
    asm volatile("ldmatrix.sync.aligned.m8n8.x4.shared.b16 {%0,%1,%2,%3}, [%4];" \
                 : "=r"((r)[0]), "=r"((r)[1]), "=r"((r)[2]), "=r"((r)[3]) : "r"(addr))
#define LDSM_X2(r, addr) \
    asm volatile("ldmatrix.sync.aligned.m8n8.x2.shared.b16 {%0,%1}, [%2];" \
                 : "=r"((r)[0]), "=r"((r)[1]) : "r"(addr))

__device__ __forceinline__ void mma_f16(float c[4], const uint32_t a[4],
                                        const uint32_t b[2]) {
    asm volatile(
        "mma.sync.aligned.m16n8k16.row.col.f32.f16.f16.f32 "
        "{%0,%1,%2,%3}, {%4,%5,%6,%7}, {%8,%9}, {%0,%1,%2,%3};"
        : "+f"(c[0]), "+f"(c[1]), "+f"(c[2]), "+f"(c[3])
        : "r"(a[0]), "r"(a[1]), "r"(a[2]), "r"(a[3]), "r"(b[0]), "r"(b[1]));
}

__device__ __forceinline__ void split_f16(float v, __half& h, __half& l) {
    h = __float2half(v);
    l = __float2half(v - __half2float(h));
}

// ---------------- zero BN-stat accumulators (graph-safe) --------------------
__global__ void zero_stats_kernel(float* s1, float* q1, float* s2, float* q2)
{
    int i = threadIdx.x + blockIdx.x * 256;
    if (i < H1) { s1[i] = 0.f; q1[i] = 0.f; }
    if (i < H2) { s2[i] = 0.f; q2[i] = 0.f; }
}

// ---------------- kNN: warp per query, coarse xyz in smem ------------------
__device__ __forceinline__ void top3_insert(float d, int j,
                                            float& d0, float& d1, float& d2,
                                            int& i0, int& i1, int& i2) {
    if (d < d2) {
        if (d < d1) {
            d2 = d1; i2 = i1;
            if (d < d0) { d1 = d0; i1 = i0; d0 = d; i0 = j; }
            else        { d1 = d;  i1 = j; }
        } else { d2 = d; i2 = j; }
    }
}

__global__ __launch_bounds__(256) void knn_kernel(
    const float* __restrict__ xf, const float* __restrict__ xc,
    int* __restrict__ idx_out, float* __restrict__ w_out)
{
    __shared__ float sx[MPTS], sy[MPTS], sz[MPTS];
    for (int j = threadIdx.x; j < MPTS; j += 256) {
        sx[j] = xc[j];
        sy[j] = xc[MPTS + j];
        sz[j] = xc[2 * MPTS + j];
    }
    __syncthreads();

    const int warp = threadIdx.x >> 5;
    const int lane = threadIdx.x & 31;
    const int n = blockIdx.x * 8 + warp;

    const float qx = xf[n], qy = xf[NPTS + n], qz = xf[2 * NPTS + n];

    float d0 = 3.4e38f, d1 = 3.4e38f, d2 = 3.4e38f;
    int   i0 = 0, i1 = 0, i2 = 0;

    for (int j = lane; j < MPTS; j += 32) {
        float dx = qx - sx[j], dy = qy - sy[j], dz = qz - sz[j];
        float d = fmaf(dx, dx, fmaf(dy, dy, dz * dz));
        top3_insert(d, j, d0, d1, d2, i0, i1, i2);
    }
    for (int off = 16; off; off >>= 1) {
        float od0 = __shfl_xor_sync(0xffffffffu, d0, off);
        float od1 = __shfl_xor_sync(0xffffffffu, d1, off);
        float od2 = __shfl_xor_sync(0xffffffffu, d2, off);
        int   oi0 = __shfl_xor_sync(0xffffffffu, i0, off);
        int   oi1 = __shfl_xor_sync(0xffffffffu, i1, off);
        int   oi2 = __shfl_xor_sync(0xffffffffu, i2, off);
        top3_insert(od0, oi0, d0, d1, d2, i0, i1, i2);
        top3_insert(od1, oi1, d0, d1, d2, i0, i1, i2);
        top3_insert(od2, oi2, d0, d1, d2, i0, i1, i2);
    }
    if (lane == 0) {
        float D0 = fmaxf(sqrtf(d0), 1e-8f);
        float D1 = fmaxf(sqrtf(d1), 1e-8f);
        float D2 = fmaxf(sqrtf(d2), 1e-8f);
        float w0 = 1.f / D0, w1 = 1.f / D1, w2 = 1.f / D2;
        float inv = 1.f / (w0 + w1 + w2);
        idx_out[n * 3 + 0] = i0; idx_out[n * 3 + 1] = i1; idx_out[n * 3 + 2] = i2;
        w_out[n * 3 + 0] = w0 * inv;
        w_out[n * 3 + 1] = w1 * inv;
        w_out[n * 3 + 2] = w2 * inv;
    }
}

// ---------------- transpose feats_coarse [CC][M] -> [M][CC] ----------------
__global__ void transpose_kernel(const float* __restrict__ in, float* __restrict__ out)
{
    __shared__ float t[32][33];
    int bx = blockIdx.x * 32;
    int by = blockIdx.y * 32;
    for (int r = threadIdx.y; r < 32; r += 8)
        t[r][threadIdx.x] = in[(size_t)(by + r) * MPTS + bx + threadIdx.x];
    __syncthreads();
    for (int r = threadIdx.y; r < 32; r += 8)
        out[(size_t)(bx + r) * CC + by + threadIdx.x] = t[threadIdx.x][r];
}

// ---------------- interpolation -> Bt1 rows [n][0..511] fp16 ---------------
__global__ __launch_bounds__(256) void interp_bt_kernel(
    const float* __restrict__ fcT, const int* __restrict__ idx,
    const float* __restrict__ wgt, __half* __restrict__ bt)
{
    const int warp = threadIdx.x >> 5;
    const int lane = threadIdx.x & 31;
    const int n = blockIdx.x * 8 + warp;

    const int i0 = idx[n * 3 + 0], i1 = idx[n * 3 + 1], i2 = idx[n * 3 + 2];
    const float w0 = wgt[n * 3 + 0], w1 = wgt[n * 3 + 1], w2 = wgt[n * 3 + 2];
    const float* __restrict__ r0 = fcT + (size_t)i0 * CC;
    const float* __restrict__ r1 = fcT + (size_t)i1 * CC;
    const float* __restrict__ r2 = fcT + (size_t)i2 * CC;

    for (int c0 = 0; c0 < CC; c0 += 32) {
        int c = c0 + lane;
        float v = fmaf(w0, __ldg(&r0[c]), fmaf(w1, __ldg(&r1[c]), w2 * __ldg(&r2[c])));
        bt[(size_t)n * INCH + c] = __float2half(v);
    }
}

// ---------------- transpose + (optional BN/ReLU) -> fp16 -------------------
__global__ void transpose_h_kernel(
    const float* __restrict__ in, __half* __restrict__ oh,
    int outStride, int colOff,
    const float* __restrict__ sc, const float* __restrict__ sh)
{
    __shared__ float t[32][33];
    const int n0 = blockIdx.x * 32;
    const int c0 = blockIdx.y * 32;
    for (int r = threadIdx.y; r < 32; r += 8)
        t[r][threadIdx.x] = in[(size_t)(c0 + r) * NPTS + n0 + threadIdx.x];
    __syncthreads();
    const int ch = c0 + threadIdx.x;
    float s = sc ? sc[ch] : 1.f;
    float b = sc ? sh[ch] : 0.f;
    for (int r = threadIdx.y; r < 32; r += 8) {
        float v = t[threadIdx.x][r];
        if (sc) v = fmaxf(fmaf(s, v, b), 0.f);
        oh[(size_t)(n0 + r) * outStride + colOff + ch] = __float2half(v);
    }
}

// ---------------- W -> fp16 hi/lo -------------------------------------------
__global__ void convert_w_kernel(const float* __restrict__ W,
                                 __half* __restrict__ h, __half* __restrict__ l, int n)
{
    int i = blockIdx.x * 256 + threadIdx.x;
    if (i < n) {
        __half hh, ll;
        split_f16(W[i], hh, ll);
        h[i] = hh; l[i] = ll;
    }
}

// ---------------- HMMA fp16 2-term GEMM + fused BN-stats --------------------
// C[512][NPTS] = (Ah+Al)[512][K] @ B^T, B stored [NPTS][K] fp16.
// CTA 128x128, K-slab 32, 3-stage cp.async, 8 warps 2(M)x4(N).
static constexpr int ROWH = 40;                 // padded halves per 32-half row
static constexpr int TILE_B = 128 * ROWH * 2;   // bytes per 128x32 tile (10240)
static constexpr int STAGE_B = 3 * TILE_B;      // Ah, Al, B  (30720)
static constexpr int GEMM_SMEM = 3 * STAGE_B;   // 92160 bytes

__global__ __launch_bounds__(256, 2) void gemm_mma_kernel(
    const __half* __restrict__ Ah, const __half* __restrict__ Al,
    const __half* __restrict__ B, float* __restrict__ C, int K,
    float* __restrict__ gsum, float* __restrict__ gsq)
{
    extern __shared__ __half sm[];
    const uint32_t base = smem_u32(sm);
    const int tid  = threadIdx.x;
    const int lane = tid & 31;
    const int wid  = tid >> 5;
    const int wm   = wid & 1;       // 2 M-groups of 64
    const int wn   = wid >> 1;      // 4 N-groups of 32
    const int m0 = blockIdx.y * 128;
    const int n0 = blockIdx.x * 128;
    const int nsl = K >> 5;

    float acc[4][4][4] = {};

    auto load_slab = [&](int s, int buf) {
        const int kt = s << 5;
        const uint32_t sb = base + buf * STAGE_B;
        #pragma unroll
        for (int i = 0; i < 2; i++) {
            int id = tid + i * 256;          // 0..511
            int r = id >> 2, seg = id & 3;
            uint32_t off = (uint32_t)(r * ROWH + seg * 8) * 2;
            size_t ga = (size_t)(m0 + r) * K + kt + seg * 8;
            size_t gb = (size_t)(n0 + r) * K + kt + seg * 8;
            cp16(sb + off,              Ah + ga);
            cp16(sb + TILE_B + off,     Al + ga);
            cp16(sb + 2 * TILE_B + off, B + gb);
        }
    };

    auto compute = [&](int buf) {
        const uint32_t sb = base + buf * STAGE_B;
        #pragma unroll
        for (int kk = 0; kk < 2; kk++) {
            const int kh = kk * 16;
            uint32_t fB[4][2];
            const int brow = wn * 32 + (lane & 7);
            const int bcol = kh + (((lane >> 3) & 1) << 3);
            #pragma unroll
            for (int ni = 0; ni < 4; ni++) {
                uint32_t bd = sb + 2 * TILE_B +
                              (uint32_t)((brow + ni * 8) * ROWH + bcol) * 2;
                LDSM_X2(fB[ni], bd);
            }
            const int arow = wm * 64 + (lane & 15);
            const int acol = kh + ((lane >> 4) << 3);
            {
                uint32_t fA[4][4];
                #pragma unroll
                for (int mi = 0; mi < 4; mi++) {
                    uint32_t ad = sb + (uint32_t)((arow + mi * 16) * ROWH + acol) * 2;
                    LDSM_X4(fA[mi], ad);
                }
                #pragma unroll
                for (int mi = 0; mi < 4; mi++)
                    #pragma unroll
                    for (int ni = 0; ni < 4; ni++)
                        mma_f16(acc[mi][ni], fA[mi], fB[ni]);
            }
            {
                uint32_t fA[4][4];
                #pragma unroll
                for (int mi = 0; mi < 4; mi++) {
                    uint32_t ad = sb + TILE_B +
                                  (uint32_t)((arow + mi * 16) * ROWH + acol) * 2;
                    LDSM_X4(fA[mi], ad);
                }
                #pragma unroll
                for (int mi = 0; mi < 4; mi++)
                    #pragma unroll
                    for (int ni = 0; ni < 4; ni++)
                        mma_f16(acc[mi][ni], fA[mi], fB[ni]);
            }
        }
    };

    load_slab(0, 0); CP_COMMIT();
    load_slab(1, 1); CP_COMMIT();

    for (int s = 0; s < nsl; s++) {
        CP_WAIT1();
        __syncthreads();
        int ps = s + 2;
        if (ps < nsl) load_slab(ps, ps % 3);
        CP_COMMIT();
        compute(s % 3);
    }

    // epilogue: store C + per-channel partial sums for BN stats
    const int gr = lane >> 2;
    const int gc = (lane & 3) * 2;
    #pragma unroll
    for (int mi = 0; mi < 4; mi++) {
        #pragma unroll
        for (int ni = 0; ni < 4; ni++) {
            int row = m0 + wm * 64 + mi * 16 + gr;
            int col = n0 + wn * 32 + ni * 8 + gc;
            *(float2*)&C[(size_t)row * NPTS + col] =
                make_float2(acc[mi][ni][0], acc[mi][ni][1]);
            *(float2*)&C[(size_t)(row + 8) * NPTS + col] =
                make_float2(acc[mi][ni][2], acc[mi][ni][3]);
        }
        #pragma unroll
        for (int h2 = 0; h2 < 2; h2++) {
            float s = 0.f, q = 0.f;
            #pragma unroll
            for (int ni = 0; ni < 4; ni++) {
                float v0 = acc[mi][ni][2 * h2], v1 = acc[mi][ni][2 * h2 + 1];
                s += v0 + v1;
                q += v0 * v0 + v1 * v1;
            }
            s += __shfl_xor_sync(0xffffffffu, s, 1);
            q += __shfl_xor_sync(0xffffffffu, q, 1);
            s += __shfl_xor_sync(0xffffffffu, s, 2);
            q += __shfl_xor_sync(0xffffffffu, q, 2);
            if ((lane & 3) == 0) {
                int row = m0 + wm * 64 + mi * 16 + gr + h2 * 8;
                atomicAdd(&gsum[row], s);
                atomicAdd(&gsq[row], q);
            }
        }
    }
}

// ---------------- BN finalize: stats -> scale/shift --------------------------
__global__ void bn_finalize_kernel(
    const float* __restrict__ sum, const float* __restrict__ sq,
    const float* __restrict__ g, const float* __restrict__ b,
    float* __restrict__ sc, float* __restrict__ sh)
{
    int c = threadIdx.x + blockIdx.x * 256;
    float mean = sum[c] * (1.f / NPTS);
    float var  = sq[c] * (1.f / NPTS) - mean * mean;
    float isd  = rsqrtf(var + BN_EPS);
    float scl  = g[c] * isd;
    sc[c] = scl;
    sh[c] = fmaf(-mean, scl, b[c]);
}

// ---------------- final BN+ReLU elementwise ---------------------------------
__global__ __launch_bounds__(256) void bn_apply_kernel(
    const float* __restrict__ Y, const float* __restrict__ sc,
    const float* __restrict__ sh, float* __restrict__ out)
{
    int i = blockIdx.x * 256 + threadIdx.x;
    int c = i >> 12;
    float4 v = reinterpret_cast<const float4*>(Y)[i];
    float s = sc[c], h = sh[c];
    v.x = fmaxf(fmaf(s, v.x, h), 0.f);
    v.y = fmaxf(fmaf(s, v.y, h), 0.f);
    v.z = fmaxf(fmaf(s, v.z, h), 0.f);
    v.w = fmaxf(fmaf(s, v.w, h), 0.f);
    reinterpret_cast<float4*>(out)[i] = v;
}

// ---------------- launch -----------------------------------------------------
extern "C" void kernel_launch(void* const* d_in, const int* in_sizes, int n_in,
                              void* d_out, int out_size)
{
    const float* xyz_fine     = (const float*)d_in[0];
    const float* xyz_coarse   = (const float*)d_in[1];
    const float* feats_fine   = (const float*)d_in[2];
    const float* feats_coarse = (const float*)d_in[3];
    const float* W1 = (const float*)d_in[4];
    const float* g1 = (const float*)d_in[5];
    const float* b1 = (const float*)d_in[6];
    const float* W2 = (const float*)d_in[7];
    const float* g2 = (const float*)d_in[8];
    const float* b2 = (const float*)d_in[9];
    float* out = (float*)d_out;

    void* p;
    cudaGetSymbolAddress(&p, g_fcT);  float*  fcT  = (float*)p;
    cudaGetSymbolAddress(&p, g_idx);  int*    idxp = (int*)p;
    cudaGetSymbolAddress(&p, g_w);    float*  wp   = (float*)p;
    cudaGetSymbolAddress(&p, g_Bt1);  __half* bt1  = (__half*)p;
    cudaGetSymbolAddress(&p, g_Bt2);  __half* bt2  = (__half*)p;
    cudaGetSymbolAddress(&p, g_A1h);  __half* a1h  = (__half*)p;
    cudaGetSymbolAddress(&p, g_A1l);  __half* a1l  = (__half*)p;
    cudaGetSymbolAddress(&p, g_A2h);  __half* a2h  = (__half*)p;
    cudaGetSymbolAddress(&p, g_A2l);  __half* a2l  = (__half*)p;
    cudaGetSymbolAddress(&p, g_y1);   float*  y1   = (float*)p;
    cudaGetSymbolAddress(&p, g_y2);   float*  y2   = (float*)p;
    cudaGetSymbolAddress(&p, g_sum1); float*  sum1 = (float*)p;
    cudaGetSymbolAddress(&p, g_sq1);  float*  sq1  = (float*)p;
    cudaGetSymbolAddress(&p, g_sum2); float*  sum2 = (float*)p;
    cudaGetSymbolAddress(&p, g_sq2);  float*  sq2  = (float*)p;
    cudaGetSymbolAddress(&p, g_sc1);  float*  sc1  = (float*)p;
    cudaGetSymbolAddress(&p, g_sh1);  float*  sh1  = (float*)p;
    cudaGetSymbolAddress(&p, g_sc2);  float*  sc2  = (float*)p;
    cudaGetSymbolAddress(&p, g_sh2);  float*  sh2  = (float*)p;

    cudaFuncSetAttribute(gemm_mma_kernel,
                         cudaFuncAttributeMaxDynamicSharedMemorySize, GEMM_SMEM);

    zero_stats_kernel<<<2, 256>>>(sum1, sq1, sum2, sq2);

    transpose_kernel<<<dim3(MPTS / 32, CC / 32), dim3(32, 8)>>>(feats_coarse, fcT);
    knn_kernel<<<NPTS / 8, 256>>>(xyz_fine, xyz_coarse, idxp, wp);
    interp_bt_kernel<<<NPTS / 8, 256>>>(fcT, idxp, wp, bt1);
    transpose_h_kernel<<<dim3(NPTS / 32, CF / 32), dim3(32, 8)>>>(
        feats_fine, bt1, INCH, CC, nullptr, nullptr);
    convert_w_kernel<<<(H1 * INCH + 255) / 256, 256>>>(W1, a1h, a1l, H1 * INCH);
    convert_w_kernel<<<(H2 * H1 + 255) / 256, 256>>>(W2, a2h, a2l, H2 * H1);

    gemm_mma_kernel<<<dim3(NPTS / 128, H1 / 128), 256, GEMM_SMEM>>>(
        a1h, a1l, bt1, y1, INCH, sum1, sq1);
    bn_finalize_kernel<<<H1 / 256, 256>>>(sum1, sq1, g1, b1, sc1, sh1);

    transpose_h_kernel<<<dim3(NPTS / 32, H1 / 32), dim3(32, 8)>>>(
        y1, bt2, H1, 0, sc1, sh1);

    gemm_mma_kernel<<<dim3(NPTS / 128, H2 / 128), 256, GEMM_SMEM>>>(
        a2h, a2l, bt2, y2, H1, sum2, sq2);
    bn_finalize_kernel<<<H2 / 256, 256>>>(sum2, sq2, g2, b2, sc2, sh2);

    bn_apply_kernel<<<(H2 * NPTS / 4) / 256, 256>>>(y2, sc2, sh2, out);
}

// round 8
// speedup vs baseline: 2.9022x; 1.2072x over previous
#include <cuda_runtime.h>
#include <cuda_fp16.h>
#include <cstdint>

// Problem constants (fixed by the dataset)
#define NPTS 16384   // fine points
#define MPTS 4096    // coarse points
#define CF   256     // fine feature channels
#define CC   512     // coarse feature channels
#define INCH 768     // CC + CF
#define H1   512
#define H2   512
#define BN_EPS 1e-5f

// ---------------- scratch (device globals; no runtime allocation) ----------
__device__ __align__(256) float  g_fcT[MPTS * CC];            // [M][CC]
__device__ int    g_idx[NPTS * 3];
__device__ float  g_w[NPTS * 3];
__device__ __align__(256) __half g_Bt1[(size_t)NPTS * INCH];  // B1^T fp16 [N][768]
__device__ __align__(256) __half g_Bt2[(size_t)NPTS * H1];    // B2^T fp16 [N][512]
__device__ __align__(256) __half g_A1[H1 * INCH];
__device__ __align__(256) __half g_A2[H2 * H1];
__device__ __align__(256) float  g_y1[(size_t)H1 * NPTS];
__device__ __align__(256) float  g_y2[(size_t)H2 * NPTS];
__device__ float g_sum1[H1], g_sq1[H1], g_sum2[H2], g_sq2[H2];
__device__ float g_sc1[H1], g_sh1[H1], g_sc2[H2], g_sh2[H2];

// ---------------- PTX helpers (all baseline, no 103a features) -------------
__device__ __forceinline__ uint32_t smem_u32(const void* p) {
    uint32_t a;
    asm("{ .reg .u64 t; cvta.to.shared.u64 t, %1; cvt.u32.u64 %0, t; }"
        : "=r"(a) : "l"(p));
    return a;
}
__device__ __forceinline__ void cp16(uint32_t dst, const void* src) {
    asm volatile("cp.async.cg.shared.global [%0], [%1], 16;"
                 :: "r"(dst), "l"(src) : "memory");
}
#define CP_COMMIT() asm volatile("cp.async.commit_group;" ::: "memory")
#define CP_WAIT1()  asm volatile("cp.async.wait_group 1;" ::: "memory")

#define LDSM_X4(r, addr) \
    asm volatile("ldmatrix.sync.aligned.m8n8.x4.shared.b16 {%0,%1,%2,%3}, [%4];" \
                 : "=r"((r)[0]), "=r"((r)[1]), "=r"((r)[2]), "=r"((r)[3]) : "r"(addr))
#define LDSM_X2(r, addr) \
    asm volatile("ldmatrix.sync.aligned.m8n8.x2.shared.b16 {%0,%1}, [%2];" \
                 : "=r"((r)[0]), "=r"((r)[1]) : "r"(addr))

__device__ __forceinline__ void mma_f16(float c[4], const uint32_t a[4],
                                        const uint32_t b[2]) {
    asm volatile(
        "mma.sync.aligned.m16n8k16.row.col.f32.f16.f16.f32 "
        "{%0,%1,%2,%3}, {%4,%5,%6,%7}, {%8,%9}, {%0,%1,%2,%3};"
        : "+f"(c[0]), "+f"(c[1]), "+f"(c[2]), "+f"(c[3])
        : "r"(a[0]), "r"(a[1]), "r"(a[2]), "r"(a[3]), "r"(b[0]), "r"(b[1]));
}

// ---------------- zero BN-stat accumulators (graph-safe) --------------------
__global__ void zero_stats_kernel(float* s1, float* q1, float* s2, float* q2)
{
    int i = threadIdx.x + blockIdx.x * 256;
    if (i < H1) { s1[i] = 0.f; q1[i] = 0.f; }
    if (i < H2) { s2[i] = 0.f; q2[i] = 0.f; }
}

// ---------------- kNN: warp per query, coarse xyz in smem ------------------
__device__ __forceinline__ void top3_insert(float d, int j,
                                            float& d0, float& d1, float& d2,
                                            int& i0, int& i1, int& i2) {
    if (d < d2) {
        if (d < d1) {
            d2 = d1; i2 = i1;
            if (d < d0) { d1 = d0; i1 = i0; d0 = d; i0 = j; }
            else        { d1 = d;  i1 = j; }
        } else { d2 = d; i2 = j; }
    }
}

__global__ __launch_bounds__(256) void knn_kernel(
    const float* __restrict__ xf, const float* __restrict__ xc,
    int* __restrict__ idx_out, float* __restrict__ w_out)
{
    __shared__ float sx[MPTS], sy[MPTS], sz[MPTS];
    for (int j = threadIdx.x; j < MPTS; j += 256) {
        sx[j] = xc[j];
        sy[j] = xc[MPTS + j];
        sz[j] = xc[2 * MPTS + j];
    }
    __syncthreads();

    const int warp = threadIdx.x >> 5;
    const int lane = threadIdx.x & 31;
    const int n = blockIdx.x * 8 + warp;

    const float qx = xf[n], qy = xf[NPTS + n], qz = xf[2 * NPTS + n];

    float d0 = 3.4e38f, d1 = 3.4e38f, d2 = 3.4e38f;
    int   i0 = 0, i1 = 0, i2 = 0;

    for (int j = lane; j < MPTS; j += 32) {
        float dx = qx - sx[j], dy = qy - sy[j], dz = qz - sz[j];
        float d = fmaf(dx, dx, fmaf(dy, dy, dz * dz));
        top3_insert(d, j, d0, d1, d2, i0, i1, i2);
    }
    for (int off = 16; off; off >>= 1) {
        float od0 = __shfl_xor_sync(0xffffffffu, d0, off);
        float od1 = __shfl_xor_sync(0xffffffffu, d1, off);
        float od2 = __shfl_xor_sync(0xffffffffu, d2, off);
        int   oi0 = __shfl_xor_sync(0xffffffffu, i0, off);
        int   oi1 = __shfl_xor_sync(0xffffffffu, i1, off);
        int   oi2 = __shfl_xor_sync(0xffffffffu, i2, off);
        top3_insert(od0, oi0, d0, d1, d2, i0, i1, i2);
        top3_insert(od1, oi1, d0, d1, d2, i0, i1, i2);
        top3_insert(od2, oi2, d0, d1, d2, i0, i1, i2);
    }
    if (lane == 0) {
        float D0 = fmaxf(sqrtf(d0), 1e-8f);
        float D1 = fmaxf(sqrtf(d1), 1e-8f);
        float D2 = fmaxf(sqrtf(d2), 1e-8f);
        float w0 = 1.f / D0, w1 = 1.f / D1, w2 = 1.f / D2;
        float inv = 1.f / (w0 + w1 + w2);
        idx_out[n * 3 + 0] = i0; idx_out[n * 3 + 1] = i1; idx_out[n * 3 + 2] = i2;
        w_out[n * 3 + 0] = w0 * inv;
        w_out[n * 3 + 1] = w1 * inv;
        w_out[n * 3 + 2] = w2 * inv;
    }
}

// ---------------- transpose feats_coarse [CC][M] -> [M][CC] ----------------
__global__ void transpose_kernel(const float* __restrict__ in, float* __restrict__ out)
{
    __shared__ float t[32][33];
    int bx = blockIdx.x * 32;
    int by = blockIdx.y * 32;
    for (int r = threadIdx.y; r < 32; r += 8)
        t[r][threadIdx.x] = in[(size_t)(by + r) * MPTS + bx + threadIdx.x];
    __syncthreads();
    for (int r = threadIdx.y; r < 32; r += 8)
        out[(size_t)(bx + r) * CC + by + threadIdx.x] = t[threadIdx.x][r];
}

// ---------------- interpolation -> Bt1 rows [n][0..511] fp16 ---------------
__global__ __launch_bounds__(256) void interp_bt_kernel(
    const float* __restrict__ fcT, const int* __restrict__ idx,
    const float* __restrict__ wgt, __half* __restrict__ bt)
{
    const int warp = threadIdx.x >> 5;
    const int lane = threadIdx.x & 31;
    const int n = blockIdx.x * 8 + warp;

    const int i0 = idx[n * 3 + 0], i1 = idx[n * 3 + 1], i2 = idx[n * 3 + 2];
    const float w0 = wgt[n * 3 + 0], w1 = wgt[n * 3 + 1], w2 = wgt[n * 3 + 2];
    const float* __restrict__ r0 = fcT + (size_t)i0 * CC;
    const float* __restrict__ r1 = fcT + (size_t)i1 * CC;
    const float* __restrict__ r2 = fcT + (size_t)i2 * CC;

    for (int c0 = 0; c0 < CC; c0 += 32) {
        int c = c0 + lane;
        float v = fmaf(w0, __ldg(&r0[c]), fmaf(w1, __ldg(&r1[c]), w2 * __ldg(&r2[c])));
        bt[(size_t)n * INCH + c] = __float2half(v);
    }
}

// ---------------- transpose + (optional BN/ReLU) -> fp16 -------------------
__global__ void transpose_h_kernel(
    const float* __restrict__ in, __half* __restrict__ oh,
    int outStride, int colOff,
    const float* __restrict__ sc, const float* __restrict__ sh)
{
    __shared__ float t[32][33];
    const int n0 = blockIdx.x * 32;
    const int c0 = blockIdx.y * 32;
    for (int r = threadIdx.y; r < 32; r += 8)
        t[r][threadIdx.x] = in[(size_t)(c0 + r) * NPTS + n0 + threadIdx.x];
    __syncthreads();
    const int ch = c0 + threadIdx.x;
    float s = sc ? sc[ch] : 1.f;
    float b = sc ? sh[ch] : 0.f;
    for (int r = threadIdx.y; r < 32; r += 8) {
        float v = t[threadIdx.x][r];
        if (sc) v = fmaxf(fmaf(s, v, b), 0.f);
        oh[(size_t)(n0 + r) * outStride + colOff + ch] = __float2half(v);
    }
}

// ---------------- W -> fp16 -------------------------------------------------
__global__ void convert_w_kernel(const float* __restrict__ W,
                                 __half* __restrict__ h, int n)
{
    int i = blockIdx.x * 256 + threadIdx.x;
    if (i < n) h[i] = __float2half(W[i]);
}

// ---------------- HMMA fp16 1-term GEMM + fused BN-stats --------------------
// C[512][NPTS] = A[512][K] @ B^T, A,B fp16, B stored [NPTS][K].
// CTA 128x128, K-slab 32, 3-stage cp.async, 8 warps 2(M)x4(N).
static constexpr int ROWH = 40;                 // padded halves per 32-half row
static constexpr int TILE_B = 128 * ROWH * 2;   // bytes per 128x32 tile (10240)
static constexpr int STAGE_B = 2 * TILE_B;      // A, B (20480)
static constexpr int GEMM_SMEM = 3 * STAGE_B;   // 61440 bytes

__global__ __launch_bounds__(256, 2) void gemm_mma_kernel(
    const __half* __restrict__ A, const __half* __restrict__ B,
    float* __restrict__ C, int K,
    float* __restrict__ gsum, float* __restrict__ gsq)
{
    extern __shared__ __half sm[];
    const uint32_t base = smem_u32(sm);
    const int tid  = threadIdx.x;
    const int lane = tid & 31;
    const int wid  = tid >> 5;
    const int wm   = wid & 1;       // 2 M-groups of 64
    const int wn   = wid >> 1;      // 4 N-groups of 32
    const int m0 = blockIdx.y * 128;
    const int n0 = blockIdx.x * 128;
    const int nsl = K >> 5;

    float acc[4][4][4] = {};

    auto load_slab = [&](int s, int buf) {
        const int kt = s << 5;
        const uint32_t sb = base + buf * STAGE_B;
        #pragma unroll
        for (int i = 0; i < 2; i++) {
            int id = tid + i * 256;          // 0..511
            int r = id >> 2, seg = id & 3;
            uint32_t off = (uint32_t)(r * ROWH + seg * 8) * 2;
            size_t ga = (size_t)(m0 + r) * K + kt + seg * 8;
            size_t gb = (size_t)(n0 + r) * K + kt + seg * 8;
            cp16(sb + off,          A + ga);
            cp16(sb + TILE_B + off, B + gb);
        }
    };

    auto compute = [&](int buf) {
        const uint32_t sb = base + buf * STAGE_B;
        #pragma unroll
        for (int kk = 0; kk < 2; kk++) {
            const int kh = kk * 16;
            uint32_t fB[4][2];
            const int brow = wn * 32 + (lane & 7);
            const int bcol = kh + (((lane >> 3) & 1) << 3);
            #pragma unroll
            for (int ni = 0; ni < 4; ni++) {
                uint32_t bd = sb + TILE_B +
                              (uint32_t)((brow + ni * 8) * ROWH + bcol) * 2;
                LDSM_X2(fB[ni], bd);
            }
            const int arow = wm * 64 + (lane & 15);
            const int acol = kh + ((lane >> 4) << 3);
            uint32_t fA[4][4];
            #pragma unroll
            for (int mi = 0; mi < 4; mi++) {
                uint32_t ad = sb + (uint32_t)((arow + mi * 16) * ROWH + acol) * 2;
                LDSM_X4(fA[mi], ad);
            }
            #pragma unroll
            for (int mi = 0; mi < 4; mi++)
                #pragma unroll
                for (int ni = 0; ni < 4; ni++)
                    mma_f16(acc[mi][ni], fA[mi], fB[ni]);
        }
    };

    load_slab(0, 0); CP_COMMIT();
    load_slab(1, 1); CP_COMMIT();

    for (int s = 0; s < nsl; s++) {
        CP_WAIT1();
        __syncthreads();
        int ps = s + 2;
        if (ps < nsl) load_slab(ps, ps % 3);
        CP_COMMIT();
        compute(s % 3);
    }

    // epilogue: store C + per-channel partial sums for BN stats
    const int gr = lane >> 2;
    const int gc = (lane & 3) * 2;
    #pragma unroll
    for (int mi = 0; mi < 4; mi++) {
        #pragma unroll
        for (int ni = 0; ni < 4; ni++) {
            int row = m0 + wm * 64 + mi * 16 + gr;
            int col = n0 + wn * 32 + ni * 8 + gc;
            *(float2*)&C[(size_t)row * NPTS + col] =
                make_float2(acc[mi][ni][0], acc[mi][ni][1]);
            *(float2*)&C[(size_t)(row + 8) * NPTS + col] =
                make_float2(acc[mi][ni][2], acc[mi][ni][3]);
        }
        #pragma unroll
        for (int h2 = 0; h2 < 2; h2++) {
            float s = 0.f, q = 0.f;
            #pragma unroll
            for (int ni = 0; ni < 4; ni++) {
                float v0 = acc[mi][ni][2 * h2], v1 = acc[mi][ni][2 * h2 + 1];
                s += v0 + v1;
                q += v0 * v0 + v1 * v1;
            }
            s += __shfl_xor_sync(0xffffffffu, s, 1);
            q += __shfl_xor_sync(0xffffffffu, q, 1);
            s += __shfl_xor_sync(0xffffffffu, s, 2);
            q += __shfl_xor_sync(0xffffffffu, q, 2);
            if ((lane & 3) == 0) {
                int row = m0 + wm * 64 + mi * 16 + gr + h2 * 8;
                atomicAdd(&gsum[row], s);
                atomicAdd(&gsq[row], q);
            }
        }
    }
}

// ---------------- BN finalize: stats -> scale/shift --------------------------
__global__ void bn_finalize_kernel(
    const float* __restrict__ sum, const float* __restrict__ sq,
    const float* __restrict__ g, const float* __restrict__ b,
    float* __restrict__ sc, float* __restrict__ sh)
{
    int c = threadIdx.x + blockIdx.x * 256;
    float mean = sum[c] * (1.f / NPTS);
    float var  = sq[c] * (1.f / NPTS) - mean * mean;
    float isd  = rsqrtf(var + BN_EPS);
    float scl  = g[c] * isd;
    sc[c] = scl;
    sh[c] = fmaf(-mean, scl, b[c]);
}

// ---------------- final BN+ReLU elementwise ---------------------------------
__global__ __launch_bounds__(256) void bn_apply_kernel(
    const float* __restrict__ Y, const float* __restrict__ sc,
    const float* __restrict__ sh, float* __restrict__ out)
{
    int i = blockIdx.x * 256 + threadIdx.x;
    int c = i >> 12;
    float4 v = reinterpret_cast<const float4*>(Y)[i];
    float s = sc[c], h = sh[c];
    v.x = fmaxf(fmaf(s, v.x, h), 0.f);
    v.y = fmaxf(fmaf(s, v.y, h), 0.f);
    v.z = fmaxf(fmaf(s, v.z, h), 0.f);
    v.w = fmaxf(fmaf(s, v.w, h), 0.f);
    reinterpret_cast<float4*>(out)[i] = v;
}

// ---------------- launch -----------------------------------------------------
extern "C" void kernel_launch(void* const* d_in, const int* in_sizes, int n_in,
                              void* d_out, int out_size)
{
    const float* xyz_fine     = (const float*)d_in[0];
    const float* xyz_coarse   = (const float*)d_in[1];
    const float* feats_fine   = (const float*)d_in[2];
    const float* feats_coarse = (const float*)d_in[3];
    const float* W1 = (const float*)d_in[4];
    const float* g1 = (const float*)d_in[5];
    const float* b1 = (const float*)d_in[6];
    const float* W2 = (const float*)d_in[7];
    const float* g2 = (const float*)d_in[8];
    const float* b2 = (const float*)d_in[9];
    float* out = (float*)d_out;

    void* p;
    cudaGetSymbolAddress(&p, g_fcT);  float*  fcT  = (float*)p;
    cudaGetSymbolAddress(&p, g_idx);  int*    idxp = (int*)p;
    cudaGetSymbolAddress(&p, g_w);    float*  wp   = (float*)p;
    cudaGetSymbolAddress(&p, g_Bt1);  __half* bt1  = (__half*)p;
    cudaGetSymbolAddress(&p, g_Bt2);  __half* bt2  = (__half*)p;
    cudaGetSymbolAddress(&p, g_A1);   __half* a1   = (__half*)p;
    cudaGetSymbolAddress(&p, g_A2);   __half* a2   = (__half*)p;
    cudaGetSymbolAddress(&p, g_y1);   float*  y1   = (float*)p;
    cudaGetSymbolAddress(&p, g_y2);   float*  y2   = (float*)p;
    cudaGetSymbolAddress(&p, g_sum1); float*  sum1 = (float*)p;
    cudaGetSymbolAddress(&p, g_sq1);  float*  sq1  = (float*)p;
    cudaGetSymbolAddress(&p, g_sum2); float*  sum2 = (float*)p;
    cudaGetSymbolAddress(&p, g_sq2);  float*  sq2  = (float*)p;
    cudaGetSymbolAddress(&p, g_sc1);  float*  sc1  = (float*)p;
    cudaGetSymbolAddress(&p, g_sh1);  float*  sh1  = (float*)p;
    cudaGetSymbolAddress(&p, g_sc2);  float*  sc2  = (float*)p;
    cudaGetSymbolAddress(&p, g_sh2);  float*  sh2  = (float*)p;

    cudaFuncSetAttribute(gemm_mma_kernel,
                         cudaFuncAttributeMaxDynamicSharedMemorySize, GEMM_SMEM);

    zero_stats_kernel<<<2, 256>>>(sum1, sq1, sum2, sq2);

    transpose_kernel<<<dim3(MPTS / 32, CC / 32), dim3(32, 8)>>>(feats_coarse, fcT);
    knn_kernel<<<NPTS / 8, 256>>>(xyz_fine, xyz_coarse, idxp, wp);
    interp_bt_kernel<<<NPTS / 8, 256>>>(fcT, idxp, wp, bt1);
    transpose_h_kernel<<<dim3(NPTS / 32, CF / 32), dim3(32, 8)>>>(
        feats_fine, bt1, INCH, CC, nullptr, nullptr);
    convert_w_kernel<<<(H1 * INCH + 255) / 256, 256>>>(W1, a1, H1 * INCH);
    convert_w_kernel<<<(H2 * H1 + 255) / 256, 256>>>(W2, a2, H2 * H1);

    gemm_mma_kernel<<<dim3(NPTS / 128, H1 / 128), 256, GEMM_SMEM>>>(
        a1, bt1, y1, INCH, sum1, sq1);
    bn_finalize_kernel<<<H1 / 256, 256>>>(sum1, sq1, g1, b1, sc1, sh1);

    transpose_h_kernel<<<dim3(NPTS / 32, H1 / 32), dim3(32, 8)>>>(
        y1, bt2, H1, 0, sc1, sh1);

    gemm_mma_kernel<<<dim3(NPTS / 128, H2 / 128), 256, GEMM_SMEM>>>(
        a2, bt2, y2, H1, sum2, sq2);
    bn_finalize_kernel<<<H2 / 256, 256>>>(sum2, sq2, g2, b2, sc2, sh2);

    bn_apply_kernel<<<(H2 * NPTS / 4) / 256, 256>>>(y2, sc2, sh2, out);
}

// round 9
// speedup vs baseline: 2.9495x; 1.0163x over previous
#include <cuda_runtime.h>
#include <cuda_fp16.h>
#include <cstdint>

// Problem constants (fixed by the dataset)
#define NPTS 16384   // fine points
#define MPTS 4096    // coarse points
#define CF   256     // fine feature channels
#define CC   512     // coarse feature channels
#define INCH 768     // CC + CF
#define H1   512
#define H2   512
#define BN_EPS 1e-5f

// ---------------- scratch (device globals; no runtime allocation) ----------
__device__ __align__(256) float  g_fcT[MPTS * CC];            // [M][CC]
__device__ int    g_idx[NPTS * 3];
__device__ float  g_w[NPTS * 3];
__device__ __align__(256) __half g_Bt1[(size_t)NPTS * INCH];  // B1^T fp16 [N][768]
__device__ __align__(256) __half g_Bt2[(size_t)NPTS * H1];    // B2^T fp16 [N][512]
__device__ __align__(256) __half g_A1[H1 * INCH];
__device__ __align__(256) __half g_A2[H2 * H1];
__device__ __align__(256) float  g_y1[(size_t)H1 * NPTS];
__device__ __align__(256) float  g_y2[(size_t)H2 * NPTS];
__device__ float g_sum1[H1], g_sq1[H1], g_sum2[H2], g_sq2[H2];

// ---------------- PTX helpers (all baseline, no 103a features) -------------
__device__ __forceinline__ uint32_t smem_u32(const void* p) {
    uint32_t a;
    asm("{ .reg .u64 t; cvta.to.shared.u64 t, %1; cvt.u32.u64 %0, t; }"
        : "=r"(a) : "l"(p));
    return a;
}
__device__ __forceinline__ void cp16(uint32_t dst, const void* src) {
    asm volatile("cp.async.cg.shared.global [%0], [%1], 16;"
                 :: "r"(dst), "l"(src) : "memory");
}
#define CP_COMMIT() asm volatile("cp.async.commit_group;" ::: "memory")
#define CP_WAIT1()  asm volatile("cp.async.wait_group 1;" ::: "memory")

#define LDSM_X4(r, addr) \
    asm volatile("ldmatrix.sync.aligned.m8n8.x4.shared.b16 {%0,%1,%2,%3}, [%4];" \
                 : "=r"((r)[0]), "=r"((r)[1]), "=r"((r)[2]), "=r"((r)[3]) : "r"(addr))
#define LDSM_X2(r, addr) \
    asm volatile("ldmatrix.sync.aligned.m8n8.x2.shared.b16 {%0,%1}, [%2];" \
                 : "=r"((r)[0]), "=r"((r)[1]) : "r"(addr))

__device__ __forceinline__ void mma_f16(float c[4], const uint32_t a[4],
                                        const uint32_t b[2]) {
    asm volatile(
        "mma.sync.aligned.m16n8k16.row.col.f32.f16.f16.f32 "
        "{%0,%1,%2,%3}, {%4,%5,%6,%7}, {%8,%9}, {%0,%1,%2,%3};"
        : "+f"(c[0]), "+f"(c[1]), "+f"(c[2]), "+f"(c[3])
        : "r"(a[0]), "r"(a[1]), "r"(a[2]), "r"(a[3]), "r"(b[0]), "r"(b[1]));
}

// ---------------- prep: convert W1/W2 to fp16 + zero all BN stats ----------
__global__ void prep_kernel(const float* __restrict__ W1, const float* __restrict__ W2,
                            __half* __restrict__ a1, __half* __restrict__ a2,
                            float* s1, float* q1, float* s2, float* q2)
{
    int i = blockIdx.x * 256 + threadIdx.x;
    if (i < H1 * INCH) a1[i] = __float2half(W1[i]);
    if (i < H2 * H1)   a2[i] = __float2half(W2[i]);
    if (i < H1) { s1[i] = 0.f; q1[i] = 0.f; }
    if (i < H2) { s2[i] = 0.f; q2[i] = 0.f; }
}

// ---------------- kNN: warp per query; rank by |c|^2 - 2 q.c ----------------
__device__ __forceinline__ void top3_insert(float d, int j,
                                            float& d0, float& d1, float& d2,
                                            int& i0, int& i1, int& i2) {
    if (d < d2) {
        if (d < d1) {
            d2 = d1; i2 = i1;
            if (d < d0) { d1 = d0; i1 = i0; d0 = d; i0 = j; }
            else        { d1 = d;  i1 = j; }
        } else { d2 = d; i2 = j; }
    }
}

static constexpr int KNN_SMEM = 4 * MPTS * 4;   // sx, sy, sz, sn (64 KB)

__global__ __launch_bounds__(256) void knn_kernel(
    const float* __restrict__ xf, const float* __restrict__ xc,
    int* __restrict__ idx_out, float* __restrict__ w_out)
{
    extern __shared__ float dyn[];
    float* sx = dyn;
    float* sy = dyn + MPTS;
    float* sz = dyn + 2 * MPTS;
    float* sn = dyn + 3 * MPTS;
    for (int j = threadIdx.x; j < MPTS; j += 256) {
        float x = xc[j], y = xc[MPTS + j], z = xc[2 * MPTS + j];
        sx[j] = x; sy[j] = y; sz[j] = z;
        sn[j] = fmaf(x, x, fmaf(y, y, z * z));
    }
    __syncthreads();

    const int warp = threadIdx.x >> 5;
    const int lane = threadIdx.x & 31;
    const int n = blockIdx.x * 8 + warp;

    const float qx = xf[n], qy = xf[NPTS + n], qz = xf[2 * NPTS + n];
    const float qx2 = -2.f * qx, qy2 = -2.f * qy, qz2 = -2.f * qz;

    float d0 = 3.4e38f, d1 = 3.4e38f, d2 = 3.4e38f;
    int   i0 = 0, i1 = 0, i2 = 0;

    for (int j = lane; j < MPTS; j += 32) {
        float e = fmaf(qx2, sx[j], fmaf(qy2, sy[j], fmaf(qz2, sz[j], sn[j])));
        top3_insert(e, j, d0, d1, d2, i0, i1, i2);
    }
    for (int off = 16; off; off >>= 1) {
        float od0 = __shfl_xor_sync(0xffffffffu, d0, off);
        float od1 = __shfl_xor_sync(0xffffffffu, d1, off);
        float od2 = __shfl_xor_sync(0xffffffffu, d2, off);
        int   oi0 = __shfl_xor_sync(0xffffffffu, i0, off);
        int   oi1 = __shfl_xor_sync(0xffffffffu, i1, off);
        int   oi2 = __shfl_xor_sync(0xffffffffu, i2, off);
        top3_insert(od0, oi0, d0, d1, d2, i0, i1, i2);
        top3_insert(od1, oi1, d0, d1, d2, i0, i1, i2);
        top3_insert(od2, oi2, d0, d1, d2, i0, i1, i2);
    }
    if (lane == 0) {
        // exact distances for the 3 winners (matches reference weighting)
        float dx, dy, dz;
        dx = qx - sx[i0]; dy = qy - sy[i0]; dz = qz - sz[i0];
        float D0 = fmaxf(sqrtf(fmaf(dx, dx, fmaf(dy, dy, dz * dz))), 1e-8f);
        dx = qx - sx[i1]; dy = qy - sy[i1]; dz = qz - sz[i1];
        float D1 = fmaxf(sqrtf(fmaf(dx, dx, fmaf(dy, dy, dz * dz))), 1e-8f);
        dx = qx - sx[i2]; dy = qy - sy[i2]; dz = qz - sz[i2];
        float D2 = fmaxf(sqrtf(fmaf(dx, dx, fmaf(dy, dy, dz * dz))), 1e-8f);
        float w0 = 1.f / D0, w1 = 1.f / D1, w2 = 1.f / D2;
        float inv = 1.f / (w0 + w1 + w2);
        idx_out[n * 3 + 0] = i0; idx_out[n * 3 + 1] = i1; idx_out[n * 3 + 2] = i2;
        w_out[n * 3 + 0] = w0 * inv;
        w_out[n * 3 + 1] = w1 * inv;
        w_out[n * 3 + 2] = w2 * inv;
    }
}

// ---------------- transpose feats_coarse [CC][M] -> [M][CC] ----------------
__global__ void transpose_kernel(const float* __restrict__ in, float* __restrict__ out)
{
    __shared__ float t[32][33];
    int bx = blockIdx.x * 32;
    int by = blockIdx.y * 32;
    for (int r = threadIdx.y; r < 32; r += 8)
        t[r][threadIdx.x] = in[(size_t)(by + r) * MPTS + bx + threadIdx.x];
    __syncthreads();
    for (int r = threadIdx.y; r < 32; r += 8)
        out[(size_t)(bx + r) * CC + by + threadIdx.x] = t[threadIdx.x][r];
}

// ---------------- interpolation -> Bt1 rows [n][0..511] fp16 ---------------
__global__ __launch_bounds__(256) void interp_bt_kernel(
    const float* __restrict__ fcT, const int* __restrict__ idx,
    const float* __restrict__ wgt, __half* __restrict__ bt)
{
    const int warp = threadIdx.x >> 5;
    const int lane = threadIdx.x & 31;
    const int n = blockIdx.x * 8 + warp;

    const int i0 = idx[n * 3 + 0], i1 = idx[n * 3 + 1], i2 = idx[n * 3 + 2];
    const float w0 = wgt[n * 3 + 0], w1 = wgt[n * 3 + 1], w2 = wgt[n * 3 + 2];
    const float* __restrict__ r0 = fcT + (size_t)i0 * CC;
    const float* __restrict__ r1 = fcT + (size_t)i1 * CC;
    const float* __restrict__ r2 = fcT + (size_t)i2 * CC;

    for (int c0 = 0; c0 < CC; c0 += 32) {
        int c = c0 + lane;
        float v = fmaf(w0, __ldg(&r0[c]), fmaf(w1, __ldg(&r1[c]), w2 * __ldg(&r2[c])));
        bt[(size_t)n * INCH + c] = __float2half(v);
    }
}

// ---------------- transpose (plain) -> fp16 ---------------------------------
__global__ void transpose_h_kernel(
    const float* __restrict__ in, __half* __restrict__ oh,
    int outStride, int colOff)
{
    __shared__ float t[32][33];
    const int n0 = blockIdx.x * 32;
    const int c0 = blockIdx.y * 32;
    for (int r = threadIdx.y; r < 32; r += 8)
        t[r][threadIdx.x] = in[(size_t)(c0 + r) * NPTS + n0 + threadIdx.x];
    __syncthreads();
    const int ch = c0 + threadIdx.x;
    for (int r = threadIdx.y; r < 32; r += 8)
        oh[(size_t)(n0 + r) * outStride + colOff + ch] = __float2half(t[threadIdx.x][r]);
}

// ---------------- transpose + inline BN finalize + ReLU -> fp16 -------------
__global__ void transpose_bn_kernel(
    const float* __restrict__ in, __half* __restrict__ oh,
    const float* __restrict__ sum, const float* __restrict__ sq,
    const float* __restrict__ g, const float* __restrict__ b)
{
    __shared__ float t[32][33];
    const int n0 = blockIdx.x * 32;
    const int c0 = blockIdx.y * 32;
    for (int r = threadIdx.y; r < 32; r += 8)
        t[r][threadIdx.x] = in[(size_t)(c0 + r) * NPTS + n0 + threadIdx.x];
    __syncthreads();
    const int ch = c0 + threadIdx.x;
    float mean = sum[ch] * (1.f / NPTS);
    float var  = sq[ch] * (1.f / NPTS) - mean * mean;
    float s    = g[ch] * rsqrtf(var + BN_EPS);
    float bsh  = fmaf(-mean, s, b[ch]);
    for (int r = threadIdx.y; r < 32; r += 8) {
        float v = fmaxf(fmaf(s, t[threadIdx.x][r], bsh), 0.f);
        oh[(size_t)(n0 + r) * H1 + ch] = __float2half(v);
    }
}

// ---------------- HMMA fp16 GEMM + fused BN-stats ---------------------------
// C[512][NPTS] = A[512][K] @ B^T, A,B fp16, B stored [NPTS][K].
// CTA 128x128, K-slab 32, 3-stage cp.async, 8 warps 2(M)x4(N).
static constexpr int ROWH = 40;                 // padded halves per 32-half row
static constexpr int TILE_B = 128 * ROWH * 2;   // bytes per 128x32 tile (10240)
static constexpr int STAGE_B = 2 * TILE_B;      // A, B (20480)
static constexpr int GEMM_SMEM = 3 * STAGE_B;   // 61440 bytes

__global__ __launch_bounds__(256, 2) void gemm_mma_kernel(
    const __half* __restrict__ A, const __half* __restrict__ B,
    float* __restrict__ C, int K,
    float* __restrict__ gsum, float* __restrict__ gsq)
{
    extern __shared__ __half sm[];
    const uint32_t base = smem_u32(sm);
    const int tid  = threadIdx.x;
    const int lane = tid & 31;
    const int wid  = tid >> 5;
    const int wm   = wid & 1;       // 2 M-groups of 64
    const int wn   = wid >> 1;      // 4 N-groups of 32
    const int m0 = blockIdx.y * 128;
    const int n0 = blockIdx.x * 128;
    const int nsl = K >> 5;

    float acc[4][4][4] = {};

    auto load_slab = [&](int s, int buf) {
        const int kt = s << 5;
        const uint32_t sb = base + buf * STAGE_B;
        #pragma unroll
        for (int i = 0; i < 2; i++) {
            int id = tid + i * 256;          // 0..511
            int r = id >> 2, seg = id & 3;
            uint32_t off = (uint32_t)(r * ROWH + seg * 8) * 2;
            size_t ga = (size_t)(m0 + r) * K + kt + seg * 8;
            size_t gb = (size_t)(n0 + r) * K + kt + seg * 8;
            cp16(sb + off,          A + ga);
            cp16(sb + TILE_B + off, B + gb);
        }
    };

    auto compute = [&](int buf) {
        const uint32_t sb = base + buf * STAGE_B;
        #pragma unroll
        for (int kk = 0; kk < 2; kk++) {
            const int kh = kk * 16;
            uint32_t fB[4][2];
            const int brow = wn * 32 + (lane & 7);
            const int bcol = kh + (((lane >> 3) & 1) << 3);
            #pragma unroll
            for (int ni = 0; ni < 4; ni++) {
                uint32_t bd = sb + TILE_B +
                              (uint32_t)((brow + ni * 8) * ROWH + bcol) * 2;
                LDSM_X2(fB[ni], bd);
            }
            const int arow = wm * 64 + (lane & 15);
            const int acol = kh + ((lane >> 4) << 3);
            uint32_t fA[4][4];
            #pragma unroll
            for (int mi = 0; mi < 4; mi++) {
                uint32_t ad = sb + (uint32_t)((arow + mi * 16) * ROWH + acol) * 2;
                LDSM_X4(fA[mi], ad);
            }
            #pragma unroll
            for (int mi = 0; mi < 4; mi++)
                #pragma unroll
                for (int ni = 0; ni < 4; ni++)
                    mma_f16(acc[mi][ni], fA[mi], fB[ni]);
        }
    };

    load_slab(0, 0); CP_COMMIT();
    load_slab(1, 1); CP_COMMIT();

    for (int s = 0; s < nsl; s++) {
        CP_WAIT1();
        __syncthreads();
        int ps = s + 2;
        if (ps < nsl) load_slab(ps, ps % 3);
        CP_COMMIT();
        compute(s % 3);
    }

    // epilogue: store C + per-channel partial sums for BN stats
    const int gr = lane >> 2;
    const int gc = (lane & 3) * 2;
    #pragma unroll
    for (int mi = 0; mi < 4; mi++) {
        #pragma unroll
        for (int ni = 0; ni < 4; ni++) {
            int row = m0 + wm * 64 + mi * 16 + gr;
            int col = n0 + wn * 32 + ni * 8 + gc;
            *(float2*)&C[(size_t)row * NPTS + col] =
                make_float2(acc[mi][ni][0], acc[mi][ni][1]);
            *(float2*)&C[(size_t)(row + 8) * NPTS + col] =
                make_float2(acc[mi][ni][2], acc[mi][ni][3]);
        }
        #pragma unroll
        for (int h2 = 0; h2 < 2; h2++) {
            float s = 0.f, q = 0.f;
            #pragma unroll
            for (int ni = 0; ni < 4; ni++) {
                float v0 = acc[mi][ni][2 * h2], v1 = acc[mi][ni][2 * h2 + 1];
                s += v0 + v1;
                q += v0 * v0 + v1 * v1;
            }
            s += __shfl_xor_sync(0xffffffffu, s, 1);
            q += __shfl_xor_sync(0xffffffffu, q, 1);
            s += __shfl_xor_sync(0xffffffffu, s, 2);
            q += __shfl_xor_sync(0xffffffffu, q, 2);
            if ((lane & 3) == 0) {
                int row = m0 + wm * 64 + mi * 16 + gr + h2 * 8;
                atomicAdd(&gsum[row], s);
                atomicAdd(&gsq[row], q);
            }
        }
    }
}

// ---------------- final BN+ReLU elementwise (inline finalize) ---------------
__global__ __launch_bounds__(256) void bn_apply_kernel(
    const float* __restrict__ Y,
    const float* __restrict__ sum, const float* __restrict__ sq,
    const float* __restrict__ g, const float* __restrict__ b,
    float* __restrict__ out)
{
    int i = blockIdx.x * 256 + threadIdx.x;
    int c = i >> 12;
    float mean = sum[c] * (1.f / NPTS);
    float var  = sq[c] * (1.f / NPTS) - mean * mean;
    float s    = g[c] * rsqrtf(var + BN_EPS);
    float h    = fmaf(-mean, s, b[c]);
    float4 v = reinterpret_cast<const float4*>(Y)[i];
    v.x = fmaxf(fmaf(s, v.x, h), 0.f);
    v.y = fmaxf(fmaf(s, v.y, h), 0.f);
    v.z = fmaxf(fmaf(s, v.z, h), 0.f);
    v.w = fmaxf(fmaf(s, v.w, h), 0.f);
    reinterpret_cast<float4*>(out)[i] = v;
}

// ---------------- launch -----------------------------------------------------
extern "C" void kernel_launch(void* const* d_in, const int* in_sizes, int n_in,
                              void* d_out, int out_size)
{
    const float* xyz_fine     = (const float*)d_in[0];
    const float* xyz_coarse   = (const float*)d_in[1];
    const float* feats_fine   = (const float*)d_in[2];
    const float* feats_coarse = (const float*)d_in[3];
    const float* W1 = (const float*)d_in[4];
    const float* g1 = (const float*)d_in[5];
    const float* b1 = (const float*)d_in[6];
    const float* W2 = (const float*)d_in[7];
    const float* g2 = (const float*)d_in[8];
    const float* b2 = (const float*)d_in[9];
    float* out = (float*)d_out;

    void* p;
    cudaGetSymbolAddress(&p, g_fcT);  float*  fcT  = (float*)p;
    cudaGetSymbolAddress(&p, g_idx);  int*    idxp = (int*)p;
    cudaGetSymbolAddress(&p, g_w);    float*  wp   = (float*)p;
    cudaGetSymbolAddress(&p, g_Bt1);  __half* bt1  = (__half*)p;
    cudaGetSymbolAddress(&p, g_Bt2);  __half* bt2  = (__half*)p;
    cudaGetSymbolAddress(&p, g_A1);   __half* a1   = (__half*)p;
    cudaGetSymbolAddress(&p, g_A2);   __half* a2   = (__half*)p;
    cudaGetSymbolAddress(&p, g_y1);   float*  y1   = (float*)p;
    cudaGetSymbolAddress(&p, g_y2);   float*  y2   = (float*)p;
    cudaGetSymbolAddress(&p, g_sum1); float*  sum1 = (float*)p;
    cudaGetSymbolAddress(&p, g_sq1);  float*  sq1  = (float*)p;
    cudaGetSymbolAddress(&p, g_sum2); float*  sum2 = (float*)p;
    cudaGetSymbolAddress(&p, g_sq2);  float*  sq2  = (float*)p;

    cudaFuncSetAttribute(gemm_mma_kernel,
                         cudaFuncAttributeMaxDynamicSharedMemorySize, GEMM_SMEM);
    cudaFuncSetAttribute(knn_kernel,
                         cudaFuncAttributeMaxDynamicSharedMemorySize, KNN_SMEM);

    // launch order chosen so gemm1 is launch #6 (ncu -s 5 -c 1 window)
    prep_kernel<<<(H1 * INCH + 255) / 256, 256>>>(W1, W2, a1, a2,
                                                  sum1, sq1, sum2, sq2);     // 1
    transpose_kernel<<<dim3(MPTS / 32, CC / 32), dim3(32, 8)>>>(feats_coarse, fcT); // 2
    knn_kernel<<<NPTS / 8, 256, KNN_SMEM>>>(xyz_fine, xyz_coarse, idxp, wp); // 3
    interp_bt_kernel<<<NPTS / 8, 256>>>(fcT, idxp, wp, bt1);                 // 4
    transpose_h_kernel<<<dim3(NPTS / 32, CF / 32), dim3(32, 8)>>>(
        feats_fine, bt1, INCH, CC);                                          // 5
    gemm_mma_kernel<<<dim3(NPTS / 128, H1 / 128), 256, GEMM_SMEM>>>(
        a1, bt1, y1, INCH, sum1, sq1);                                       // 6  <- profiled
    transpose_bn_kernel<<<dim3(NPTS / 32, H1 / 32), dim3(32, 8)>>>(
        y1, bt2, sum1, sq1, g1, b1);                                         // 7
    gemm_mma_kernel<<<dim3(NPTS / 128, H2 / 128), 256, GEMM_SMEM>>>(
        a2, bt2, y2, H1, sum2, sq2);                                         // 8
    bn_apply_kernel<<<(H2 * NPTS / 4) / 256, 256>>>(
        y2, sum2, sq2, g2, b2, out);                                         // 9
}

// round 10
// speedup vs baseline: 3.0324x; 1.0281x over previous
#include <cuda_runtime.h>
#include <cuda_fp16.h>
#include <cstdint>

// Problem constants (fixed by the dataset)
#define NPTS 16384   // fine points
#define MPTS 4096    // coarse points
#define CF   256     // fine feature channels
#define CC   512     // coarse feature channels
#define INCH 768     // CC + CF
#define H1   512
#define H2   512
#define BN_EPS 1e-5f

// ---------------- scratch (device globals; no runtime allocation) ----------
__device__ __align__(256) float  g_fcT[MPTS * CC];            // [M][CC]
__device__ int    g_idx[NPTS * 3];
__device__ float  g_w[NPTS * 3];
__device__ __align__(256) __half g_Bt1[(size_t)NPTS * INCH];  // B1^T fp16 [N][768]
__device__ __align__(256) __half g_y1t[(size_t)NPTS * H1];    // raw y1^T fp16 [N][512]
__device__ __align__(256) __half g_A1[H1 * INCH];
__device__ __align__(256) __half g_A2[H2 * H1];
__device__ __align__(256) float  g_y2[(size_t)H2 * NPTS];
__device__ float g_sum1[H1], g_sq1[H1], g_sum2[H2], g_sq2[H2];
__device__ float g_sc1[H1], g_sh1[H1];

// ---------------- PTX helpers (all baseline, no 103a features) -------------
__device__ __forceinline__ uint32_t smem_u32(const void* p) {
    uint32_t a;
    asm("{ .reg .u64 t; cvta.to.shared.u64 t, %1; cvt.u32.u64 %0, t; }"
        : "=r"(a) : "l"(p));
    return a;
}
__device__ __forceinline__ void cp16(uint32_t dst, const void* src) {
    asm volatile("cp.async.cg.shared.global [%0], [%1], 16;"
                 :: "r"(dst), "l"(src) : "memory");
}
#define CP_COMMIT() asm volatile("cp.async.commit_group;" ::: "memory")
#define CP_WAIT1()  asm volatile("cp.async.wait_group 1;" ::: "memory")

#define LDSM_X4(r, addr) \
    asm volatile("ldmatrix.sync.aligned.m8n8.x4.shared.b16 {%0,%1,%2,%3}, [%4];" \
                 : "=r"((r)[0]), "=r"((r)[1]), "=r"((r)[2]), "=r"((r)[3]) : "r"(addr))
#define LDSM_X2(r, addr) \
    asm volatile("ldmatrix.sync.aligned.m8n8.x2.shared.b16 {%0,%1}, [%2];" \
                 : "=r"((r)[0]), "=r"((r)[1]) : "r"(addr))

__device__ __forceinline__ void mma_f16(float c[4], const uint32_t a[4],
                                        const uint32_t b[2]) {
    asm volatile(
        "mma.sync.aligned.m16n8k16.row.col.f32.f16.f16.f32 "
        "{%0,%1,%2,%3}, {%4,%5,%6,%7}, {%8,%9}, {%0,%1,%2,%3};"
        : "+f"(c[0]), "+f"(c[1]), "+f"(c[2]), "+f"(c[3])
        : "r"(a[0]), "r"(a[1]), "r"(a[2]), "r"(a[3]), "r"(b[0]), "r"(b[1]));
}

// ---------------- prep: convert W1/W2 to fp16 + zero all BN stats ----------
__global__ void prep_kernel(const float* __restrict__ W1, const float* __restrict__ W2,
                            __half* __restrict__ a1, __half* __restrict__ a2,
                            float* s1, float* q1, float* s2, float* q2)
{
    int i = blockIdx.x * 256 + threadIdx.x;
    if (i < H1 * INCH) a1[i] = __float2half(W1[i]);
    if (i < H2 * H1)   a2[i] = __float2half(W2[i]);
    if (i < H1) { s1[i] = 0.f; q1[i] = 0.f; }
    if (i < H2) { s2[i] = 0.f; q2[i] = 0.f; }
}

// ---------------- kNN: warp per query; rank by |c|^2 - 2 q.c ----------------
__device__ __forceinline__ void top3_insert(float d, int j,
                                            float& d0, float& d1, float& d2,
                                            int& i0, int& i1, int& i2) {
    if (d < d2) {
        if (d < d1) {
            d2 = d1; i2 = i1;
            if (d < d0) { d1 = d0; i1 = i0; d0 = d; i0 = j; }
            else        { d1 = d;  i1 = j; }
        } else { d2 = d; i2 = j; }
    }
}

static constexpr int KNN_SMEM = 4 * MPTS * 4;   // sx, sy, sz, sn (64 KB)

__global__ __launch_bounds__(256) void knn_kernel(
    const float* __restrict__ xf, const float* __restrict__ xc,
    int* __restrict__ idx_out, float* __restrict__ w_out)
{
    extern __shared__ float dyn[];
    float* sx = dyn;
    float* sy = dyn + MPTS;
    float* sz = dyn + 2 * MPTS;
    float* sn = dyn + 3 * MPTS;
    for (int j = threadIdx.x; j < MPTS; j += 256) {
        float x = xc[j], y = xc[MPTS + j], z = xc[2 * MPTS + j];
        sx[j] = x; sy[j] = y; sz[j] = z;
        sn[j] = fmaf(x, x, fmaf(y, y, z * z));
    }
    __syncthreads();

    const int warp = threadIdx.x >> 5;
    const int lane = threadIdx.x & 31;
    const int n = blockIdx.x * 8 + warp;

    const float qx = xf[n], qy = xf[NPTS + n], qz = xf[2 * NPTS + n];
    const float qx2 = -2.f * qx, qy2 = -2.f * qy, qz2 = -2.f * qz;

    float d0 = 3.4e38f, d1 = 3.4e38f, d2 = 3.4e38f;
    int   i0 = 0, i1 = 0, i2 = 0;

    for (int j = lane; j < MPTS; j += 32) {
        float e = fmaf(qx2, sx[j], fmaf(qy2, sy[j], fmaf(qz2, sz[j], sn[j])));
        top3_insert(e, j, d0, d1, d2, i0, i1, i2);
    }
    for (int off = 16; off; off >>= 1) {
        float od0 = __shfl_xor_sync(0xffffffffu, d0, off);
        float od1 = __shfl_xor_sync(0xffffffffu, d1, off);
        float od2 = __shfl_xor_sync(0xffffffffu, d2, off);
        int   oi0 = __shfl_xor_sync(0xffffffffu, i0, off);
        int   oi1 = __shfl_xor_sync(0xffffffffu, i1, off);
        int   oi2 = __shfl_xor_sync(0xffffffffu, i2, off);
        top3_insert(od0, oi0, d0, d1, d2, i0, i1, i2);
        top3_insert(od1, oi1, d0, d1, d2, i0, i1, i2);
        top3_insert(od2, oi2, d0, d1, d2, i0, i1, i2);
    }
    if (lane == 0) {
        float dx, dy, dz;
        dx = qx - sx[i0]; dy = qy - sy[i0]; dz = qz - sz[i0];
        float D0 = fmaxf(sqrtf(fmaf(dx, dx, fmaf(dy, dy, dz * dz))), 1e-8f);
        dx = qx - sx[i1]; dy = qy - sy[i1]; dz = qz - sz[i1];
        float D1 = fmaxf(sqrtf(fmaf(dx, dx, fmaf(dy, dy, dz * dz))), 1e-8f);
        dx = qx - sx[i2]; dy = qy - sy[i2]; dz = qz - sz[i2];
        float D2 = fmaxf(sqrtf(fmaf(dx, dx, fmaf(dy, dy, dz * dz))), 1e-8f);
        float w0 = 1.f / D0, w1 = 1.f / D1, w2 = 1.f / D2;
        float inv = 1.f / (w0 + w1 + w2);
        idx_out[n * 3 + 0] = i0; idx_out[n * 3 + 1] = i1; idx_out[n * 3 + 2] = i2;
        w_out[n * 3 + 0] = w0 * inv;
        w_out[n * 3 + 1] = w1 * inv;
        w_out[n * 3 + 2] = w2 * inv;
    }
}

// ---------------- transpose feats_coarse [CC][M] -> [M][CC] ----------------
__global__ void transpose_kernel(const float* __restrict__ in, float* __restrict__ out)
{
    __shared__ float t[32][33];
    int bx = blockIdx.x * 32;
    int by = blockIdx.y * 32;
    for (int r = threadIdx.y; r < 32; r += 8)
        t[r][threadIdx.x] = in[(size_t)(by + r) * MPTS + bx + threadIdx.x];
    __syncthreads();
    for (int r = threadIdx.y; r < 32; r += 8)
        out[(size_t)(bx + r) * CC + by + threadIdx.x] = t[threadIdx.x][r];
}

// ---------------- interpolation -> Bt1 rows [n][0..511] fp16 ---------------
__global__ __launch_bounds__(256) void interp_bt_kernel(
    const float* __restrict__ fcT, const int* __restrict__ idx,
    const float* __restrict__ wgt, __half* __restrict__ bt)
{
    const int warp = threadIdx.x >> 5;
    const int lane = threadIdx.x & 31;
    const int n = blockIdx.x * 8 + warp;

    const int i0 = idx[n * 3 + 0], i1 = idx[n * 3 + 1], i2 = idx[n * 3 + 2];
    const float w0 = wgt[n * 3 + 0], w1 = wgt[n * 3 + 1], w2 = wgt[n * 3 + 2];
    const float* __restrict__ r0 = fcT + (size_t)i0 * CC;
    const float* __restrict__ r1 = fcT + (size_t)i1 * CC;
    const float* __restrict__ r2 = fcT + (size_t)i2 * CC;

    for (int c0 = 0; c0 < CC; c0 += 32) {
        int c = c0 + lane;
        float v = fmaf(w0, __ldg(&r0[c]), fmaf(w1, __ldg(&r1[c]), w2 * __ldg(&r2[c])));
        bt[(size_t)n * INCH + c] = __float2half(v);
    }
}

// ---------------- transpose (plain) -> fp16 ---------------------------------
__global__ void transpose_h_kernel(
    const float* __restrict__ in, __half* __restrict__ oh,
    int outStride, int colOff)
{
    __shared__ float t[32][33];
    const int n0 = blockIdx.x * 32;
    const int c0 = blockIdx.y * 32;
    for (int r = threadIdx.y; r < 32; r += 8)
        t[r][threadIdx.x] = in[(size_t)(c0 + r) * NPTS + n0 + threadIdx.x];
    __syncthreads();
    const int ch = c0 + threadIdx.x;
    for (int r = threadIdx.y; r < 32; r += 8)
        oh[(size_t)(n0 + r) * outStride + colOff + ch] = __float2half(t[threadIdx.x][r]);
}

// ---------------- shared GEMM constants --------------------------------------
static constexpr int ROWH = 40;                 // padded halves per 32-half row
static constexpr int TILE_B = 128 * ROWH * 2;   // bytes per 128x32 tile (10240)
static constexpr int STAGE_B = 2 * TILE_B;      // A, B (20480)
static constexpr int G1_SMEM = 3 * STAGE_B;          // 61440
static constexpr int G2_SMEM = 3 * STAGE_B + 4096;   // + sc/sh staging

// ---------------- GEMM1: fp16 HMMA, epilogue -> y1t fp16 [N][512] + stats ---
__global__ __launch_bounds__(256, 2) void gemm1_kernel(
    const __half* __restrict__ A, const __half* __restrict__ B,
    __half* __restrict__ y1t,
    float* __restrict__ gsum, float* __restrict__ gsq)
{
    extern __shared__ __half sm[];
    const uint32_t base = smem_u32(sm);
    const int tid  = threadIdx.x;
    const int lane = tid & 31;
    const int wid  = tid >> 5;
    const int wm   = wid & 1;
    const int wn   = wid >> 1;
    const int m0 = blockIdx.y * 128;
    const int n0 = blockIdx.x * 128;
    constexpr int K = INCH;
    constexpr int nsl = K >> 5;   // 24

    float acc[4][4][4] = {};

    auto load_slab = [&](int s, int buf) {
        const int kt = s << 5;
        const uint32_t sb = base + buf * STAGE_B;
        #pragma unroll
        for (int i = 0; i < 2; i++) {
            int id = tid + i * 256;
            int r = id >> 2, seg = id & 3;
            uint32_t off = (uint32_t)(r * ROWH + seg * 8) * 2;
            cp16(sb + off,          A + (size_t)(m0 + r) * K + kt + seg * 8);
            cp16(sb + TILE_B + off, B + (size_t)(n0 + r) * K + kt + seg * 8);
        }
    };

    auto compute = [&](int buf) {
        const uint32_t sb = base + buf * STAGE_B;
        #pragma unroll
        for (int kk = 0; kk < 2; kk++) {
            const int kh = kk * 16;
            uint32_t fB[4][2];
            const int brow = wn * 32 + (lane & 7);
            const int bcol = kh + (((lane >> 3) & 1) << 3);
            #pragma unroll
            for (int ni = 0; ni < 4; ni++)
                LDSM_X2(fB[ni], sb + TILE_B +
                        (uint32_t)((brow + ni * 8) * ROWH + bcol) * 2);
            const int arow = wm * 64 + (lane & 15);
            const int acol = kh + ((lane >> 4) << 3);
            uint32_t fA[4][4];
            #pragma unroll
            for (int mi = 0; mi < 4; mi++)
                LDSM_X4(fA[mi], sb + (uint32_t)((arow + mi * 16) * ROWH + acol) * 2);
            #pragma unroll
            for (int mi = 0; mi < 4; mi++)
                #pragma unroll
                for (int ni = 0; ni < 4; ni++)
                    mma_f16(acc[mi][ni], fA[mi], fB[ni]);
        }
    };

    load_slab(0, 0); CP_COMMIT();
    load_slab(1, 1); CP_COMMIT();
    for (int s = 0; s < nsl; s++) {
        CP_WAIT1();
        __syncthreads();
        int ps = s + 2;
        if (ps < nsl) load_slab(ps, ps % 3);
        CP_COMMIT();
        compute(s % 3);
    }

    // per-channel BN partial sums (register-only)
    const int gr = lane >> 2;
    const int gc = (lane & 3) * 2;
    #pragma unroll
    for (int mi = 0; mi < 4; mi++) {
        #pragma unroll
        for (int h2 = 0; h2 < 2; h2++) {
            float s = 0.f, q = 0.f;
            #pragma unroll
            for (int ni = 0; ni < 4; ni++) {
                float v0 = acc[mi][ni][2 * h2], v1 = acc[mi][ni][2 * h2 + 1];
                s += v0 + v1;
                q += v0 * v0 + v1 * v1;
            }
            s += __shfl_xor_sync(0xffffffffu, s, 1);
            q += __shfl_xor_sync(0xffffffffu, q, 1);
            s += __shfl_xor_sync(0xffffffffu, s, 2);
            q += __shfl_xor_sync(0xffffffffu, q, 2);
            if ((lane & 3) == 0) {
                int row = m0 + wm * 64 + mi * 16 + gr + h2 * 8;
                atomicAdd(&gsum[row], s);
                atomicAdd(&gsq[row], q);
            }
        }
    }

    // transpose tile in smem -> coalesced fp16 stores to y1t[N][512]
    __syncthreads();                      // pipeline smem no longer in use
    __half* st = sm;                      // [128][136] halves (34816 B)
    #pragma unroll
    for (int mi = 0; mi < 4; mi++) {
        int row = wm * 64 + mi * 16 + gr;
        #pragma unroll
        for (int ni = 0; ni < 4; ni++) {
            int col = wn * 32 + ni * 8 + gc;
            st[(uint32_t)col * 136 + row]           = __float2half(acc[mi][ni][0]);
            st[(uint32_t)(col + 1) * 136 + row]     = __float2half(acc[mi][ni][1]);
            st[(uint32_t)col * 136 + row + 8]       = __float2half(acc[mi][ni][2]);
            st[(uint32_t)(col + 1) * 136 + row + 8] = __float2half(acc[mi][ni][3]);
        }
    }
    __syncthreads();
    #pragma unroll
    for (int j = 0; j < 8; j++) {
        int idx = j * 256 + tid;          // 2048 uint4 chunks
        int nl = idx >> 4, ch = idx & 15;
        uint4 v = *(const uint4*)&st[(uint32_t)nl * 136 + ch * 8];
        *(uint4*)&y1t[(size_t)(n0 + nl) * H1 + m0 + ch * 8] = v;
    }
}

// ---------------- finalize layer-1 BN: (sum,sq) -> (sc,sh) ------------------
__global__ void finalize1_kernel(
    const float* __restrict__ sum, const float* __restrict__ sq,
    const float* __restrict__ g, const float* __restrict__ b,
    float* __restrict__ sc, float* __restrict__ sh)
{
    int c = threadIdx.x + blockIdx.x * 256;
    float mean = sum[c] * (1.f / NPTS);
    float var  = sq[c] * (1.f / NPTS) - mean * mean;
    float s    = g[c] * rsqrtf(var + BN_EPS);
    sc[c] = s;
    sh[c] = fmaf(-mean, s, b[c]);
}

// ---------------- GEMM2: B = y1t with inline BN+ReLU; C fp32 + stats --------
__global__ __launch_bounds__(256, 2) void gemm2_kernel(
    const __half* __restrict__ A, const __half* __restrict__ B,
    const float* __restrict__ sc, const float* __restrict__ sh,
    float* __restrict__ C,
    float* __restrict__ gsum, float* __restrict__ gsq)
{
    extern __shared__ __half sm[];
    const uint32_t base = smem_u32(sm);
    float* scs = (float*)(sm + 3 * STAGE_B / 2);   // 512 floats
    float* shs = scs + H1;                          // 512 floats
    const int tid  = threadIdx.x;
    const int lane = tid & 31;
    const int wid  = tid >> 5;
    const int wm   = wid & 1;
    const int wn   = wid >> 1;
    const int m0 = blockIdx.y * 128;
    const int n0 = blockIdx.x * 128;
    constexpr int K = H1;
    constexpr int nsl = K >> 5;   // 16

    for (int j = tid; j < H1; j += 256) { scs[j] = sc[j]; shs[j] = sh[j]; }
    __syncthreads();

    float acc[4][4][4] = {};

    auto loadA = [&](int s, int buf) {
        const int kt = s << 5;
        const uint32_t sb = base + buf * STAGE_B;
        #pragma unroll
        for (int i = 0; i < 2; i++) {
            int id = tid + i * 256;
            int r = id >> 2, seg = id & 3;
            cp16(sb + (uint32_t)(r * ROWH + seg * 8) * 2,
                 A + (size_t)(m0 + r) * K + kt + seg * 8);
        }
    };
    auto ldgB = [&](int s, uint4* v) {
        const int kt = s << 5;
        #pragma unroll
        for (int i = 0; i < 2; i++) {
            int id = tid + i * 256;
            int r = id >> 2, seg = id & 3;
            v[i] = *(const uint4*)&B[(size_t)(n0 + r) * K + kt + seg * 8];
        }
    };
    auto stsB = [&](int s, int buf, const uint4* v) {
        const int kt = s << 5;
        const uint32_t sb = base + buf * STAGE_B + TILE_B;
        #pragma unroll
        for (int i = 0; i < 2; i++) {
            int id = tid + i * 256;
            int r = id >> 2, seg = id & 3;
            const __half* hv = (const __half*)&v[i];
            __half o[8];
            #pragma unroll
            for (int e = 0; e < 8; e++) {
                int k = kt + seg * 8 + e;
                float f = __half2float(hv[e]);
                o[e] = __float2half(fmaxf(fmaf(scs[k], f, shs[k]), 0.f));
            }
            *(uint4*)((char*)sm + (sb - base) + (uint32_t)(r * ROWH + seg * 8) * 2)
                = *(const uint4*)o;
        }
    };

    auto compute = [&](int buf) {
        const uint32_t sb = base + buf * STAGE_B;
        #pragma unroll
        for (int kk = 0; kk < 2; kk++) {
            const int kh = kk * 16;
            uint32_t fB[4][2];
            const int brow = wn * 32 + (lane & 7);
            const int bcol = kh + (((lane >> 3) & 1) << 3);
            #pragma unroll
            for (int ni = 0; ni < 4; ni++)
                LDSM_X2(fB[ni], sb + TILE_B +
                        (uint32_t)((brow + ni * 8) * ROWH + bcol) * 2);
            const int arow = wm * 64 + (lane & 15);
            const int acol = kh + ((lane >> 4) << 3);
            uint32_t fA[4][4];
            #pragma unroll
            for (int mi = 0; mi < 4; mi++)
                LDSM_X4(fA[mi], sb + (uint32_t)((arow + mi * 16) * ROWH + acol) * 2);
            #pragma unroll
            for (int mi = 0; mi < 4; mi++)
                #pragma unroll
                for (int ni = 0; ni < 4; ni++)
                    mma_f16(acc[mi][ni], fA[mi], fB[ni]);
        }
    };

    // prologue: B(0), B(1) transformed+stored; A(0), A(1) async
    {
        uint4 v0[2], v1[2];
        ldgB(0, v0); loadA(0, 0); CP_COMMIT();
        ldgB(1, v1); loadA(1, 1); CP_COMMIT();
        stsB(0, 0, v0);
        stsB(1, 1, v1);
    }
    for (int s = 0; s < nsl; s++) {
        CP_WAIT1();
        __syncthreads();
        uint4 vv[2];
        int ps = s + 2;
        if (ps < nsl) { ldgB(ps, vv); loadA(ps, ps % 3); }
        CP_COMMIT();
        compute(s % 3);
        if (ps < nsl) stsB(ps, ps % 3, vv);
    }

    // epilogue: fp32 C + stats
    const int gr = lane >> 2;
    const int gc = (lane & 3) * 2;
    #pragma unroll
    for (int mi = 0; mi < 4; mi++) {
        #pragma unroll
        for (int ni = 0; ni < 4; ni++) {
            int row = m0 + wm * 64 + mi * 16 + gr;
            int col = n0 + wn * 32 + ni * 8 + gc;
            *(float2*)&C[(size_t)row * NPTS + col] =
                make_float2(acc[mi][ni][0], acc[mi][ni][1]);
            *(float2*)&C[(size_t)(row + 8) * NPTS + col] =
                make_float2(acc[mi][ni][2], acc[mi][ni][3]);
        }
        #pragma unroll
        for (int h2 = 0; h2 < 2; h2++) {
            float s = 0.f, q = 0.f;
            #pragma unroll
            for (int ni = 0; ni < 4; ni++) {
                float v0 = acc[mi][ni][2 * h2], v1 = acc[mi][ni][2 * h2 + 1];
                s += v0 + v1;
                q += v0 * v0 + v1 * v1;
            }
            s += __shfl_xor_sync(0xffffffffu, s, 1);
            q += __shfl_xor_sync(0xffffffffu, q, 1);
            s += __shfl_xor_sync(0xffffffffu, s, 2);
            q += __shfl_xor_sync(0xffffffffu, q, 2);
            if ((lane & 3) == 0) {
                int row = m0 + wm * 64 + mi * 16 + gr + h2 * 8;
                atomicAdd(&gsum[row], s);
                atomicAdd(&gsq[row], q);
            }
        }
    }
}

// ---------------- final BN+ReLU elementwise (inline finalize) ---------------
__global__ __launch_bounds__(256) void bn_apply_kernel(
    const float* __restrict__ Y,
    const float* __restrict__ sum, const float* __restrict__ sq,
    const float* __restrict__ g, const float* __restrict__ b,
    float* __restrict__ out)
{
    int i = blockIdx.x * 256 + threadIdx.x;
    int c = i >> 12;
    float mean = sum[c] * (1.f / NPTS);
    float var  = sq[c] * (1.f / NPTS) - mean * mean;
    float s    = g[c] * rsqrtf(var + BN_EPS);
    float h    = fmaf(-mean, s, b[c]);
    float4 v = reinterpret_cast<const float4*>(Y)[i];
    v.x = fmaxf(fmaf(s, v.x, h), 0.f);
    v.y = fmaxf(fmaf(s, v.y, h), 0.f);
    v.z = fmaxf(fmaf(s, v.z, h), 0.f);
    v.w = fmaxf(fmaf(s, v.w, h), 0.f);
    reinterpret_cast<float4*>(out)[i] = v;
}

// ---------------- launch -----------------------------------------------------
extern "C" void kernel_launch(void* const* d_in, const int* in_sizes, int n_in,
                              void* d_out, int out_size)
{
    const float* xyz_fine     = (const float*)d_in[0];
    const float* xyz_coarse   = (const float*)d_in[1];
    const float* feats_fine   = (const float*)d_in[2];
    const float* feats_coarse = (const float*)d_in[3];
    const float* W1 = (const float*)d_in[4];
    const float* g1 = (const float*)d_in[5];
    const float* b1 = (const float*)d_in[6];
    const float* W2 = (const float*)d_in[7];
    const float* g2 = (const float*)d_in[8];
    const float* b2 = (const float*)d_in[9];
    float* out = (float*)d_out;

    void* p;
    cudaGetSymbolAddress(&p, g_fcT);  float*  fcT  = (float*)p;
    cudaGetSymbolAddress(&p, g_idx);  int*    idxp = (int*)p;
    cudaGetSymbolAddress(&p, g_w);    float*  wp   = (float*)p;
    cudaGetSymbolAddress(&p, g_Bt1);  __half* bt1  = (__half*)p;
    cudaGetSymbolAddress(&p, g_y1t);  __half* y1t  = (__half*)p;
    cudaGetSymbolAddress(&p, g_A1);   __half* a1   = (__half*)p;
    cudaGetSymbolAddress(&p, g_A2);   __half* a2   = (__half*)p;
    cudaGetSymbolAddress(&p, g_y2);   float*  y2   = (float*)p;
    cudaGetSymbolAddress(&p, g_sum1); float*  sum1 = (float*)p;
    cudaGetSymbolAddress(&p, g_sq1);  float*  sq1  = (float*)p;
    cudaGetSymbolAddress(&p, g_sum2); float*  sum2 = (float*)p;
    cudaGetSymbolAddress(&p, g_sq2);  float*  sq2  = (float*)p;
    cudaGetSymbolAddress(&p, g_sc1);  float*  sc1  = (float*)p;
    cudaGetSymbolAddress(&p, g_sh1);  float*  sh1  = (float*)p;

    cudaFuncSetAttribute(gemm1_kernel,
                         cudaFuncAttributeMaxDynamicSharedMemorySize, G1_SMEM);
    cudaFuncSetAttribute(gemm2_kernel,
                         cudaFuncAttributeMaxDynamicSharedMemorySize, G2_SMEM);
    cudaFuncSetAttribute(knn_kernel,
                         cudaFuncAttributeMaxDynamicSharedMemorySize, KNN_SMEM);

    prep_kernel<<<(H1 * INCH + 255) / 256, 256>>>(W1, W2, a1, a2,
                                                  sum1, sq1, sum2, sq2);
    transpose_kernel<<<dim3(MPTS / 32, CC / 32), dim3(32, 8)>>>(feats_coarse, fcT);
    knn_kernel<<<NPTS / 8, 256, KNN_SMEM>>>(xyz_fine, xyz_coarse, idxp, wp);
    interp_bt_kernel<<<NPTS / 8, 256>>>(fcT, idxp, wp, bt1);
    transpose_h_kernel<<<dim3(NPTS / 32, CF / 32), dim3(32, 8)>>>(
        feats_fine, bt1, INCH, CC);
    gemm1_kernel<<<dim3(NPTS / 128, H1 / 128), 256, G1_SMEM>>>(
        a1, bt1, y1t, sum1, sq1);
    finalize1_kernel<<<H1 / 256, 256>>>(sum1, sq1, g1, b1, sc1, sh1);
    gemm2_kernel<<<dim3(NPTS / 128, H2 / 128), 256, G2_SMEM>>>(
        a2, y1t, sc1, sh1, y2, sum2, sq2);
    bn_apply_kernel<<<(H2 * NPTS / 4) / 256, 256>>>(
        y2, sum2, sq2, g2, b2, out);
}

// round 11
// speedup vs baseline: 3.0662x; 1.0112x over previous
#include <cuda_runtime.h>
#include <cuda_fp16.h>
#include <cstdint>

// Problem constants (fixed by the dataset)
#define NPTS 16384   // fine points
#define MPTS 4096    // coarse points
#define CF   256     // fine feature channels
#define CC   512     // coarse feature channels
#define INCH 768     // CC + CF
#define H1   512
#define H2   512
#define BN_EPS 1e-5f

// ---------------- scratch (device globals; no runtime allocation) ----------
__device__ int    g_idx[NPTS * 3];
__device__ float  g_w[NPTS * 3];
__device__ __align__(256) __half g_fcTh[(size_t)MPTS * CC];   // fc^T fp16 [M][512]
__device__ __align__(256) __half g_btf[(size_t)NPTS * CF];    // ff^T fp16 [N][256]
__device__ __align__(256) float  g_Zt[(size_t)MPTS * H1];     // (W1a@fc)^T fp32 [M][512]
__device__ __align__(256) __half g_y1bt[(size_t)NPTS * H1];   // (W1b@ff)^T fp16 [N][512]
__device__ __align__(256) __half g_y1t[(size_t)NPTS * H1];    // raw y1^T fp16 [N][512]
__device__ __align__(256) __half g_A1a[H1 * CC];
__device__ __align__(256) __half g_A1b[H1 * CF];
__device__ __align__(256) __half g_A2[H2 * H1];
__device__ __align__(256) float  g_y2[(size_t)H2 * NPTS];
__device__ float g_sum1[H1], g_sq1[H1], g_sum2[H2], g_sq2[H2];
__device__ float g_sc1[H1], g_sh1[H1];

// ---------------- PTX helpers (all baseline, no 103a features) -------------
__device__ __forceinline__ uint32_t smem_u32(const void* p) {
    uint32_t a;
    asm("{ .reg .u64 t; cvta.to.shared.u64 t, %1; cvt.u32.u64 %0, t; }"
        : "=r"(a) : "l"(p));
    return a;
}
__device__ __forceinline__ void cp16(uint32_t dst, const void* src) {
    asm volatile("cp.async.cg.shared.global [%0], [%1], 16;"
                 :: "r"(dst), "l"(src) : "memory");
}
#define CP_COMMIT() asm volatile("cp.async.commit_group;" ::: "memory")
#define CP_WAIT1()  asm volatile("cp.async.wait_group 1;" ::: "memory")

#define LDSM_X4(r, addr) \
    asm volatile("ldmatrix.sync.aligned.m8n8.x4.shared.b16 {%0,%1,%2,%3}, [%4];" \
                 : "=r"((r)[0]), "=r"((r)[1]), "=r"((r)[2]), "=r"((r)[3]) : "r"(addr))
#define LDSM_X2(r, addr) \
    asm volatile("ldmatrix.sync.aligned.m8n8.x2.shared.b16 {%0,%1}, [%2];" \
                 : "=r"((r)[0]), "=r"((r)[1]) : "r"(addr))

__device__ __forceinline__ void mma_f16(float c[4], const uint32_t a[4],
                                        const uint32_t b[2]) {
    asm volatile(
        "mma.sync.aligned.m16n8k16.row.col.f32.f16.f16.f32 "
        "{%0,%1,%2,%3}, {%4,%5,%6,%7}, {%8,%9}, {%0,%1,%2,%3};"
        : "+f"(c[0]), "+f"(c[1]), "+f"(c[2]), "+f"(c[3])
        : "r"(a[0]), "r"(a[1]), "r"(a[2]), "r"(a[3]), "r"(b[0]), "r"(b[1]));
}

// ---------------- prep: W1 split + W2 convert + zero BN stats ---------------
__global__ void prep_kernel(const float* __restrict__ W1, const float* __restrict__ W2,
                            __half* __restrict__ a1a, __half* __restrict__ a1b,
                            __half* __restrict__ a2,
                            float* s1, float* q1, float* s2, float* q2)
{
    int i = blockIdx.x * 256 + threadIdx.x;
    if (i < H1 * CC) {
        a1a[i] = __float2half(W1[(i >> 9) * INCH + (i & 511)]);
        a2[i]  = __float2half(W2[i]);
    }
    if (i < H1 * CF)
        a1b[i] = __float2half(W1[(i >> 8) * INCH + CC + (i & 255)]);
    if (i < H1) { s1[i] = 0.f; q1[i] = 0.f; }
    if (i < H2) { s2[i] = 0.f; q2[i] = 0.f; }
}

// ---------------- kNN: warp per query; rank by |c|^2 - 2 q.c ----------------
__device__ __forceinline__ void top3_insert(float d, int j,
                                            float& d0, float& d1, float& d2,
                                            int& i0, int& i1, int& i2) {
    if (d < d2) {
        if (d < d1) {
            d2 = d1; i2 = i1;
            if (d < d0) { d1 = d0; i1 = i0; d0 = d; i0 = j; }
            else        { d1 = d;  i1 = j; }
        } else { d2 = d; i2 = j; }
    }
}

static constexpr int KNN_SMEM = 4 * MPTS * 4;   // sx, sy, sz, sn (64 KB)

__global__ __launch_bounds__(256) void knn_kernel(
    const float* __restrict__ xf, const float* __restrict__ xc,
    int* __restrict__ idx_out, float* __restrict__ w_out)
{
    extern __shared__ float dyn[];
    float* sx = dyn;
    float* sy = dyn + MPTS;
    float* sz = dyn + 2 * MPTS;
    float* sn = dyn + 3 * MPTS;
    for (int j = threadIdx.x; j < MPTS; j += 256) {
        float x = xc[j], y = xc[MPTS + j], z = xc[2 * MPTS + j];
        sx[j] = x; sy[j] = y; sz[j] = z;
        sn[j] = fmaf(x, x, fmaf(y, y, z * z));
    }
    __syncthreads();

    const int warp = threadIdx.x >> 5;
    const int lane = threadIdx.x & 31;
    const int n = blockIdx.x * 8 + warp;

    const float qx = xf[n], qy = xf[NPTS + n], qz = xf[2 * NPTS + n];
    const float qx2 = -2.f * qx, qy2 = -2.f * qy, qz2 = -2.f * qz;

    float d0 = 3.4e38f, d1 = 3.4e38f, d2 = 3.4e38f;
    int   i0 = 0, i1 = 0, i2 = 0;

    for (int j = lane; j < MPTS; j += 32) {
        float e = fmaf(qx2, sx[j], fmaf(qy2, sy[j], fmaf(qz2, sz[j], sn[j])));
        top3_insert(e, j, d0, d1, d2, i0, i1, i2);
    }
    for (int off = 16; off; off >>= 1) {
        float od0 = __shfl_xor_sync(0xffffffffu, d0, off);
        float od1 = __shfl_xor_sync(0xffffffffu, d1, off);
        float od2 = __shfl_xor_sync(0xffffffffu, d2, off);
        int   oi0 = __shfl_xor_sync(0xffffffffu, i0, off);
        int   oi1 = __shfl_xor_sync(0xffffffffu, i1, off);
        int   oi2 = __shfl_xor_sync(0xffffffffu, i2, off);
        top3_insert(od0, oi0, d0, d1, d2, i0, i1, i2);
        top3_insert(od1, oi1, d0, d1, d2, i0, i1, i2);
        top3_insert(od2, oi2, d0, d1, d2, i0, i1, i2);
    }
    if (lane == 0) {
        float dx, dy, dz;
        dx = qx - sx[i0]; dy = qy - sy[i0]; dz = qz - sz[i0];
        float D0 = fmaxf(sqrtf(fmaf(dx, dx, fmaf(dy, dy, dz * dz))), 1e-8f);
        dx = qx - sx[i1]; dy = qy - sy[i1]; dz = qz - sz[i1];
        float D1 = fmaxf(sqrtf(fmaf(dx, dx, fmaf(dy, dy, dz * dz))), 1e-8f);
        dx = qx - sx[i2]; dy = qy - sy[i2]; dz = qz - sz[i2];
        float D2 = fmaxf(sqrtf(fmaf(dx, dx, fmaf(dy, dy, dz * dz))), 1e-8f);
        float w0 = 1.f / D0, w1 = 1.f / D1, w2 = 1.f / D2;
        float inv = 1.f / (w0 + w1 + w2);
        idx_out[n * 3 + 0] = i0; idx_out[n * 3 + 1] = i1; idx_out[n * 3 + 2] = i2;
        w_out[n * 3 + 0] = w0 * inv;
        w_out[n * 3 + 1] = w1 * inv;
        w_out[n * 3 + 2] = w2 * inv;
    }
}

// ---------------- transpose fc [CC][M] -> fcTh fp16 [M][CC] -----------------
__global__ void transpose_fc_kernel(const float* __restrict__ in,
                                    __half* __restrict__ out)
{
    __shared__ float t[32][33];
    int bx = blockIdx.x * 32;  // M dim
    int by = blockIdx.y * 32;  // CC dim
    for (int r = threadIdx.y; r < 32; r += 8)
        t[r][threadIdx.x] = in[(size_t)(by + r) * MPTS + bx + threadIdx.x];
    __syncthreads();
    for (int r = threadIdx.y; r < 32; r += 8)
        out[(size_t)(bx + r) * CC + by + threadIdx.x] =
            __float2half(t[threadIdx.x][r]);
}

// ---------------- transpose ff [CF][N] -> btf fp16 [N][CF] ------------------
__global__ void transpose_ff_kernel(const float* __restrict__ in,
                                    __half* __restrict__ out)
{
    __shared__ float t[32][33];
    int bx = blockIdx.x * 32;  // N dim
    int by = blockIdx.y * 32;  // CF dim
    for (int r = threadIdx.y; r < 32; r += 8)
        t[r][threadIdx.x] = in[(size_t)(by + r) * NPTS + bx + threadIdx.x];
    __syncthreads();
    for (int r = threadIdx.y; r < 32; r += 8)
        out[(size_t)(bx + r) * CF + by + threadIdx.x] =
            __float2half(t[threadIdx.x][r]);
}

// ---------------- shared GEMM constants --------------------------------------
static constexpr int ROWH = 40;                 // padded halves per 32-half row
static constexpr int TILE_B = 128 * ROWH * 2;   // bytes per 128x32 tile (10240)
static constexpr int STAGE_B = 2 * TILE_B;      // A, B (20480)
static constexpr int GZ_SMEM  = 128 * 132 * 4;       // 67584 (>= 3*STAGE_B)
static constexpr int G1B_SMEM = 3 * STAGE_B;         // 61440
static constexpr int G2_SMEM  = 3 * STAGE_B + 4096;  // + sc/sh staging

// ---------------- generic A-side GEMM: C^T = (A @ B^T)^T --------------------
// A [512][K] fp16 row-major, B [Nrows][K] fp16 K-major.
// Output transposed: OutT [Nrows][512]; F16OUT picks fp16 vs fp32.
template<int K, bool F16OUT>
__global__ __launch_bounds__(256, 2) void gemm_a_kernel(
    const __half* __restrict__ A, const __half* __restrict__ B,
    void* __restrict__ outT)
{
    extern __shared__ __half sm[];
    const uint32_t base = smem_u32(sm);
    const int tid  = threadIdx.x;
    const int lane = tid & 31;
    const int wid  = tid >> 5;
    const int wm   = wid & 1;
    const int wn   = wid >> 1;
    const int m0 = blockIdx.y * 128;
    const int n0 = blockIdx.x * 128;
    constexpr int nsl = K >> 5;

    float acc[4][4][4] = {};

    auto load_slab = [&](int s, int buf) {
        const int kt = s << 5;
        const uint32_t sb = base + buf * STAGE_B;
        #pragma unroll
        for (int i = 0; i < 2; i++) {
            int id = tid + i * 256;
            int r = id >> 2, seg = id & 3;
            uint32_t off = (uint32_t)(r * ROWH + seg * 8) * 2;
            cp16(sb + off,          A + (size_t)(m0 + r) * K + kt + seg * 8);
            cp16(sb + TILE_B + off, B + (size_t)(n0 + r) * K + kt + seg * 8);
        }
    };

    auto compute = [&](int buf) {
        const uint32_t sb = base + buf * STAGE_B;
        #pragma unroll
        for (int kk = 0; kk < 2; kk++) {
            const int kh = kk * 16;
            uint32_t fB[4][2];
            const int brow = wn * 32 + (lane & 7);
            const int bcol = kh + (((lane >> 3) & 1) << 3);
            #pragma unroll
            for (int ni = 0; ni < 4; ni++)
                LDSM_X2(fB[ni], sb + TILE_B +
                        (uint32_t)((brow + ni * 8) * ROWH + bcol) * 2);
            const int arow = wm * 64 + (lane & 15);
            const int acol = kh + ((lane >> 4) << 3);
            uint32_t fA[4][4];
            #pragma unroll
            for (int mi = 0; mi < 4; mi++)
                LDSM_X4(fA[mi], sb + (uint32_t)((arow + mi * 16) * ROWH + acol) * 2);
            #pragma unroll
            for (int mi = 0; mi < 4; mi++)
                #pragma unroll
                for (int ni = 0; ni < 4; ni++)
                    mma_f16(acc[mi][ni], fA[mi], fB[ni]);
        }
    };

    load_slab(0, 0); CP_COMMIT();
    load_slab(1, 1); CP_COMMIT();
    for (int s = 0; s < nsl; s++) {
        CP_WAIT1();
        __syncthreads();
        int ps = s + 2;
        if (ps < nsl) load_slab(ps, ps % 3);
        CP_COMMIT();
        compute(s % 3);
    }

    const int gr = lane >> 2;
    const int gc = (lane & 3) * 2;
    __syncthreads();   // pipeline smem no longer in use

    if (F16OUT) {
        __half* y = (__half*)outT;
        __half* st = sm;   // [128][136] halves (34816 B)
        #pragma unroll
        for (int mi = 0; mi < 4; mi++) {
            int row = wm * 64 + mi * 16 + gr;
            #pragma unroll
            for (int ni = 0; ni < 4; ni++) {
                int col = wn * 32 + ni * 8 + gc;
                st[(uint32_t)col * 136 + row]           = __float2half(acc[mi][ni][0]);
                st[(uint32_t)(col + 1) * 136 + row]     = __float2half(acc[mi][ni][1]);
                st[(uint32_t)col * 136 + row + 8]       = __float2half(acc[mi][ni][2]);
                st[(uint32_t)(col + 1) * 136 + row + 8] = __float2half(acc[mi][ni][3]);
            }
        }
        __syncthreads();
        #pragma unroll
        for (int j = 0; j < 8; j++) {
            int idx = j * 256 + tid;      // 2048 uint4 chunks
            int nl = idx >> 4, ch = idx & 15;
            uint4 v = *(const uint4*)&st[(uint32_t)nl * 136 + ch * 8];
            *(uint4*)&y[(size_t)(n0 + nl) * 512 + m0 + ch * 8] = v;
        }
    } else {
        float* y = (float*)outT;
        float* st = (float*)sm;  // [128][132] floats (67584 B)
        #pragma unroll
        for (int mi = 0; mi < 4; mi++) {
            int row = wm * 64 + mi * 16 + gr;
            #pragma unroll
            for (int ni = 0; ni < 4; ni++) {
                int col = wn * 32 + ni * 8 + gc;
                st[(uint32_t)col * 132 + row]           = acc[mi][ni][0];
                st[(uint32_t)(col + 1) * 132 + row]     = acc[mi][ni][1];
                st[(uint32_t)col * 132 + row + 8]       = acc[mi][ni][2];
                st[(uint32_t)(col + 1) * 132 + row + 8] = acc[mi][ni][3];
            }
        }
        __syncthreads();
        #pragma unroll
        for (int j = 0; j < 16; j++) {
            int idx = j * 256 + tid;      // 4096 float4 chunks
            int nl = idx >> 5, ch = idx & 31;
            float4 v = *(const float4*)&st[(uint32_t)nl * 132 + ch * 4];
            *(float4*)&y[(size_t)(n0 + nl) * 512 + m0 + ch * 4] = v;
        }
    }
}

// ---------------- interp2: y1 = gather(Zt) + y1b; fp16 out + BN1 stats ------
__global__ __launch_bounds__(256) void interp2_kernel(
    const float* __restrict__ Zt, const __half* __restrict__ y1bt,
    const int* __restrict__ idx, const float* __restrict__ wgt,
    __half* __restrict__ y1t, float* __restrict__ gsum, float* __restrict__ gsq)
{
    __shared__ float bsum[8][512];
    __shared__ float bsq[8][512];
    const int w = threadIdx.x >> 5;
    const int lane = threadIdx.x & 31;
    const int nb = blockIdx.x * 64 + w * 8;

    int ii[8][3]; float ww[8][3];
    #pragma unroll
    for (int t = 0; t < 8; t++) {
        int n = nb + t;
        ii[t][0] = __ldg(&idx[n * 3 + 0]);
        ii[t][1] = __ldg(&idx[n * 3 + 1]);
        ii[t][2] = __ldg(&idx[n * 3 + 2]);
        ww[t][0] = __ldg(&wgt[n * 3 + 0]);
        ww[t][1] = __ldg(&wgt[n * 3 + 1]);
        ww[t][2] = __ldg(&wgt[n * 3 + 2]);
    }

    for (int c0 = 0; c0 < 512; c0 += 32) {
        int c = c0 + lane;
        float s = 0.f, q = 0.f;
        #pragma unroll
        for (int t = 0; t < 8; t++) {
            int n = nb + t;
            float v = fmaf(ww[t][0], __ldg(&Zt[(size_t)ii[t][0] * 512 + c]),
                     fmaf(ww[t][1], __ldg(&Zt[(size_t)ii[t][1] * 512 + c]),
                          ww[t][2] * __ldg(&Zt[(size_t)ii[t][2] * 512 + c])));
            v += __half2float(__ldg(&y1bt[(size_t)n * 512 + c]));
            y1t[(size_t)n * 512 + c] = __float2half(v);
            s += v;
            q = fmaf(v, v, q);
        }
        bsum[w][c] = s;
        bsq[w][c] = q;
    }
    __syncthreads();
    for (int c = threadIdx.x; c < 512; c += 256) {
        float s = 0.f, q = 0.f;
        #pragma unroll
        for (int r = 0; r < 8; r++) { s += bsum[r][c]; q += bsq[r][c]; }
        atomicAdd(&gsum[c], s);
        atomicAdd(&gsq[c], q);
    }
}

// ---------------- finalize layer-1 BN: (sum,sq) -> (sc,sh) ------------------
__global__ void finalize1_kernel(
    const float* __restrict__ sum, const float* __restrict__ sq,
    const float* __restrict__ g, const float* __restrict__ b,
    float* __restrict__ sc, float* __restrict__ sh)
{
    int c = threadIdx.x + blockIdx.x * 256;
    float mean = sum[c] * (1.f / NPTS);
    float var  = sq[c] * (1.f / NPTS) - mean * mean;
    float s    = g[c] * rsqrtf(var + BN_EPS);
    sc[c] = s;
    sh[c] = fmaf(-mean, s, b[c]);
}

// ---------------- GEMM2: B = y1t with inline BN+ReLU; C fp32 + stats --------
__global__ __launch_bounds__(256, 2) void gemm2_kernel(
    const __half* __restrict__ A, const __half* __restrict__ B,
    const float* __restrict__ sc, const float* __restrict__ sh,
    float* __restrict__ C,
    float* __restrict__ gsum, float* __restrict__ gsq)
{
    extern __shared__ __half sm[];
    const uint32_t base = smem_u32(sm);
    float* scs = (float*)(sm + 3 * STAGE_B / 2);   // 512 floats
    float* shs = scs + H1;                          // 512 floats
    const int tid  = threadIdx.x;
    const int lane = tid & 31;
    const int wid  = tid >> 5;
    const int wm   = wid & 1;
    const int wn   = wid >> 1;
    const int m0 = blockIdx.y * 128;
    const int n0 = blockIdx.x * 128;
    constexpr int K = H1;
    constexpr int nsl = K >> 5;   // 16

    for (int j = tid; j < H1; j += 256) { scs[j] = sc[j]; shs[j] = sh[j]; }
    __syncthreads();

    float acc[4][4][4] = {};

    auto loadA = [&](int s, int buf) {
        const int kt = s << 5;
        const uint32_t sb = base + buf * STAGE_B;
        #pragma unroll
        for (int i = 0; i < 2; i++) {
            int id = tid + i * 256;
            int r = id >> 2, seg = id & 3;
            cp16(sb + (uint32_t)(r * ROWH + seg * 8) * 2,
                 A + (size_t)(m0 + r) * K + kt + seg * 8);
        }
    };
    auto ldgB = [&](int s, uint4* v) {
        const int kt = s << 5;
        #pragma unroll
        for (int i = 0; i < 2; i++) {
            int id = tid + i * 256;
            int r = id >> 2, seg = id & 3;
            v[i] = *(const uint4*)&B[(size_t)(n0 + r) * K + kt + seg * 8];
        }
    };
    auto stsB = [&](int s, int buf, const uint4* v) {
        const int kt = s << 5;
        const uint32_t off0 = buf * STAGE_B + TILE_B;
        #pragma unroll
        for (int i = 0; i < 2; i++) {
            int id = tid + i * 256;
            int r = id >> 2, seg = id & 3;
            const __half* hv = (const __half*)&v[i];
            __half o[8];
            #pragma unroll
            for (int e = 0; e < 8; e++) {
                int k = kt + seg * 8 + e;
                float f = __half2float(hv[e]);
                o[e] = __float2half(fmaxf(fmaf(scs[k], f, shs[k]), 0.f));
            }
            *(uint4*)((char*)sm + off0 + (uint32_t)(r * ROWH + seg * 8) * 2)
                = *(const uint4*)o;
        }
    };

    auto compute = [&](int buf) {
        const uint32_t sb = base + buf * STAGE_B;
        #pragma unroll
        for (int kk = 0; kk < 2; kk++) {
            const int kh = kk * 16;
            uint32_t fB[4][2];
            const int brow = wn * 32 + (lane & 7);
            const int bcol = kh + (((lane >> 3) & 1) << 3);
            #pragma unroll
            for (int ni = 0; ni < 4; ni++)
                LDSM_X2(fB[ni], sb + TILE_B +
                        (uint32_t)((brow + ni * 8) * ROWH + bcol) * 2);
            const int arow = wm * 64 + (lane & 15);
            const int acol = kh + ((lane >> 4) << 3);
            uint32_t fA[4][4];
            #pragma unroll
            for (int mi = 0; mi < 4; mi++)
                LDSM_X4(fA[mi], sb + (uint32_t)((arow + mi * 16) * ROWH + acol) * 2);
            #pragma unroll
            for (int mi = 0; mi < 4; mi++)
                #pragma unroll
                for (int ni = 0; ni < 4; ni++)
                    mma_f16(acc[mi][ni], fA[mi], fB[ni]);
        }
    };

    {
        uint4 v0[2], v1[2];
        ldgB(0, v0); loadA(0, 0); CP_COMMIT();
        ldgB(1, v1); loadA(1, 1); CP_COMMIT();
        stsB(0, 0, v0);
        stsB(1, 1, v1);
    }
    for (int s = 0; s < nsl; s++) {
        CP_WAIT1();
        __syncthreads();
        uint4 vv[2];
        int ps = s + 2;
        if (ps < nsl) { ldgB(ps, vv); loadA(ps, ps % 3); }
        CP_COMMIT();
        compute(s % 3);
        if (ps < nsl) stsB(ps, ps % 3, vv);
    }

    const int gr = lane >> 2;
    const int gc = (lane & 3) * 2;
    #pragma unroll
    for (int mi = 0; mi < 4; mi++) {
        #pragma unroll
        for (int ni = 0; ni < 4; ni++) {
            int row = m0 + wm * 64 + mi * 16 + gr;
            int col = n0 + wn * 32 + ni * 8 + gc;
            *(float2*)&C[(size_t)row * NPTS + col] =
                make_float2(acc[mi][ni][0], acc[mi][ni][1]);
            *(float2*)&C[(size_t)(row + 8) * NPTS + col] =
                make_float2(acc[mi][ni][2], acc[mi][ni][3]);
        }
        #pragma unroll
        for (int h2 = 0; h2 < 2; h2++) {
            float s = 0.f, q = 0.f;
            #pragma unroll
            for (int ni = 0; ni < 4; ni++) {
                float v0 = acc[mi][ni][2 * h2], v1 = acc[mi][ni][2 * h2 + 1];
                s += v0 + v1;
                q += v0 * v0 + v1 * v1;
            }
            s += __shfl_xor_sync(0xffffffffu, s, 1);
            q += __shfl_xor_sync(0xffffffffu, q, 1);
            s += __shfl_xor_sync(0xffffffffu, s, 2);
            q += __shfl_xor_sync(0xffffffffu, q, 2);
            if ((lane & 3) == 0) {
                int row = m0 + wm * 64 + mi * 16 + gr + h2 * 8;
                atomicAdd(&gsum[row], s);
                atomicAdd(&gsq[row], q);
            }
        }
    }
}

// ---------------- final BN+ReLU elementwise (inline finalize) ---------------
__global__ __launch_bounds__(256) void bn_apply_kernel(
    const float* __restrict__ Y,
    const float* __restrict__ sum, const float* __restrict__ sq,
    const float* __restrict__ g, const float* __restrict__ b,
    float* __restrict__ out)
{
    int i = blockIdx.x * 256 + threadIdx.x;
    int c = i >> 12;
    float mean = sum[c] * (1.f / NPTS);
    float var  = sq[c] * (1.f / NPTS) - mean * mean;
    float s    = g[c] * rsqrtf(var + BN_EPS);
    float h    = fmaf(-mean, s, b[c]);
    float4 v = reinterpret_cast<const float4*>(Y)[i];
    v.x = fmaxf(fmaf(s, v.x, h), 0.f);
    v.y = fmaxf(fmaf(s, v.y, h), 0.f);
    v.z = fmaxf(fmaf(s, v.z, h), 0.f);
    v.w = fmaxf(fmaf(s, v.w, h), 0.f);
    reinterpret_cast<float4*>(out)[i] = v;
}

// ---------------- launch -----------------------------------------------------
extern "C" void kernel_launch(void* const* d_in, const int* in_sizes, int n_in,
                              void* d_out, int out_size)
{
    const float* xyz_fine     = (const float*)d_in[0];
    const float* xyz_coarse   = (const float*)d_in[1];
    const float* feats_fine   = (const float*)d_in[2];
    const float* feats_coarse = (const float*)d_in[3];
    const float* W1 = (const float*)d_in[4];
    const float* g1 = (const float*)d_in[5];
    const float* b1 = (const float*)d_in[6];
    const float* W2 = (const float*)d_in[7];
    const float* g2 = (const float*)d_in[8];
    const float* b2 = (const float*)d_in[9];
    float* out = (float*)d_out;

    void* p;
    cudaGetSymbolAddress(&p, g_idx);  int*    idxp = (int*)p;
    cudaGetSymbolAddress(&p, g_w);    float*  wp   = (float*)p;
    cudaGetSymbolAddress(&p, g_fcTh); __half* fcTh = (__half*)p;
    cudaGetSymbolAddress(&p, g_btf);  __half* btf  = (__half*)p;
    cudaGetSymbolAddress(&p, g_Zt);   float*  Zt   = (float*)p;
    cudaGetSymbolAddress(&p, g_y1bt); __half* y1bt = (__half*)p;
    cudaGetSymbolAddress(&p, g_y1t);  __half* y1t  = (__half*)p;
    cudaGetSymbolAddress(&p, g_A1a);  __half* a1a  = (__half*)p;
    cudaGetSymbolAddress(&p, g_A1b);  __half* a1b  = (__half*)p;
    cudaGetSymbolAddress(&p, g_A2);   __half* a2   = (__half*)p;
    cudaGetSymbolAddress(&p, g_y2);   float*  y2   = (float*)p;
    cudaGetSymbolAddress(&p, g_sum1); float*  sum1 = (float*)p;
    cudaGetSymbolAddress(&p, g_sq1);  float*  sq1  = (float*)p;
    cudaGetSymbolAddress(&p, g_sum2); float*  sum2 = (float*)p;
    cudaGetSymbolAddress(&p, g_sq2);  float*  sq2  = (float*)p;
    cudaGetSymbolAddress(&p, g_sc1);  float*  sc1  = (float*)p;
    cudaGetSymbolAddress(&p, g_sh1);  float*  sh1  = (float*)p;

    cudaFuncSetAttribute(gemm_a_kernel<CC, false>,
                         cudaFuncAttributeMaxDynamicSharedMemorySize, GZ_SMEM);
    cudaFuncSetAttribute(gemm_a_kernel<CF, true>,
                         cudaFuncAttributeMaxDynamicSharedMemorySize, G1B_SMEM);
    cudaFuncSetAttribute(gemm2_kernel,
                         cudaFuncAttributeMaxDynamicSharedMemorySize, G2_SMEM);
    cudaFuncSetAttribute(knn_kernel,
                         cudaFuncAttributeMaxDynamicSharedMemorySize, KNN_SMEM);

    prep_kernel<<<(H1 * CC + 255) / 256, 256>>>(W1, W2, a1a, a1b, a2,
                                                sum1, sq1, sum2, sq2);
    transpose_fc_kernel<<<dim3(MPTS / 32, CC / 32), dim3(32, 8)>>>(feats_coarse, fcTh);
    knn_kernel<<<NPTS / 8, 256, KNN_SMEM>>>(xyz_fine, xyz_coarse, idxp, wp);
    transpose_ff_kernel<<<dim3(NPTS / 32, CF / 32), dim3(32, 8)>>>(feats_fine, btf);
    // Z^T = (W1a @ fc)^T : [4096][512] fp32
    gemm_a_kernel<CC, false><<<dim3(MPTS / 128, H1 / 128), 256, GZ_SMEM>>>(
        a1a, fcTh, Zt);
    // y1b^T = (W1b @ ff)^T : [16384][512] fp16
    gemm_a_kernel<CF, true><<<dim3(NPTS / 128, H1 / 128), 256, G1B_SMEM>>>(
        a1b, btf, y1bt);
    interp2_kernel<<<NPTS / 64, 256>>>(Zt, y1bt, idxp, wp, y1t, sum1, sq1);
    finalize1_kernel<<<H1 / 256, 256>>>(sum1, sq1, g1, b1, sc1, sh1);
    gemm2_kernel<<<dim3(NPTS / 128, H2 / 128), 256, G2_SMEM>>>(
        a2, y1t, sc1, sh1, y2, sum2, sq2);
    bn_apply_kernel<<<(H2 * NPTS / 4) / 256, 256>>>(
        y2, sum2, sq2, g2, b2, out);
}

// round 12
// speedup vs baseline: 3.2048x; 1.0452x over previous
#include <cuda_runtime.h>
#include <cuda_fp16.h>
#include <cstdint>

// Problem constants (fixed by the dataset)
#define NPTS 16384   // fine points
#define MPTS 4096    // coarse points
#define CF   256     // fine feature channels
#define CC   512     // coarse feature channels
#define INCH 768     // CC + CF
#define H1   512
#define H2   512
#define BN_EPS 1e-5f

// ---------------- scratch (device globals; no runtime allocation) ----------
__device__ int    g_idx[NPTS * 3];
__device__ float  g_w[NPTS * 3];
__device__ __align__(256) float  g_Zt[(size_t)MPTS * H1];     // (W1a@fc)^T fp32 [M][512]
__device__ __align__(256) __half g_y1bt[(size_t)NPTS * H1];   // (W1b@ff)^T fp16 [N][512]
__device__ __align__(256) __half g_y1t[(size_t)NPTS * H1];    // raw y1^T fp16 [N][512]
__device__ __align__(256) __half g_A1a[H1 * CC];
__device__ __align__(256) __half g_A1b[H1 * CF];
__device__ __align__(256) __half g_A2[H2 * H1];
__device__ __align__(256) __half g_y2h[(size_t)H2 * NPTS];    // raw y2 fp16
__device__ float g_sum1[H1], g_sq1[H1], g_sum2[H2], g_sq2[H2];

// ---------------- PTX helpers (all baseline, no 103a features) -------------
__device__ __forceinline__ uint32_t smem_u32(const void* p) {
    uint32_t a;
    asm("{ .reg .u64 t; cvta.to.shared.u64 t, %1; cvt.u32.u64 %0, t; }"
        : "=r"(a) : "l"(p));
    return a;
}
__device__ __forceinline__ void cp16(uint32_t dst, const void* src) {
    asm volatile("cp.async.cg.shared.global [%0], [%1], 16;"
                 :: "r"(dst), "l"(src) : "memory");
}
#define CP_COMMIT() asm volatile("cp.async.commit_group;" ::: "memory")
#define CP_WAIT1()  asm volatile("cp.async.wait_group 1;" ::: "memory")

#define LDSM_X4(r, addr) \
    asm volatile("ldmatrix.sync.aligned.m8n8.x4.shared.b16 {%0,%1,%2,%3}, [%4];" \
                 : "=r"((r)[0]), "=r"((r)[1]), "=r"((r)[2]), "=r"((r)[3]) : "r"(addr))
#define LDSM_X2(r, addr) \
    asm volatile("ldmatrix.sync.aligned.m8n8.x2.shared.b16 {%0,%1}, [%2];" \
                 : "=r"((r)[0]), "=r"((r)[1]) : "r"(addr))
#define LDSM_X2T(r, addr) \
    asm volatile("ldmatrix.sync.aligned.m8n8.x2.trans.shared.b16 {%0,%1}, [%2];" \
                 : "=r"((r)[0]), "=r"((r)[1]) : "r"(addr))

__device__ __forceinline__ void mma_f16(float c[4], const uint32_t a[4],
                                        const uint32_t b[2]) {
    asm volatile(
        "mma.sync.aligned.m16n8k16.row.col.f32.f16.f16.f32 "
        "{%0,%1,%2,%3}, {%4,%5,%6,%7}, {%8,%9}, {%0,%1,%2,%3};"
        : "+f"(c[0]), "+f"(c[1]), "+f"(c[2]), "+f"(c[3])
        : "r"(a[0]), "r"(a[1]), "r"(a[2]), "r"(a[3]), "r"(b[0]), "r"(b[1]));
}

// ---------------- prep: W1 split + W2 convert + zero BN stats ---------------
__global__ void prep_kernel(const float* __restrict__ W1, const float* __restrict__ W2,
                            __half* __restrict__ a1a, __half* __restrict__ a1b,
                            __half* __restrict__ a2,
                            float* s1, float* q1, float* s2, float* q2)
{
    int i = blockIdx.x * 256 + threadIdx.x;
    if (i < H1 * CC) {
        a1a[i] = __float2half(W1[(i >> 9) * INCH + (i & 511)]);
        a2[i]  = __float2half(W2[i]);
    }
    if (i < H1 * CF)
        a1b[i] = __float2half(W1[(i >> 8) * INCH + CC + (i & 255)]);
    if (i < H1) { s1[i] = 0.f; q1[i] = 0.f; }
    if (i < H2) { s2[i] = 0.f; q2[i] = 0.f; }
}

// ---------------- kNN: warp per 4 queries; points packed float4 -------------
__device__ __forceinline__ void top3_insert(float d, int j,
                                            float& d0, float& d1, float& d2,
                                            int& i0, int& i1, int& i2) {
    if (d < d2) {
        if (d < d1) {
            d2 = d1; i2 = i1;
            if (d < d0) { d1 = d0; i1 = i0; d0 = d; i0 = j; }
            else        { d1 = d;  i1 = j; }
        } else { d2 = d; i2 = j; }
    }
}

static constexpr int KNN_SMEM = MPTS * 16;   // float4 per point (64 KB)

__global__ __launch_bounds__(256) void knn_kernel(
    const float* __restrict__ xf, const float* __restrict__ xc,
    int* __restrict__ idx_out, float* __restrict__ w_out)
{
    extern __shared__ float4 spts[];
    for (int j = threadIdx.x; j < MPTS; j += 256) {
        float x = xc[j], y = xc[MPTS + j], z = xc[2 * MPTS + j];
        spts[j] = make_float4(x, y, z, fmaf(x, x, fmaf(y, y, z * z)));
    }
    __syncthreads();

    const int warp = threadIdx.x >> 5;
    const int lane = threadIdx.x & 31;
    const int nb = blockIdx.x * 32 + warp * 4;

    float qx[4], qy[4], qz[4], q2x[4], q2y[4], q2z[4];
    #pragma unroll
    for (int t = 0; t < 4; t++) {
        qx[t] = xf[nb + t]; qy[t] = xf[NPTS + nb + t]; qz[t] = xf[2 * NPTS + nb + t];
        q2x[t] = -2.f * qx[t]; q2y[t] = -2.f * qy[t]; q2z[t] = -2.f * qz[t];
    }

    float d[4][3];
    int   ix[4][3];
    #pragma unroll
    for (int t = 0; t < 4; t++) {
        d[t][0] = d[t][1] = d[t][2] = 3.4e38f;
        ix[t][0] = ix[t][1] = ix[t][2] = 0;
    }

    for (int j = lane; j < MPTS; j += 32) {
        float4 p = spts[j];
        #pragma unroll
        for (int t = 0; t < 4; t++) {
            float e = fmaf(q2x[t], p.x, fmaf(q2y[t], p.y, fmaf(q2z[t], p.z, p.w)));
            top3_insert(e, j, d[t][0], d[t][1], d[t][2], ix[t][0], ix[t][1], ix[t][2]);
        }
    }

    #pragma unroll
    for (int t = 0; t < 4; t++) {
        for (int off = 16; off; off >>= 1) {
            float od0 = __shfl_xor_sync(0xffffffffu, d[t][0], off);
            float od1 = __shfl_xor_sync(0xffffffffu, d[t][1], off);
            float od2 = __shfl_xor_sync(0xffffffffu, d[t][2], off);
            int   oi0 = __shfl_xor_sync(0xffffffffu, ix[t][0], off);
            int   oi1 = __shfl_xor_sync(0xffffffffu, ix[t][1], off);
            int   oi2 = __shfl_xor_sync(0xffffffffu, ix[t][2], off);
            top3_insert(od0, oi0, d[t][0], d[t][1], d[t][2], ix[t][0], ix[t][1], ix[t][2]);
            top3_insert(od1, oi1, d[t][0], d[t][1], d[t][2], ix[t][0], ix[t][1], ix[t][2]);
            top3_insert(od2, oi2, d[t][0], d[t][1], d[t][2], ix[t][0], ix[t][1], ix[t][2]);
        }
        if (lane == 0) {
            int n = nb + t;
            float D[3];
            #pragma unroll
            for (int k = 0; k < 3; k++) {
                float4 p = spts[ix[t][k]];
                float dx = qx[t] - p.x, dy = qy[t] - p.y, dz = qz[t] - p.z;
                D[k] = fmaxf(sqrtf(fmaf(dx, dx, fmaf(dy, dy, dz * dz))), 1e-8f);
            }
            float w0 = 1.f / D[0], w1 = 1.f / D[1], w2 = 1.f / D[2];
            float inv = 1.f / (w0 + w1 + w2);
            idx_out[n * 3 + 0] = ix[t][0];
            idx_out[n * 3 + 1] = ix[t][1];
            idx_out[n * 3 + 2] = ix[t][2];
            w_out[n * 3 + 0] = w0 * inv;
            w_out[n * 3 + 1] = w1 * inv;
            w_out[n * 3 + 2] = w2 * inv;
        }
    }
}

// ---------------- shared GEMM constants --------------------------------------
static constexpr int ROWH = 40;                   // padded halves per A row
static constexpr int A_TILE = 128 * ROWH * 2;     // 10240 B (128m x 32k)
static constexpr int BROW = 136;                  // padded halves per B [k] row
static constexpr int B_TILE2 = 32 * BROW * 2;     // 8704 B (32k x 128n)
static constexpr int STG = A_TILE + B_TILE2;      // 18944 B per stage
static constexpr int GZ_SMEM  = 128 * 132 * 4;         // 67584 (fp32 epilogue)
static constexpr int G1B_SMEM = 3 * STG;               // 56832
static constexpr int STAGE_B = 2 * (128 * ROWH * 2);   // gemm2 stage (A+B, 20480)
static constexpr int G2_SMEM  = 3 * STAGE_B + 4096;    // + sc/sh staging

// ---------------- gemm_bmn: A[512][K] fp16 @ B fp32 [K][Nall] (MN-major) ----
// B loaded direct from global with inline fp16 convert; ldmatrix.trans path.
// OutT [Nall][512]: fp16 (F16OUT) or fp32.
template<int K, bool F16OUT>
__global__ __launch_bounds__(256, 2) void gemm_bmn_kernel(
    const __half* __restrict__ A, const float* __restrict__ Bg, int Nall,
    void* __restrict__ outT)
{
    extern __shared__ __half sm[];
    const uint32_t base = smem_u32(sm);
    const int tid  = threadIdx.x;
    const int lane = tid & 31;
    const int wid  = tid >> 5;
    const int wm   = wid & 1;
    const int wn   = wid >> 1;
    const int m0 = blockIdx.y * 128;
    const int n0 = blockIdx.x * 128;
    constexpr int nsl = K >> 5;

    float acc[4][4][4] = {};

    auto loadA = [&](int s, int buf) {
        const int kt = s << 5;
        const uint32_t sb = base + buf * STG;
        #pragma unroll
        for (int i = 0; i < 2; i++) {
            int id = tid + i * 256;
            int r = id >> 2, seg = id & 3;
            cp16(sb + (uint32_t)(r * ROWH + seg * 8) * 2,
                 A + (size_t)(m0 + r) * K + kt + seg * 8);
        }
    };
    auto ldgB = [&](int s, float4* v) {
        const int kt = s << 5;
        #pragma unroll
        for (int i = 0; i < 4; i++) {
            int id = tid + i * 256;            // 0..1023
            int kr = id >> 5, nc4 = (id & 31) * 4;
            v[i] = *(const float4*)&Bg[(size_t)(kt + kr) * Nall + n0 + nc4];
        }
    };
    auto stsB = [&](int buf, const float4* v) {
        const uint32_t off0 = buf * STG + A_TILE;
        #pragma unroll
        for (int i = 0; i < 4; i++) {
            int id = tid + i * 256;
            int kr = id >> 5, nc4 = (id & 31) * 4;
            __half o[4];
            o[0] = __float2half(v[i].x); o[1] = __float2half(v[i].y);
            o[2] = __float2half(v[i].z); o[3] = __float2half(v[i].w);
            *(uint2*)((char*)sm + off0 + (uint32_t)(kr * BROW + nc4) * 2)
                = *(const uint2*)o;
        }
    };

    auto compute = [&](int buf) {
        const uint32_t sbA = base + buf * STG;
        const uint32_t sbB = sbA + A_TILE;
        #pragma unroll
        for (int kk = 0; kk < 2; kk++) {
            const int kh = kk * 16;
            uint32_t fB[4][2];
            const int krow = kh + (lane & 15);
            #pragma unroll
            for (int ni = 0; ni < 4; ni++)
                LDSM_X2T(fB[ni], sbB +
                         (uint32_t)(krow * BROW + wn * 32 + ni * 8) * 2);
            const int arow = wm * 64 + (lane & 15);
            const int acol = kh + ((lane >> 4) << 3);
            uint32_t fA[4][4];
            #pragma unroll
            for (int mi = 0; mi < 4; mi++)
                LDSM_X4(fA[mi], sbA + (uint32_t)((arow + mi * 16) * ROWH + acol) * 2);
            #pragma unroll
            for (int mi = 0; mi < 4; mi++)
                #pragma unroll
                for (int ni = 0; ni < 4; ni++)
                    mma_f16(acc[mi][ni], fA[mi], fB[ni]);
        }
    };

    {
        float4 v0[4], v1[4];
        ldgB(0, v0); loadA(0, 0); CP_COMMIT();
        ldgB(1, v1); loadA(1, 1); CP_COMMIT();
        stsB(0, v0);
        stsB(1, v1);
    }
    for (int s = 0; s < nsl; s++) {
        CP_WAIT1();
        __syncthreads();
        float4 vv[4];
        int ps = s + 2;
        if (ps < nsl) { ldgB(ps, vv); loadA(ps, ps % 3); }
        CP_COMMIT();
        compute(s % 3);
        if (ps < nsl) stsB(ps % 3, vv);
    }

    const int gr = lane >> 2;
    const int gc = (lane & 3) * 2;
    __syncthreads();   // pipeline smem no longer in use

    if (F16OUT) {
        __half* y = (__half*)outT;
        __half* st = sm;   // [128][136] halves
        #pragma unroll
        for (int mi = 0; mi < 4; mi++) {
            int row = wm * 64 + mi * 16 + gr;
            #pragma unroll
            for (int ni = 0; ni < 4; ni++) {
                int col = wn * 32 + ni * 8 + gc;
                st[(uint32_t)col * 136 + row]           = __float2half(acc[mi][ni][0]);
                st[(uint32_t)(col + 1) * 136 + row]     = __float2half(acc[mi][ni][1]);
                st[(uint32_t)col * 136 + row + 8]       = __float2half(acc[mi][ni][2]);
                st[(uint32_t)(col + 1) * 136 + row + 8] = __float2half(acc[mi][ni][3]);
            }
        }
        __syncthreads();
        #pragma unroll
        for (int j = 0; j < 8; j++) {
            int idx = j * 256 + tid;
            int nl = idx >> 4, ch = idx & 15;
            uint4 v = *(const uint4*)&st[(uint32_t)nl * 136 + ch * 8];
            *(uint4*)&y[(size_t)(n0 + nl) * 512 + m0 + ch * 8] = v;
        }
    } else {
        float* y = (float*)outT;
        float* st = (float*)sm;  // [128][132] floats
        #pragma unroll
        for (int mi = 0; mi < 4; mi++) {
            int row = wm * 64 + mi * 16 + gr;
            #pragma unroll
            for (int ni = 0; ni < 4; ni++) {
                int col = wn * 32 + ni * 8 + gc;
                st[(uint32_t)col * 132 + row]           = acc[mi][ni][0];
                st[(uint32_t)(col + 1) * 132 + row]     = acc[mi][ni][1];
                st[(uint32_t)col * 132 + row + 8]       = acc[mi][ni][2];
                st[(uint32_t)(col + 1) * 132 + row + 8] = acc[mi][ni][3];
            }
        }
        __syncthreads();
        #pragma unroll
        for (int j = 0; j < 16; j++) {
            int idx = j * 256 + tid;
            int nl = idx >> 5, ch = idx & 31;
            float4 v = *(const float4*)&st[(uint32_t)nl * 132 + ch * 4];
            *(float4*)&y[(size_t)(n0 + nl) * 512 + m0 + ch * 4] = v;
        }
    }
}

// ---------------- interp2: y1 = gather(Zt) + y1b; fp16 out + BN1 stats ------
__global__ __launch_bounds__(256) void interp2_kernel(
    const float* __restrict__ Zt, const __half* __restrict__ y1bt,
    const int* __restrict__ idx, const float* __restrict__ wgt,
    __half* __restrict__ y1t, float* __restrict__ gsum, float* __restrict__ gsq)
{
    __shared__ float bsum[8][512];
    __shared__ float bsq[8][512];
    const int w = threadIdx.x >> 5;
    const int lane = threadIdx.x & 31;
    const int nb = blockIdx.x * 64 + w * 8;

    int ii[8][3]; float ww[8][3];
    #pragma unroll
    for (int t = 0; t < 8; t++) {
        int n = nb + t;
        ii[t][0] = __ldg(&idx[n * 3 + 0]);
        ii[t][1] = __ldg(&idx[n * 3 + 1]);
        ii[t][2] = __ldg(&idx[n * 3 + 2]);
        ww[t][0] = __ldg(&wgt[n * 3 + 0]);
        ww[t][1] = __ldg(&wgt[n * 3 + 1]);
        ww[t][2] = __ldg(&wgt[n * 3 + 2]);
    }

    for (int c0 = 0; c0 < 512; c0 += 32) {
        int c = c0 + lane;
        float s = 0.f, q = 0.f;
        #pragma unroll
        for (int t = 0; t < 8; t++) {
            int n = nb + t;
            float v = fmaf(ww[t][0], __ldg(&Zt[(size_t)ii[t][0] * 512 + c]),
                     fmaf(ww[t][1], __ldg(&Zt[(size_t)ii[t][1] * 512 + c]),
                          ww[t][2] * __ldg(&Zt[(size_t)ii[t][2] * 512 + c])));
            v += __half2float(__ldg(&y1bt[(size_t)n * 512 + c]));
            y1t[(size_t)n * 512 + c] = __float2half(v);
            s += v;
            q = fmaf(v, v, q);
        }
        bsum[w][c] = s;
        bsq[w][c] = q;
    }
    __syncthreads();
    for (int c = threadIdx.x; c < 512; c += 256) {
        float s = 0.f, q = 0.f;
        #pragma unroll
        for (int r = 0; r < 8; r++) { s += bsum[r][c]; q += bsq[r][c]; }
        atomicAdd(&gsum[c], s);
        atomicAdd(&gsq[c], q);
    }
}

// ---------------- GEMM2: B = y1t, inline BN1+ReLU; y2 fp16 + stats ----------
__global__ __launch_bounds__(256, 2) void gemm2_kernel(
    const __half* __restrict__ A, const __half* __restrict__ B,
    const float* __restrict__ sum1, const float* __restrict__ sq1,
    const float* __restrict__ g1, const float* __restrict__ b1,
    __half* __restrict__ Ch,
    float* __restrict__ gsum, float* __restrict__ gsq)
{
    extern __shared__ __half sm[];
    const uint32_t base = smem_u32(sm);
    float* scs = (float*)(sm + 3 * STAGE_B / 2);
    float* shs = scs + H1;
    const int tid  = threadIdx.x;
    const int lane = tid & 31;
    const int wid  = tid >> 5;
    const int wm   = wid & 1;
    const int wn   = wid >> 1;
    const int m0 = blockIdx.y * 128;
    const int n0 = blockIdx.x * 128;
    constexpr int K = H1;
    constexpr int nsl = K >> 5;

    for (int j = tid; j < H1; j += 256) {
        float mean = sum1[j] * (1.f / NPTS);
        float var  = sq1[j] * (1.f / NPTS) - mean * mean;
        float s    = g1[j] * rsqrtf(var + BN_EPS);
        scs[j] = s;
        shs[j] = fmaf(-mean, s, b1[j]);
    }
    __syncthreads();

    float acc[4][4][4] = {};

    auto loadA = [&](int s, int buf) {
        const int kt = s << 5;
        const uint32_t sb = base + buf * STAGE_B;
        #pragma unroll
        for (int i = 0; i < 2; i++) {
            int id = tid + i * 256;
            int r = id >> 2, seg = id & 3;
            cp16(sb + (uint32_t)(r * ROWH + seg * 8) * 2,
                 A + (size_t)(m0 + r) * K + kt + seg * 8);
        }
    };
    auto ldgB = [&](int s, uint4* v) {
        const int kt = s << 5;
        #pragma unroll
        for (int i = 0; i < 2; i++) {
            int id = tid + i * 256;
            int r = id >> 2, seg = id & 3;
            v[i] = *(const uint4*)&B[(size_t)(n0 + r) * K + kt + seg * 8];
        }
    };
    auto stsB = [&](int s, int buf, const uint4* v) {
        const int kt = s << 5;
        const uint32_t off0 = buf * STAGE_B + 128 * ROWH * 2;
        #pragma unroll
        for (int i = 0; i < 2; i++) {
            int id = tid + i * 256;
            int r = id >> 2, seg = id & 3;
            const __half* hv = (const __half*)&v[i];
            __half o[8];
            #pragma unroll
            for (int e = 0; e < 8; e++) {
                int k = kt + seg * 8 + e;
                float f = __half2float(hv[e]);
                o[e] = __float2half(fmaxf(fmaf(scs[k], f, shs[k]), 0.f));
            }
            *(uint4*)((char*)sm + off0 + (uint32_t)(r * ROWH + seg * 8) * 2)
                = *(const uint4*)o;
        }
    };

    auto compute = [&](int buf) {
        const uint32_t sb = base + buf * STAGE_B;
        #pragma unroll
        for (int kk = 0; kk < 2; kk++) {
            const int kh = kk * 16;
            uint32_t fB[4][2];
            const int brow = wn * 32 + (lane & 7);
            const int bcol = kh + (((lane >> 3) & 1) << 3);
            #pragma unroll
            for (int ni = 0; ni < 4; ni++)
                LDSM_X2(fB[ni], sb + 128 * ROWH * 2 +
                        (uint32_t)((brow + ni * 8) * ROWH + bcol) * 2);
            const int arow = wm * 64 + (lane & 15);
            const int acol = kh + ((lane >> 4) << 3);
            uint32_t fA[4][4];
            #pragma unroll
            for (int mi = 0; mi < 4; mi++)
                LDSM_X4(fA[mi], sb + (uint32_t)((arow + mi * 16) * ROWH + acol) * 2);
            #pragma unroll
            for (int mi = 0; mi < 4; mi++)
                #pragma unroll
                for (int ni = 0; ni < 4; ni++)
                    mma_f16(acc[mi][ni], fA[mi], fB[ni]);
        }
    };

    {
        uint4 v0[2], v1[2];
        ldgB(0, v0); loadA(0, 0); CP_COMMIT();
        ldgB(1, v1); loadA(1, 1); CP_COMMIT();
        stsB(0, 0, v0);
        stsB(1, 1, v1);
    }
    for (int s = 0; s < nsl; s++) {
        CP_WAIT1();
        __syncthreads();
        uint4 vv[2];
        int ps = s + 2;
        if (ps < nsl) { ldgB(ps, vv); loadA(ps, ps % 3); }
        CP_COMMIT();
        compute(s % 3);
        if (ps < nsl) stsB(ps, ps % 3, vv);
    }

    const int gr = lane >> 2;
    const int gc = (lane & 3) * 2;
    #pragma unroll
    for (int mi = 0; mi < 4; mi++) {
        #pragma unroll
        for (int ni = 0; ni < 4; ni++) {
            int row = m0 + wm * 64 + mi * 16 + gr;
            int col = n0 + wn * 32 + ni * 8 + gc;
            *(__half2*)&Ch[(size_t)row * NPTS + col] =
                __floats2half2_rn(acc[mi][ni][0], acc[mi][ni][1]);
            *(__half2*)&Ch[(size_t)(row + 8) * NPTS + col] =
                __floats2half2_rn(acc[mi][ni][2], acc[mi][ni][3]);
        }
        #pragma unroll
        for (int h2 = 0; h2 < 2; h2++) {
            float s = 0.f, q = 0.f;
            #pragma unroll
            for (int ni = 0; ni < 4; ni++) {
                float v0 = acc[mi][ni][2 * h2], v1 = acc[mi][ni][2 * h2 + 1];
                s += v0 + v1;
                q += v0 * v0 + v1 * v1;
            }
            s += __shfl_xor_sync(0xffffffffu, s, 1);
            q += __shfl_xor_sync(0xffffffffu, q, 1);
            s += __shfl_xor_sync(0xffffffffu, s, 2);
            q += __shfl_xor_sync(0xffffffffu, q, 2);
            if ((lane & 3) == 0) {
                int row = m0 + wm * 64 + mi * 16 + gr + h2 * 8;
                atomicAdd(&gsum[row], s);
                atomicAdd(&gsq[row], q);
            }
        }
    }
}

// ---------------- final BN+ReLU elementwise (fp16 in, fp32 out) -------------
__global__ __launch_bounds__(256) void bn_apply_kernel(
    const __half* __restrict__ Yh,
    const float* __restrict__ sum, const float* __restrict__ sq,
    const float* __restrict__ g, const float* __restrict__ b,
    float* __restrict__ out)
{
    int i = blockIdx.x * 256 + threadIdx.x;   // 4-element groups
    int c = i >> 12;
    float mean = sum[c] * (1.f / NPTS);
    float var  = sq[c] * (1.f / NPTS) - mean * mean;
    float s    = g[c] * rsqrtf(var + BN_EPS);
    float h    = fmaf(-mean, s, b[c]);
    const __half2* Y2 = (const __half2*)Yh;
    float2 p0 = __half22float2(Y2[2 * i]);
    float2 p1 = __half22float2(Y2[2 * i + 1]);
    float4 v;
    v.x = fmaxf(fmaf(s, p0.x, h), 0.f);
    v.y = fmaxf(fmaf(s, p0.y, h), 0.f);
    v.z = fmaxf(fmaf(s, p1.x, h), 0.f);
    v.w = fmaxf(fmaf(s, p1.y, h), 0.f);
    reinterpret_cast<float4*>(out)[i] = v;
}

// ---------------- launch -----------------------------------------------------
extern "C" void kernel_launch(void* const* d_in, const int* in_sizes, int n_in,
                              void* d_out, int out_size)
{
    const float* xyz_fine     = (const float*)d_in[0];
    const float* xyz_coarse   = (const float*)d_in[1];
    const float* feats_fine   = (const float*)d_in[2];
    const float* feats_coarse = (const float*)d_in[3];
    const float* W1 = (const float*)d_in[4];
    const float* g1 = (const float*)d_in[5];
    const float* b1 = (const float*)d_in[6];
    const float* W2 = (const float*)d_in[7];
    const float* g2 = (const float*)d_in[8];
    const float* b2 = (const float*)d_in[9];
    float* out = (float*)d_out;

    void* p;
    cudaGetSymbolAddress(&p, g_idx);  int*    idxp = (int*)p;
    cudaGetSymbolAddress(&p, g_w);    float*  wp   = (float*)p;
    cudaGetSymbolAddress(&p, g_Zt);   float*  Zt   = (float*)p;
    cudaGetSymbolAddress(&p, g_y1bt); __half* y1bt = (__half*)p;
    cudaGetSymbolAddress(&p, g_y1t);  __half* y1t  = (__half*)p;
    cudaGetSymbolAddress(&p, g_A1a);  __half* a1a  = (__half*)p;
    cudaGetSymbolAddress(&p, g_A1b);  __half* a1b  = (__half*)p;
    cudaGetSymbolAddress(&p, g_A2);   __half* a2   = (__half*)p;
    cudaGetSymbolAddress(&p, g_y2h);  __half* y2h  = (__half*)p;
    cudaGetSymbolAddress(&p, g_sum1); float*  sum1 = (float*)p;
    cudaGetSymbolAddress(&p, g_sq1);  float*  sq1  = (float*)p;
    cudaGetSymbolAddress(&p, g_sum2); float*  sum2 = (float*)p;
    cudaGetSymbolAddress(&p, g_sq2);  float*  sq2  = (float*)p;

    cudaFuncSetAttribute(gemm_bmn_kernel<CC, false>,
                         cudaFuncAttributeMaxDynamicSharedMemorySize, GZ_SMEM);
    cudaFuncSetAttribute(gemm_bmn_kernel<CF, true>,
                         cudaFuncAttributeMaxDynamicSharedMemorySize, G1B_SMEM);
    cudaFuncSetAttribute(gemm2_kernel,
                         cudaFuncAttributeMaxDynamicSharedMemorySize, G2_SMEM);
    cudaFuncSetAttribute(knn_kernel,
                         cudaFuncAttributeMaxDynamicSharedMemorySize, KNN_SMEM);

    prep_kernel<<<(H1 * CC + 255) / 256, 256>>>(W1, W2, a1a, a1b, a2,
                                                sum1, sq1, sum2, sq2);
    knn_kernel<<<NPTS / 32, 256, KNN_SMEM>>>(xyz_fine, xyz_coarse, idxp, wp);
    // Z^T = (W1a @ fc)^T : [4096][512] fp32; B direct from feats_coarse
    gemm_bmn_kernel<CC, false><<<dim3(MPTS / 128, H1 / 128), 256, GZ_SMEM>>>(
        a1a, feats_coarse, MPTS, Zt);
    // y1b^T = (W1b @ ff)^T : [16384][512] fp16; B direct from feats_fine
    gemm_bmn_kernel<CF, true><<<dim3(NPTS / 128, H1 / 128), 256, G1B_SMEM>>>(
        a1b, feats_fine, NPTS, y1bt);
    interp2_kernel<<<NPTS / 64, 256>>>(Zt, y1bt, idxp, wp, y1t, sum1, sq1);
    gemm2_kernel<<<dim3(NPTS / 128, H2 / 128), 256, G2_SMEM>>>(
        a2, y1t, sum1, sq1, g1, b1, y2h, sum2, sq2);
    bn_apply_kernel<<<(H2 * NPTS / 4) / 256, 256>>>(
        y2h, sum2, sq2, g2, b2, out);
}

// round 13
// speedup vs baseline: 3.2103x; 1.0017x over previous
#include <cuda_runtime.h>
#include <cuda_fp16.h>
#include <cstdint>

// Problem constants (fixed by the dataset)
#define NPTS 16384   // fine points
#define MPTS 4096    // coarse points
#define CF   256     // fine feature channels
#define CC   512     // coarse feature channels
#define INCH 768     // CC + CF
#define H1   512
#define H2   512
#define BN_EPS 1e-5f

// ---------------- scratch (device globals; no runtime allocation) ----------
__device__ int    g_idx[NPTS * 3];
__device__ float  g_w[NPTS * 3];
__device__ __align__(256) float  g_Zt[(size_t)MPTS * H1];     // (W1a@fc)^T fp32 [M][512]
__device__ __align__(256) __half g_y1bt[(size_t)NPTS * H1];   // (W1b@ff)^T fp16 [N][512]
__device__ __align__(256) __half g_y1t[(size_t)NPTS * H1];    // raw y1^T fp16 [N][512]
__device__ __align__(256) __half g_A1a[H1 * CC];
__device__ __align__(256) __half g_A1b[H1 * CF];
__device__ __align__(256) __half g_A2[H2 * H1];
__device__ __align__(256) __half g_y2h[(size_t)H2 * NPTS];    // raw y2 fp16
__device__ float g_sum1[H1], g_sq1[H1], g_sum2[H2], g_sq2[H2];

// ---------------- PTX helpers (all baseline, no 103a features) -------------
__device__ __forceinline__ uint32_t smem_u32(const void* p) {
    uint32_t a;
    asm("{ .reg .u64 t; cvta.to.shared.u64 t, %1; cvt.u32.u64 %0, t; }"
        : "=r"(a) : "l"(p));
    return a;
}
__device__ __forceinline__ void cp16(uint32_t dst, const void* src) {
    asm volatile("cp.async.cg.shared.global [%0], [%1], 16;"
                 :: "r"(dst), "l"(src) : "memory");
}
#define CP_COMMIT() asm volatile("cp.async.commit_group;" ::: "memory")
#define CP_WAIT2()  asm volatile("cp.async.wait_group 2;" ::: "memory")

#define LDSM_X4(r, addr) \
    asm volatile("ldmatrix.sync.aligned.m8n8.x4.shared.b16 {%0,%1,%2,%3}, [%4];" \
                 : "=r"((r)[0]), "=r"((r)[1]), "=r"((r)[2]), "=r"((r)[3]) : "r"(addr))
#define LDSM_X2(r, addr) \
    asm volatile("ldmatrix.sync.aligned.m8n8.x2.shared.b16 {%0,%1}, [%2];" \
                 : "=r"((r)[0]), "=r"((r)[1]) : "r"(addr))
#define LDSM_X2T(r, addr) \
    asm volatile("ldmatrix.sync.aligned.m8n8.x2.trans.shared.b16 {%0,%1}, [%2];" \
                 : "=r"((r)[0]), "=r"((r)[1]) : "r"(addr))

__device__ __forceinline__ void mma_f16(float c[4], const uint32_t a[4],
                                        const uint32_t b[2]) {
    asm volatile(
        "mma.sync.aligned.m16n8k16.row.col.f32.f16.f16.f32 "
        "{%0,%1,%2,%3}, {%4,%5,%6,%7}, {%8,%9}, {%0,%1,%2,%3};"
        : "+f"(c[0]), "+f"(c[1]), "+f"(c[2]), "+f"(c[3])
        : "r"(a[0]), "r"(a[1]), "r"(a[2]), "r"(a[3]), "r"(b[0]), "r"(b[1]));
}

// ---------------- prep: W1 split + W2 convert + zero BN stats ---------------
__global__ void prep_kernel(const float* __restrict__ W1, const float* __restrict__ W2,
                            __half* __restrict__ a1a, __half* __restrict__ a1b,
                            __half* __restrict__ a2,
                            float* s1, float* q1, float* s2, float* q2)
{
    int i = blockIdx.x * 256 + threadIdx.x;
    if (i < H1 * CC) {
        a1a[i] = __float2half(W1[(i >> 9) * INCH + (i & 511)]);
        a2[i]  = __float2half(W2[i]);
    }
    if (i < H1 * CF)
        a1b[i] = __float2half(W1[(i >> 8) * INCH + CC + (i & 255)]);
    if (i < H1) { s1[i] = 0.f; q1[i] = 0.f; }
    if (i < H2) { s2[i] = 0.f; q2[i] = 0.f; }
}

// ---------------- kNN: warp per 4 queries; points packed float4 -------------
__device__ __forceinline__ void top3_insert(float d, int j,
                                            float& d0, float& d1, float& d2,
                                            int& i0, int& i1, int& i2) {
    if (d < d2) {
        if (d < d1) {
            d2 = d1; i2 = i1;
            if (d < d0) { d1 = d0; i1 = i0; d0 = d; i0 = j; }
            else        { d1 = d;  i1 = j; }
        } else { d2 = d; i2 = j; }
    }
}

static constexpr int KNN_SMEM = MPTS * 16;   // float4 per point (64 KB)

__global__ __launch_bounds__(256) void knn_kernel(
    const float* __restrict__ xf, const float* __restrict__ xc,
    int* __restrict__ idx_out, float* __restrict__ w_out)
{
    extern __shared__ float4 spts[];
    for (int j = threadIdx.x; j < MPTS; j += 256) {
        float x = xc[j], y = xc[MPTS + j], z = xc[2 * MPTS + j];
        spts[j] = make_float4(x, y, z, fmaf(x, x, fmaf(y, y, z * z)));
    }
    __syncthreads();

    const int warp = threadIdx.x >> 5;
    const int lane = threadIdx.x & 31;
    const int nb = blockIdx.x * 32 + warp * 4;

    float qx[4], qy[4], qz[4], q2x[4], q2y[4], q2z[4];
    #pragma unroll
    for (int t = 0; t < 4; t++) {
        qx[t] = xf[nb + t]; qy[t] = xf[NPTS + nb + t]; qz[t] = xf[2 * NPTS + nb + t];
        q2x[t] = -2.f * qx[t]; q2y[t] = -2.f * qy[t]; q2z[t] = -2.f * qz[t];
    }

    float d[4][3];
    int   ix[4][3];
    #pragma unroll
    for (int t = 0; t < 4; t++) {
        d[t][0] = d[t][1] = d[t][2] = 3.4e38f;
        ix[t][0] = ix[t][1] = ix[t][2] = 0;
    }

    for (int j = lane; j < MPTS; j += 32) {
        float4 p = spts[j];
        #pragma unroll
        for (int t = 0; t < 4; t++) {
            float e = fmaf(q2x[t], p.x, fmaf(q2y[t], p.y, fmaf(q2z[t], p.z, p.w)));
            top3_insert(e, j, d[t][0], d[t][1], d[t][2], ix[t][0], ix[t][1], ix[t][2]);
        }
    }

    #pragma unroll
    for (int t = 0; t < 4; t++) {
        for (int off = 16; off; off >>= 1) {
            float od0 = __shfl_xor_sync(0xffffffffu, d[t][0], off);
            float od1 = __shfl_xor_sync(0xffffffffu, d[t][1], off);
            float od2 = __shfl_xor_sync(0xffffffffu, d[t][2], off);
            int   oi0 = __shfl_xor_sync(0xffffffffu, ix[t][0], off);
            int   oi1 = __shfl_xor_sync(0xffffffffu, ix[t][1], off);
            int   oi2 = __shfl_xor_sync(0xffffffffu, ix[t][2], off);
            top3_insert(od0, oi0, d[t][0], d[t][1], d[t][2], ix[t][0], ix[t][1], ix[t][2]);
            top3_insert(od1, oi1, d[t][0], d[t][1], d[t][2], ix[t][0], ix[t][1], ix[t][2]);
            top3_insert(od2, oi2, d[t][0], d[t][1], d[t][2], ix[t][0], ix[t][1], ix[t][2]);
        }
        if (lane == 0) {
            int n = nb + t;
            float D[3];
            #pragma unroll
            for (int k = 0; k < 3; k++) {
                float4 p = spts[ix[t][k]];
                float dx = qx[t] - p.x, dy = qy[t] - p.y, dz = qz[t] - p.z;
                D[k] = fmaxf(sqrtf(fmaf(dx, dx, fmaf(dy, dy, dz * dz))), 1e-8f);
            }
            float w0 = 1.f / D[0], w1 = 1.f / D[1], w2 = 1.f / D[2];
            float inv = 1.f / (w0 + w1 + w2);
            idx_out[n * 3 + 0] = ix[t][0];
            idx_out[n * 3 + 1] = ix[t][1];
            idx_out[n * 3 + 2] = ix[t][2];
            w_out[n * 3 + 0] = w0 * inv;
            w_out[n * 3 + 1] = w1 * inv;
            w_out[n * 3 + 2] = w2 * inv;
        }
    }
}

// ---------------- shared GEMM constants --------------------------------------
static constexpr int ROWH = 40;                   // padded halves per A row
static constexpr int A_TILE = 128 * ROWH * 2;     // 10240 B (128m x 32k)
static constexpr int BROW = 136;                  // padded halves per B [k] row
static constexpr int B_TILE2 = 32 * BROW * 2;     // 8704 B (32k x 128n)
static constexpr int STG = A_TILE + B_TILE2;      // 18944 B per stage
static constexpr int GZ_SMEM  = 4 * STG;               // 75776 (>= fp32 epilogue 67584)
static constexpr int G1B_SMEM = 4 * STG;               // 75776
static constexpr int STAGE_B = 2 * (128 * ROWH * 2);   // gemm2 stage (A+B, 20480)
static constexpr int G2_SMEM  = 4 * STAGE_B + 4096;    // 86016

// ---------------- gemm_bmn: A[512][K] fp16 @ B fp32 [K][Nall] (MN-major) ----
// B loaded direct from global with inline fp16 convert; ldmatrix.trans path.
// OutT [Nall][512]: fp16 (F16OUT) or fp32. 4-stage cp.async, wait_group 2.
template<int K, bool F16OUT>
__global__ __launch_bounds__(256, 2) void gemm_bmn_kernel(
    const __half* __restrict__ A, const float* __restrict__ Bg, int Nall,
    void* __restrict__ outT)
{
    extern __shared__ __half sm[];
    const uint32_t base = smem_u32(sm);
    const int tid  = threadIdx.x;
    const int lane = tid & 31;
    const int wid  = tid >> 5;
    const int wm   = wid & 1;
    const int wn   = wid >> 1;
    const int m0 = blockIdx.y * 128;
    const int n0 = blockIdx.x * 128;
    constexpr int nsl = K >> 5;

    float acc[4][4][4] = {};

    auto loadA = [&](int s, int buf) {
        const int kt = s << 5;
        const uint32_t sb = base + buf * STG;
        #pragma unroll
        for (int i = 0; i < 2; i++) {
            int id = tid + i * 256;
            int r = id >> 2, seg = id & 3;
            cp16(sb + (uint32_t)(r * ROWH + seg * 8) * 2,
                 A + (size_t)(m0 + r) * K + kt + seg * 8);
        }
    };
    auto ldgB = [&](int s, float4* v) {
        const int kt = s << 5;
        #pragma unroll
        for (int i = 0; i < 4; i++) {
            int id = tid + i * 256;            // 0..1023
            int kr = id >> 5, nc4 = (id & 31) * 4;
            v[i] = *(const float4*)&Bg[(size_t)(kt + kr) * Nall + n0 + nc4];
        }
    };
    auto stsB = [&](int buf, const float4* v) {
        const uint32_t off0 = buf * STG + A_TILE;
        #pragma unroll
        for (int i = 0; i < 4; i++) {
            int id = tid + i * 256;
            int kr = id >> 5, nc4 = (id & 31) * 4;
            __half o[4];
            o[0] = __float2half(v[i].x); o[1] = __float2half(v[i].y);
            o[2] = __float2half(v[i].z); o[3] = __float2half(v[i].w);
            *(uint2*)((char*)sm + off0 + (uint32_t)(kr * BROW + nc4) * 2)
                = *(const uint2*)o;
        }
    };

    auto compute = [&](int buf) {
        const uint32_t sbA = base + buf * STG;
        const uint32_t sbB = sbA + A_TILE;
        #pragma unroll
        for (int kk = 0; kk < 2; kk++) {
            const int kh = kk * 16;
            uint32_t fB[4][2];
            const int krow = kh + (lane & 15);
            #pragma unroll
            for (int ni = 0; ni < 4; ni++)
                LDSM_X2T(fB[ni], sbB +
                         (uint32_t)(krow * BROW + wn * 32 + ni * 8) * 2);
            const int arow = wm * 64 + (lane & 15);
            const int acol = kh + ((lane >> 4) << 3);
            uint32_t fA[4][4];
            #pragma unroll
            for (int mi = 0; mi < 4; mi++)
                LDSM_X4(fA[mi], sbA + (uint32_t)((arow + mi * 16) * ROWH + acol) * 2);
            #pragma unroll
            for (int mi = 0; mi < 4; mi++)
                #pragma unroll
                for (int ni = 0; ni < 4; ni++)
                    mma_f16(acc[mi][ni], fA[mi], fB[ni]);
        }
    };

    {
        float4 v0[4], v1[4], v2[4];
        ldgB(0, v0); loadA(0, 0); CP_COMMIT();
        ldgB(1, v1); loadA(1, 1); CP_COMMIT();
        ldgB(2, v2); loadA(2, 2); CP_COMMIT();
        stsB(0, v0);
        stsB(1, v1);
        stsB(2, v2);
    }
    for (int s = 0; s < nsl; s++) {
        CP_WAIT2();
        __syncthreads();
        float4 vv[4];
        int ps = s + 3;
        if (ps < nsl) { ldgB(ps, vv); loadA(ps, ps & 3); }
        CP_COMMIT();
        compute(s & 3);
        if (ps < nsl) stsB(ps & 3, vv);
    }

    const int gr = lane >> 2;
    const int gc = (lane & 3) * 2;
    __syncthreads();   // pipeline smem no longer in use

    if (F16OUT) {
        __half* y = (__half*)outT;
        __half* st = sm;   // [128][136] halves
        #pragma unroll
        for (int mi = 0; mi < 4; mi++) {
            int row = wm * 64 + mi * 16 + gr;
            #pragma unroll
            for (int ni = 0; ni < 4; ni++) {
                int col = wn * 32 + ni * 8 + gc;
                st[(uint32_t)col * 136 + row]           = __float2half(acc[mi][ni][0]);
                st[(uint32_t)(col + 1) * 136 + row]     = __float2half(acc[mi][ni][1]);
                st[(uint32_t)col * 136 + row + 8]       = __float2half(acc[mi][ni][2]);
                st[(uint32_t)(col + 1) * 136 + row + 8] = __float2half(acc[mi][ni][3]);
            }
        }
        __syncthreads();
        #pragma unroll
        for (int j = 0; j < 8; j++) {
            int idx = j * 256 + tid;
            int nl = idx >> 4, ch = idx & 15;
            uint4 v = *(const uint4*)&st[(uint32_t)nl * 136 + ch * 8];
            *(uint4*)&y[(size_t)(n0 + nl) * 512 + m0 + ch * 8] = v;
        }
    } else {
        float* y = (float*)outT;
        float* st = (float*)sm;  // [128][132] floats
        #pragma unroll
        for (int mi = 0; mi < 4; mi++) {
            int row = wm * 64 + mi * 16 + gr;
            #pragma unroll
            for (int ni = 0; ni < 4; ni++) {
                int col = wn * 32 + ni * 8 + gc;
                st[(uint32_t)col * 132 + row]           = acc[mi][ni][0];
                st[(uint32_t)(col + 1) * 132 + row]     = acc[mi][ni][1];
                st[(uint32_t)col * 132 + row + 8]       = acc[mi][ni][2];
                st[(uint32_t)(col + 1) * 132 + row + 8] = acc[mi][ni][3];
            }
        }
        __syncthreads();
        #pragma unroll
        for (int j = 0; j < 16; j++) {
            int idx = j * 256 + tid;
            int nl = idx >> 5, ch = idx & 31;
            float4 v = *(const float4*)&st[(uint32_t)nl * 132 + ch * 4];
            *(float4*)&y[(size_t)(n0 + nl) * 512 + m0 + ch * 4] = v;
        }
    }
}

// ---------------- interp2: y1 = gather(Zt) + y1b; fp16 out + BN1 stats ------
__global__ __launch_bounds__(256) void interp2_kernel(
    const float* __restrict__ Zt, const __half* __restrict__ y1bt,
    const int* __restrict__ idx, const float* __restrict__ wgt,
    __half* __restrict__ y1t, float* __restrict__ gsum, float* __restrict__ gsq)
{
    __shared__ float bsum[8][512];
    __shared__ float bsq[8][512];
    const int w = threadIdx.x >> 5;
    const int lane = threadIdx.x & 31;
    const int nb = blockIdx.x * 64 + w * 8;

    int ii[8][3]; float ww[8][3];
    #pragma unroll
    for (int t = 0; t < 8; t++) {
        int n = nb + t;
        ii[t][0] = __ldg(&idx[n * 3 + 0]);
        ii[t][1] = __ldg(&idx[n * 3 + 1]);
        ii[t][2] = __ldg(&idx[n * 3 + 2]);
        ww[t][0] = __ldg(&wgt[n * 3 + 0]);
        ww[t][1] = __ldg(&wgt[n * 3 + 1]);
        ww[t][2] = __ldg(&wgt[n * 3 + 2]);
    }

    for (int c0 = 0; c0 < 512; c0 += 32) {
        int c = c0 + lane;
        float s = 0.f, q = 0.f;
        #pragma unroll
        for (int t = 0; t < 8; t++) {
            int n = nb + t;
            float v = fmaf(ww[t][0], __ldg(&Zt[(size_t)ii[t][0] * 512 + c]),
                     fmaf(ww[t][1], __ldg(&Zt[(size_t)ii[t][1] * 512 + c]),
                          ww[t][2] * __ldg(&Zt[(size_t)ii[t][2] * 512 + c])));
            v += __half2float(__ldg(&y1bt[(size_t)n * 512 + c]));
            y1t[(size_t)n * 512 + c] = __float2half(v);
            s += v;
            q = fmaf(v, v, q);
        }
        bsum[w][c] = s;
        bsq[w][c] = q;
    }
    __syncthreads();
    for (int c = threadIdx.x; c < 512; c += 256) {
        float s = 0.f, q = 0.f;
        #pragma unroll
        for (int r = 0; r < 8; r++) { s += bsum[r][c]; q += bsq[r][c]; }
        atomicAdd(&gsum[c], s);
        atomicAdd(&gsq[c], q);
    }
}

// ---------------- GEMM2: B = y1t, inline BN1+ReLU; y2 fp16 + stats ----------
// 4-stage cp.async (A) + register-staged B transform, wait_group 2.
__global__ __launch_bounds__(256, 2) void gemm2_kernel(
    const __half* __restrict__ A, const __half* __restrict__ B,
    const float* __restrict__ sum1, const float* __restrict__ sq1,
    const float* __restrict__ g1, const float* __restrict__ b1,
    __half* __restrict__ Ch,
    float* __restrict__ gsum, float* __restrict__ gsq)
{
    extern __shared__ __half sm[];
    const uint32_t base = smem_u32(sm);
    float* scs = (float*)(sm + 4 * STAGE_B / 2);
    float* shs = scs + H1;
    const int tid  = threadIdx.x;
    const int lane = tid & 31;
    const int wid  = tid >> 5;
    const int wm   = wid & 1;
    const int wn   = wid >> 1;
    const int m0 = blockIdx.y * 128;
    const int n0 = blockIdx.x * 128;
    constexpr int K = H1;
    constexpr int nsl = K >> 5;

    for (int j = tid; j < H1; j += 256) {
        float mean = sum1[j] * (1.f / NPTS);
        float var  = sq1[j] * (1.f / NPTS) - mean * mean;
        float s    = g1[j] * rsqrtf(var + BN_EPS);
        scs[j] = s;
        shs[j] = fmaf(-mean, s, b1[j]);
    }
    __syncthreads();

    float acc[4][4][4] = {};

    auto loadA = [&](int s, int buf) {
        const int kt = s << 5;
        const uint32_t sb = base + buf * STAGE_B;
        #pragma unroll
        for (int i = 0; i < 2; i++) {
            int id = tid + i * 256;
            int r = id >> 2, seg = id & 3;
            cp16(sb + (uint32_t)(r * ROWH + seg * 8) * 2,
                 A + (size_t)(m0 + r) * K + kt + seg * 8);
        }
    };
    auto ldgB = [&](int s, uint4* v) {
        const int kt = s << 5;
        #pragma unroll
        for (int i = 0; i < 2; i++) {
            int id = tid + i * 256;
            int r = id >> 2, seg = id & 3;
            v[i] = *(const uint4*)&B[(size_t)(n0 + r) * K + kt + seg * 8];
        }
    };
    auto stsB = [&](int s, int buf, const uint4* v) {
        const int kt = s << 5;
        const uint32_t off0 = buf * STAGE_B + 128 * ROWH * 2;
        #pragma unroll
        for (int i = 0; i < 2; i++) {
            int id = tid + i * 256;
            int r = id >> 2, seg = id & 3;
            const __half* hv = (const __half*)&v[i];
            __half o[8];
            #pragma unroll
            for (int e = 0; e < 8; e++) {
                int k = kt + seg * 8 + e;
                float f = __half2float(hv[e]);
                o[e] = __float2half(fmaxf(fmaf(scs[k], f, shs[k]), 0.f));
            }
            *(uint4*)((char*)sm + off0 + (uint32_t)(r * ROWH + seg * 8) * 2)
                = *(const uint4*)o;
        }
    };

    auto compute = [&](int buf) {
        const uint32_t sb = base + buf * STAGE_B;
        #pragma unroll
        for (int kk = 0; kk < 2; kk++) {
            const int kh = kk * 16;
            uint32_t fB[4][2];
            const int brow = wn * 32 + (lane & 7);
            const int bcol = kh + (((lane >> 3) & 1) << 3);
            #pragma unroll
            for (int ni = 0; ni < 4; ni++)
                LDSM_X2(fB[ni], sb + 128 * ROWH * 2 +
                        (uint32_t)((brow + ni * 8) * ROWH + bcol) * 2);
            const int arow = wm * 64 + (lane & 15);
            const int acol = kh + ((lane >> 4) << 3);
            uint32_t fA[4][4];
            #pragma unroll
            for (int mi = 0; mi < 4; mi++)
                LDSM_X4(fA[mi], sb + (uint32_t)((arow + mi * 16) * ROWH + acol) * 2);
            #pragma unroll
            for (int mi = 0; mi < 4; mi++)
                #pragma unroll
                for (int ni = 0; ni < 4; ni++)
                    mma_f16(acc[mi][ni], fA[mi], fB[ni]);
        }
    };

    {
        uint4 v0[2], v1[2], v2[2];
        ldgB(0, v0); loadA(0, 0); CP_COMMIT();
        ldgB(1, v1); loadA(1, 1); CP_COMMIT();
        ldgB(2, v2); loadA(2, 2); CP_COMMIT();
        stsB(0, 0, v0);
        stsB(1, 1, v1);
        stsB(2, 2, v2);
    }
    for (int s = 0; s < nsl; s++) {
        CP_WAIT2();
        __syncthreads();
        uint4 vv[2];
        int ps = s + 3;
        if (ps < nsl) { ldgB(ps, vv); loadA(ps, ps & 3); }
        CP_COMMIT();
        compute(s & 3);
        if (ps < nsl) stsB(ps, ps & 3, vv);
    }

    const int gr = lane >> 2;
    const int gc = (lane & 3) * 2;
    #pragma unroll
    for (int mi = 0; mi < 4; mi++) {
        #pragma unroll
        for (int ni = 0; ni < 4; ni++) {
            int row = m0 + wm * 64 + mi * 16 + gr;
            int col = n0 + wn * 32 + ni * 8 + gc;
            *(__half2*)&Ch[(size_t)row * NPTS + col] =
                __floats2half2_rn(acc[mi][ni][0], acc[mi][ni][1]);
            *(__half2*)&Ch[(size_t)(row + 8) * NPTS + col] =
                __floats2half2_rn(acc[mi][ni][2], acc[mi][ni][3]);
        }
        #pragma unroll
        for (int h2 = 0; h2 < 2; h2++) {
            float s = 0.f, q = 0.f;
            #pragma unroll
            for (int ni = 0; ni < 4; ni++) {
                float v0 = acc[mi][ni][2 * h2], v1 = acc[mi][ni][2 * h2 + 1];
                s += v0 + v1;
                q += v0 * v0 + v1 * v1;
            }
            s += __shfl_xor_sync(0xffffffffu, s, 1);
            q += __shfl_xor_sync(0xffffffffu, q, 1);
            s += __shfl_xor_sync(0xffffffffu, s, 2);
            q += __shfl_xor_sync(0xffffffffu, q, 2);
            if ((lane & 3) == 0) {
                int row = m0 + wm * 64 + mi * 16 + gr + h2 * 8;
                atomicAdd(&gsum[row], s);
                atomicAdd(&gsq[row], q);
            }
        }
    }
}

// ---------------- final BN+ReLU elementwise (fp16 in, fp32 out) -------------
__global__ __launch_bounds__(256) void bn_apply_kernel(
    const __half* __restrict__ Yh,
    const float* __restrict__ sum, const float* __restrict__ sq,
    const float* __restrict__ g, const float* __restrict__ b,
    float* __restrict__ out)
{
    int i = blockIdx.x * 256 + threadIdx.x;   // 4-element groups
    int c = i >> 12;
    float mean = sum[c] * (1.f / NPTS);
    float var  = sq[c] * (1.f / NPTS) - mean * mean;
    float s    = g[c] * rsqrtf(var + BN_EPS);
    float h    = fmaf(-mean, s, b[c]);
    const __half2* Y2 = (const __half2*)Yh;
    float2 p0 = __half22float2(Y2[2 * i]);
    float2 p1 = __half22float2(Y2[2 * i + 1]);
    float4 v;
    v.x = fmaxf(fmaf(s, p0.x, h), 0.f);
    v.y = fmaxf(fmaf(s, p0.y, h), 0.f);
    v.z = fmaxf(fmaf(s, p1.x, h), 0.f);
    v.w = fmaxf(fmaf(s, p1.y, h), 0.f);
    reinterpret_cast<float4*>(out)[i] = v;
}

// ---------------- launch -----------------------------------------------------
extern "C" void kernel_launch(void* const* d_in, const int* in_sizes, int n_in,
                              void* d_out, int out_size)
{
    const float* xyz_fine     = (const float*)d_in[0];
    const float* xyz_coarse   = (const float*)d_in[1];
    const float* feats_fine   = (const float*)d_in[2];
    const float* feats_coarse = (const float*)d_in[3];
    const float* W1 = (const float*)d_in[4];
    const float* g1 = (const float*)d_in[5];
    const float* b1 = (const float*)d_in[6];
    const float* W2 = (const float*)d_in[7];
    const float* g2 = (const float*)d_in[8];
    const float* b2 = (const float*)d_in[9];
    float* out = (float*)d_out;

    void* p;
    cudaGetSymbolAddress(&p, g_idx);  int*    idxp = (int*)p;
    cudaGetSymbolAddress(&p, g_w);    float*  wp   = (float*)p;
    cudaGetSymbolAddress(&p, g_Zt);   float*  Zt   = (float*)p;
    cudaGetSymbolAddress(&p, g_y1bt); __half* y1bt = (__half*)p;
    cudaGetSymbolAddress(&p, g_y1t);  __half* y1t  = (__half*)p;
    cudaGetSymbolAddress(&p, g_A1a);  __half* a1a  = (__half*)p;
    cudaGetSymbolAddress(&p, g_A1b);  __half* a1b  = (__half*)p;
    cudaGetSymbolAddress(&p, g_A2);   __half* a2   = (__half*)p;
    cudaGetSymbolAddress(&p, g_y2h);  __half* y2h  = (__half*)p;
    cudaGetSymbolAddress(&p, g_sum1); float*  sum1 = (float*)p;
    cudaGetSymbolAddress(&p, g_sq1);  float*  sq1  = (float*)p;
    cudaGetSymbolAddress(&p, g_sum2); float*  sum2 = (float*)p;
    cudaGetSymbolAddress(&p, g_sq2);  float*  sq2  = (float*)p;

    cudaFuncSetAttribute(gemm_bmn_kernel<CC, false>,
                         cudaFuncAttributeMaxDynamicSharedMemorySize, GZ_SMEM);
    cudaFuncSetAttribute(gemm_bmn_kernel<CF, true>,
                         cudaFuncAttributeMaxDynamicSharedMemorySize, G1B_SMEM);
    cudaFuncSetAttribute(gemm2_kernel,
                         cudaFuncAttributeMaxDynamicSharedMemorySize, G2_SMEM);
    cudaFuncSetAttribute(knn_kernel,
                         cudaFuncAttributeMaxDynamicSharedMemorySize, KNN_SMEM);

    prep_kernel<<<(H1 * CC + 255) / 256, 256>>>(W1, W2, a1a, a1b, a2,
                                                sum1, sq1, sum2, sq2);
    knn_kernel<<<NPTS / 32, 256, KNN_SMEM>>>(xyz_fine, xyz_coarse, idxp, wp);
    // Z^T = (W1a @ fc)^T : [4096][512] fp32; B direct from feats_coarse
    gemm_bmn_kernel<CC, false><<<dim3(MPTS / 128, H1 / 128), 256, GZ_SMEM>>>(
        a1a, feats_coarse, MPTS, Zt);
    // y1b^T = (W1b @ ff)^T : [16384][512] fp16; B direct from feats_fine
    gemm_bmn_kernel<CF, true><<<dim3(NPTS / 128, H1 / 128), 256, G1B_SMEM>>>(
        a1b, feats_fine, NPTS, y1bt);
    interp2_kernel<<<NPTS / 64, 256>>>(Zt, y1bt, idxp, wp, y1t, sum1, sq1);
    gemm2_kernel<<<dim3(NPTS / 128, H2 / 128), 256, G2_SMEM>>>(
        a2, y1t, sum1, sq1, g1, b1, y2h, sum2, sq2);
    bn_apply_kernel<<<(H2 * NPTS / 4) / 256, 256>>>(
        y2h, sum2, sq2, g2, b2, out);
}